// round 1
// baseline (speedup 1.0000x reference)
#include <cuda_runtime.h>
#include <math.h>

#define NHH   4
#define HDD   64
#define KDD   16
#define DDD   64      // D = AR*KD
#define NNN   1600
#define BBB   16
#define HIMG  40
#define WIMG  40
#define DIMC  256
#define EPSB  1e-5f
#define SCALEQ 0.25f  // KD^-0.5

// ---------------- device scratch (no allocations allowed) ----------------
__device__ float g_xi  [BBB*HDD*NNN];     // conv+bn(+prev) output, (B,64,N)
__device__ float g_q   [BBB*NNN*KDD];     // (B,N,16)
__device__ float g_k   [BBB*NNN*KDD];     // (B,N,16)
__device__ float g_v   [BBB*NNN*DDD];     // (B,N,64)
__device__ float g_prev[BBB*HDD*NNN];     // (B,64,N)
__device__ float g_cat [BBB*NNN*DIMC];    // (B,N,256)
__device__ float g_dw_wf[NHH*HDD*25];
__device__ float g_dw_bf[NHH*HDD];
__device__ float g_qkv_wf[NHH*96*HDD];    // rows 0-15 q, 16-31 k, 32-95 v
__device__ float g_qkv_bf[NHH*96];
__device__ float g_p_wf[DIMC*DIMC];
__device__ float g_p_bf[DIMC];

// ---------------- fold BN into weights ----------------
__global__ void prep_fold(
    const float* dw_w, const float* dw_g, const float* dw_b, const float* dw_m, const float* dw_v,
    const float* q_w,  const float* q_g,  const float* q_b,  const float* q_m,  const float* q_v,
    const float* k_w,  const float* k_g,  const float* k_b,  const float* k_m,  const float* k_v,
    const float* v_w,  const float* v_g,  const float* v_b,  const float* v_m,  const float* v_v,
    const float* p_w,  const float* p_g,  const float* p_b,  const float* p_m,  const float* p_v)
{
    int t = blockIdx.x * blockDim.x + threadIdx.x;
    int stride = gridDim.x * blockDim.x;

    for (int ch = t; ch < NHH*HDD; ch += stride) {
        float s = dw_g[ch] * rsqrtf(dw_v[ch] + EPSB);
        for (int k = 0; k < 25; k++) g_dw_wf[ch*25 + k] = dw_w[ch*25 + k] * s;
        g_dw_bf[ch] = dw_b[ch] - s * dw_m[ch];
    }

    for (int r = t; r < NHH*96; r += stride) {
        int i = r / 96, oc = r % 96;
        const float* w; float s, bias;
        if (oc < 16) {
            int j = i*KDD + oc;
            s = q_g[j] * rsqrtf(q_v[j] + EPSB);
            bias = q_b[j] - s * q_m[j];
            w = q_w + (size_t)j * HDD;
            s *= SCALEQ; bias *= SCALEQ;     // fold attention scale into q
        } else if (oc < 32) {
            int j = i*KDD + (oc - 16);
            s = k_g[j] * rsqrtf(k_v[j] + EPSB);
            bias = k_b[j] - s * k_m[j];
            w = k_w + (size_t)j * HDD;
        } else {
            int j = i*DDD + (oc - 32);
            s = v_g[j] * rsqrtf(v_v[j] + EPSB);
            bias = v_b[j] - s * v_m[j];
            w = v_w + (size_t)j * HDD;
        }
        for (int c = 0; c < HDD; c++) g_qkv_wf[(size_t)r*HDD + c] = w[c] * s;
        g_qkv_bf[r] = bias;
    }

    for (int o = t; o < DIMC; o += stride) {
        float s = p_g[o] * rsqrtf(p_v[o] + EPSB);
        for (int c = 0; c < DIMC; c++) g_p_wf[o*DIMC + c] = p_w[o*DIMC + c] * s;
        g_p_bf[o] = p_b[o] - s * p_m[o];
    }
}

// ---------------- depthwise 5x5 conv + folded BN + prev add ----------------
__global__ __launch_bounds__(256) void dwconv_bn(const float* __restrict__ x, int head, int addprev)
{
    int idx = blockIdx.x * 256 + threadIdx.x;
    if (idx >= BBB*HDD*NNN) return;
    int n = idx % NNN;
    int c = (idx / NNN) % HDD;
    int b = idx / (NNN * HDD);
    int h = n / WIMG, w = n % WIMG;

    const float* xin = x + ((size_t)b * DIMC + head*HDD + c) * NNN;
    const float* wf  = g_dw_wf + (head*HDD + c) * 25;
    float acc = g_dw_bf[head*HDD + c];

    #pragma unroll
    for (int dy = 0; dy < 5; dy++) {
        int hh = h + dy - 2;
        if ((unsigned)hh >= (unsigned)HIMG) continue;
        #pragma unroll
        for (int dx = 0; dx < 5; dx++) {
            int ww = w + dx - 2;
            if ((unsigned)ww >= (unsigned)WIMG) continue;
            acc += wf[dy*5 + dx] * xin[hh*WIMG + ww];
        }
    }
    if (addprev) acc += g_prev[((size_t)b*HDD + c)*NNN + n];
    g_xi[((size_t)b*HDD + c)*NNN + n] = acc;
}

// ---------------- QKV projection (96x64 GEMM over 64-position tiles) ----------------
__global__ __launch_bounds__(256) void qkv_proj(int head)
{
    __shared__ float xs[64][65];
    __shared__ float ws[96][64];
    __shared__ float bsm[96];

    int b  = blockIdx.x / 25;
    int p0 = (blockIdx.x % 25) * 64;
    int t  = threadIdx.x;

    for (int idx = t; idx < 96*64; idx += 256)
        ws[idx/64][idx%64] = g_qkv_wf[(size_t)head*96*64 + idx];
    if (t < 96) bsm[t] = g_qkv_bf[head*96 + t];
    for (int idx = t; idx < 64*64; idx += 256) {
        int c = idx / 64, p = idx % 64;
        xs[c][p] = g_xi[((size_t)b*HDD + c)*NNN + p0 + p];
    }
    __syncthreads();

    #pragma unroll 4
    for (int j = 0; j < 24; j++) {
        int idx = t + j*256;
        int oc = idx / 64, p = idx % 64;
        float acc = bsm[oc];
        #pragma unroll
        for (int c = 0; c < 64; c++) acc += ws[oc][c] * xs[c][p];
        int n = p0 + p;
        if (oc < 16)      g_q[((size_t)b*NNN + n)*KDD + oc]        = acc;
        else if (oc < 32) g_k[((size_t)b*NNN + n)*KDD + (oc - 16)] = acc;
        else              g_v[((size_t)b*NNN + n)*DDD + (oc - 32)] = acc;
    }
}

// ---------------- flash attention: TQ=64 queries/block, TK=64 key tiles ----------------
__global__ __launch_bounds__(256) void attn_kernel(const float* __restrict__ attn_bias, int head)
{
    __shared__ float qsT[16][65];
    __shared__ float ksT[16][65];
    __shared__ __align__(16) float vs[64][68];
    __shared__ float ss[64][68];
    __shared__ float bias_s[64];
    __shared__ float m_s[64], l_s[64], f_s[64];

    int b  = blockIdx.x / 25;
    int q0 = (blockIdx.x % 25) * 64;
    int t = threadIdx.x;
    int lane = t & 31, wrp = t >> 5;
    int q_sub = lane & 7, dg = lane >> 3;
    int q = wrp*8 + q_sub;                 // my query row (0..63)

    float o[16];
    #pragma unroll
    for (int j = 0; j < 16; j++) o[j] = 0.f;

    for (int idx = t; idx < 64*16; idx += 256) {
        int qq = idx >> 4, c = idx & 15;
        qsT[c][qq] = g_q[((size_t)b*NNN + q0 + qq)*KDD + c];
    }
    if (t < 64) { m_s[t] = -1e30f; l_s[t] = 0.f; }
    __syncthreads();

    for (int k0 = 0; k0 < NNN; k0 += 64) {
        for (int idx = t; idx < 64*16; idx += 256) {
            int kk = idx >> 4, c = idx & 15;
            ksT[c][kk] = g_k[((size_t)b*NNN + k0 + kk)*KDD + c];
        }
        for (int idx = t; idx < 64*64; idx += 256) {
            int kk = idx >> 6, d = idx & 63;
            vs[kk][d] = g_v[((size_t)b*NNN + k0 + kk)*DDD + d];
        }
        if (t < 64) bias_s[t] = attn_bias[head*NNN + k0 + t];
        __syncthreads();

        // ---- S = q·k (scale folded into q) + bias, 4x4 per thread ----
        {
            int tq = t >> 4, tk = t & 15;
            int q4 = tq*4, k4 = tk*4;
            float acc[4][4];
            #pragma unroll
            for (int i = 0; i < 4; i++)
                #pragma unroll
                for (int j = 0; j < 4; j++) acc[i][j] = 0.f;
            #pragma unroll
            for (int c = 0; c < 16; c++) {
                float a0 = qsT[c][q4+0], a1 = qsT[c][q4+1], a2 = qsT[c][q4+2], a3 = qsT[c][q4+3];
                float b0 = ksT[c][k4+0], b1 = ksT[c][k4+1], b2 = ksT[c][k4+2], b3 = ksT[c][k4+3];
                acc[0][0] += a0*b0; acc[0][1] += a0*b1; acc[0][2] += a0*b2; acc[0][3] += a0*b3;
                acc[1][0] += a1*b0; acc[1][1] += a1*b1; acc[1][2] += a1*b2; acc[1][3] += a1*b3;
                acc[2][0] += a2*b0; acc[2][1] += a2*b1; acc[2][2] += a2*b2; acc[2][3] += a2*b3;
                acc[3][0] += a3*b0; acc[3][1] += a3*b1; acc[3][2] += a3*b2; acc[3][3] += a3*b3;
            }
            #pragma unroll
            for (int i = 0; i < 4; i++)
                #pragma unroll
                for (int j = 0; j < 4; j++)
                    ss[q4+i][k4+j] = acc[i][j] + bias_s[k4+j];
        }
        __syncthreads();

        // ---- online softmax update (4 threads per row, 16 cols each) ----
        {
            int r = t >> 2, jj = t & 3;
            int c0 = jj * 16;
            float mx = -1e30f;
            #pragma unroll
            for (int c = 0; c < 16; c++) mx = fmaxf(mx, ss[r][c0+c]);
            mx = fmaxf(mx, __shfl_xor_sync(0xffffffffu, mx, 1));
            mx = fmaxf(mx, __shfl_xor_sync(0xffffffffu, mx, 2));
            float newm = fmaxf(m_s[r], mx);
            float sum = 0.f;
            #pragma unroll
            for (int c = 0; c < 16; c++) {
                float p = __expf(ss[r][c0+c] - newm);
                ss[r][c0+c] = p;
                sum += p;
            }
            sum += __shfl_xor_sync(0xffffffffu, sum, 1);
            sum += __shfl_xor_sync(0xffffffffu, sum, 2);
            if (jj == 0) {
                float f = __expf(m_s[r] - newm);
                f_s[r] = f;
                l_s[r] = l_s[r]*f + sum;
                m_s[r] = newm;
            }
        }
        __syncthreads();

        // ---- O += P @ V (thread: 1 query x 16 dims) ----
        {
            float f = f_s[q];
            #pragma unroll
            for (int j = 0; j < 16; j++) o[j] *= f;
            #pragma unroll 8
            for (int kk = 0; kk < 64; kk++) {
                float p = ss[q][kk];
                const float4* vrow = reinterpret_cast<const float4*>(&vs[kk][dg*16]);
                float4 v0 = vrow[0], v1 = vrow[1], v2 = vrow[2], v3 = vrow[3];
                o[0]  += p*v0.x; o[1]  += p*v0.y; o[2]  += p*v0.z; o[3]  += p*v0.w;
                o[4]  += p*v1.x; o[5]  += p*v1.y; o[6]  += p*v1.z; o[7]  += p*v1.w;
                o[8]  += p*v2.x; o[9]  += p*v2.y; o[10] += p*v2.z; o[11] += p*v2.w;
                o[12] += p*v3.x; o[13] += p*v3.y; o[14] += p*v3.z; o[15] += p*v3.w;
            }
        }
        __syncthreads();
    }

    // ---- epilogue: normalize, write concat buffer (B,N,256) + prev (B,64,N) ----
    float inv = 1.f / l_s[q];
    int n = q0 + q;
    float* catp = &g_cat[((size_t)b*NNN + n)*DIMC + head*DDD + dg*16];
    #pragma unroll
    for (int j = 0; j < 16; j++) {
        float val = o[j] * inv;
        catp[j] = val;
        g_prev[((size_t)b*HDD + dg*16 + j)*NNN + n] = val;
    }
}

// ---------------- final proj (256x256) + folded BN + ReLU ----------------
__global__ __launch_bounds__(256) void proj_kernel(float* __restrict__ out)
{
    __shared__ float wsm[64][65];
    __shared__ float xsm[64][65];

    int pt = blockIdx.x % 400;        // position tile (B*25)
    int ot = blockIdx.x / 400;        // out-channel tile (0..3)
    int b  = pt / 25;
    int p0 = (pt % 25) * 64;
    int o0 = ot * 64;

    int t = threadIdx.x;
    int to = t >> 4, tp = t & 15;
    int o4 = to*4, p4 = tp*4;

    float acc[4][4];
    #pragma unroll
    for (int i = 0; i < 4; i++)
        #pragma unroll
        for (int j = 0; j < 4; j++) acc[i][j] = 0.f;

    for (int c0 = 0; c0 < DIMC; c0 += 64) {
        for (int idx = t; idx < 64*64; idx += 256) {
            int o = idx >> 6, c = idx & 63;
            wsm[o][c] = g_p_wf[(o0+o)*DIMC + c0 + c];
        }
        for (int idx = t; idx < 64*64; idx += 256) {
            int p = idx >> 6, c = idx & 63;
            xsm[c][p] = g_cat[((size_t)b*NNN + p0 + p)*DIMC + c0 + c];
        }
        __syncthreads();

        #pragma unroll 8
        for (int c = 0; c < 64; c++) {
            float a0 = wsm[o4+0][c], a1 = wsm[o4+1][c], a2 = wsm[o4+2][c], a3 = wsm[o4+3][c];
            float b0 = xsm[c][p4+0], b1 = xsm[c][p4+1], b2 = xsm[c][p4+2], b3 = xsm[c][p4+3];
            acc[0][0] += a0*b0; acc[0][1] += a0*b1; acc[0][2] += a0*b2; acc[0][3] += a0*b3;
            acc[1][0] += a1*b0; acc[1][1] += a1*b1; acc[1][2] += a1*b2; acc[1][3] += a1*b3;
            acc[2][0] += a2*b0; acc[2][1] += a2*b1; acc[2][2] += a2*b2; acc[2][3] += a2*b3;
            acc[3][0] += a3*b0; acc[3][1] += a3*b1; acc[3][2] += a3*b2; acc[3][3] += a3*b3;
        }
        __syncthreads();
    }

    #pragma unroll
    for (int i = 0; i < 4; i++) {
        int o = o0 + o4 + i;
        float bb = g_p_bf[o];
        #pragma unroll
        for (int j = 0; j < 4; j++) {
            int n = p0 + p4 + j;
            float v = acc[i][j] + bb;
            out[((size_t)b*DIMC + o)*NNN + n] = fmaxf(v, 0.f);
        }
    }
}

// ---------------- launch ----------------
extern "C" void kernel_launch(void* const* d_in, const int* in_sizes, int n_in,
                              void* d_out, int out_size)
{
    const float* x    = (const float*)d_in[0];
    const float* dw_w = (const float*)d_in[1];
    const float* dw_g = (const float*)d_in[2];
    const float* dw_b = (const float*)d_in[3];
    const float* dw_m = (const float*)d_in[4];
    const float* dw_v = (const float*)d_in[5];
    const float* q_w  = (const float*)d_in[6];
    const float* q_g  = (const float*)d_in[7];
    const float* q_b  = (const float*)d_in[8];
    const float* q_m  = (const float*)d_in[9];
    const float* q_v  = (const float*)d_in[10];
    const float* k_w  = (const float*)d_in[11];
    const float* k_g  = (const float*)d_in[12];
    const float* k_b  = (const float*)d_in[13];
    const float* k_m  = (const float*)d_in[14];
    const float* k_v  = (const float*)d_in[15];
    const float* v_w  = (const float*)d_in[16];
    const float* v_g  = (const float*)d_in[17];
    const float* v_b  = (const float*)d_in[18];
    const float* v_m  = (const float*)d_in[19];
    const float* v_v  = (const float*)d_in[20];
    const float* p_w  = (const float*)d_in[21];
    const float* p_g  = (const float*)d_in[22];
    const float* p_b  = (const float*)d_in[23];
    const float* p_m  = (const float*)d_in[24];
    const float* p_v  = (const float*)d_in[25];
    const float* attn_bias = (const float*)d_in[26];

    prep_fold<<<64, 256>>>(dw_w, dw_g, dw_b, dw_m, dw_v,
                           q_w, q_g, q_b, q_m, q_v,
                           k_w, k_g, k_b, k_m, k_v,
                           v_w, v_g, v_b, v_m, v_v,
                           p_w, p_g, p_b, p_m, p_v);

    for (int i = 0; i < NHH; i++) {
        dwconv_bn<<<(BBB*HDD*NNN)/256, 256>>>(x, i, i > 0 ? 1 : 0);
        qkv_proj<<<BBB*25, 256>>>(i);
        attn_kernel<<<BBB*25, 256>>>(attn_bias, i);
    }

    proj_kernel<<<4*400, 256>>>((float*)d_out);
}

// round 2
// speedup vs baseline: 1.9755x; 1.9755x over previous
#include <cuda_runtime.h>
#include <math.h>

#define NHH   4
#define HDD   64
#define KDD   16
#define DDD   64      // D = AR*KD
#define NNN   1600
#define BBB   16
#define HIMG  40
#define WIMG  40
#define DIMC  256
#define EPSB  1e-5f
#define SCALEQ 0.25f  // KD^-0.5

// ---------------- device scratch (no allocations allowed) ----------------
__device__ float g_xi  [BBB*HDD*NNN];     // conv+bn(+prev) output, (B,64,N)
__device__ float g_q   [BBB*NNN*KDD];     // (B,N,16)
__device__ float g_k   [BBB*NNN*KDD];     // (B,N,16)
__device__ float g_v   [BBB*NNN*DDD];     // (B,N,64)
__device__ float g_prev[BBB*HDD*NNN];     // (B,64,N)
__device__ float g_cat [BBB*NNN*DIMC];    // (B,N,256)
__device__ float g_dw_wf[NHH*HDD*25];
__device__ float g_dw_bf[NHH*HDD];
__device__ float g_qkv_wf[NHH*96*HDD];    // rows 0-15 q, 16-31 k, 32-95 v
__device__ float g_qkv_bf[NHH*96];
__device__ float g_p_wf[DIMC*DIMC];
__device__ float g_p_bf[DIMC];

// ---------------- helpers ----------------
__device__ __forceinline__ unsigned f2tf32(float f) {
    unsigned u; asm("cvt.rna.tf32.f32 %0, %1;" : "=r"(u) : "f"(f)); return u;
}

__device__ __forceinline__ void mma_tf32(float c[4], const unsigned a[4],
                                         unsigned b0, unsigned b1) {
    asm volatile("mma.sync.aligned.m16n8k8.row.col.f32.tf32.tf32.f32 "
        "{%0,%1,%2,%3}, {%4,%5,%6,%7}, {%8,%9}, {%0,%1,%2,%3};"
        : "+f"(c[0]), "+f"(c[1]), "+f"(c[2]), "+f"(c[3])
        : "r"(a[0]), "r"(a[1]), "r"(a[2]), "r"(a[3]), "r"(b0), "r"(b1));
}

// ---------------- fold BN into weights ----------------
__global__ void prep_fold(
    const float* dw_w, const float* dw_g, const float* dw_b, const float* dw_m, const float* dw_v,
    const float* q_w,  const float* q_g,  const float* q_b,  const float* q_m,  const float* q_v,
    const float* k_w,  const float* k_g,  const float* k_b,  const float* k_m,  const float* k_v,
    const float* v_w,  const float* v_g,  const float* v_b,  const float* v_m,  const float* v_v,
    const float* p_w,  const float* p_g,  const float* p_b,  const float* p_m,  const float* p_v)
{
    int t = blockIdx.x * blockDim.x + threadIdx.x;
    int stride = gridDim.x * blockDim.x;

    for (int ch = t; ch < NHH*HDD; ch += stride) {
        float s = dw_g[ch] * rsqrtf(dw_v[ch] + EPSB);
        for (int k = 0; k < 25; k++) g_dw_wf[ch*25 + k] = dw_w[ch*25 + k] * s;
        g_dw_bf[ch] = dw_b[ch] - s * dw_m[ch];
    }

    for (int r = t; r < NHH*96; r += stride) {
        int i = r / 96, oc = r % 96;
        const float* w; float s, bias;
        if (oc < 16) {
            int j = i*KDD + oc;
            s = q_g[j] * rsqrtf(q_v[j] + EPSB);
            bias = q_b[j] - s * q_m[j];
            w = q_w + (size_t)j * HDD;
            s *= SCALEQ; bias *= SCALEQ;     // fold attention scale into q
        } else if (oc < 32) {
            int j = i*KDD + (oc - 16);
            s = k_g[j] * rsqrtf(k_v[j] + EPSB);
            bias = k_b[j] - s * k_m[j];
            w = k_w + (size_t)j * HDD;
        } else {
            int j = i*DDD + (oc - 32);
            s = v_g[j] * rsqrtf(v_v[j] + EPSB);
            bias = v_b[j] - s * v_m[j];
            w = v_w + (size_t)j * HDD;
        }
        for (int c = 0; c < HDD; c++) g_qkv_wf[(size_t)r*HDD + c] = w[c] * s;
        g_qkv_bf[r] = bias;
    }

    for (int o = t; o < DIMC; o += stride) {
        float s = p_g[o] * rsqrtf(p_v[o] + EPSB);
        for (int c = 0; c < DIMC; c++) g_p_wf[o*DIMC + c] = p_w[o*DIMC + c] * s;
        g_p_bf[o] = p_b[o] - s * p_m[o];
    }
}

// ---------------- depthwise 5x5 conv + folded BN + prev add ----------------
__global__ __launch_bounds__(256) void dwconv_bn(const float* __restrict__ x, int head, int addprev)
{
    int idx = blockIdx.x * 256 + threadIdx.x;
    if (idx >= BBB*HDD*NNN) return;
    int n = idx % NNN;
    int c = (idx / NNN) % HDD;
    int b = idx / (NNN * HDD);
    int h = n / WIMG, w = n % WIMG;

    const float* xin = x + ((size_t)b * DIMC + head*HDD + c) * NNN;
    const float* wf  = g_dw_wf + (head*HDD + c) * 25;
    float acc = g_dw_bf[head*HDD + c];

    #pragma unroll
    for (int dy = 0; dy < 5; dy++) {
        int hh = h + dy - 2;
        if ((unsigned)hh >= (unsigned)HIMG) continue;
        #pragma unroll
        for (int dx = 0; dx < 5; dx++) {
            int ww = w + dx - 2;
            if ((unsigned)ww >= (unsigned)WIMG) continue;
            acc += wf[dy*5 + dx] * xin[hh*WIMG + ww];
        }
    }
    if (addprev) acc += g_prev[((size_t)b*HDD + c)*NNN + n];
    g_xi[((size_t)b*HDD + c)*NNN + n] = acc;
}

// ---------------- QKV projection (96x64 GEMM over 64-position tiles) ----------------
__global__ __launch_bounds__(256) void qkv_proj(int head)
{
    __shared__ float xs[64][65];
    __shared__ float ws[96][64];
    __shared__ float bsm[96];

    int b  = blockIdx.x / 25;
    int p0 = (blockIdx.x % 25) * 64;
    int t  = threadIdx.x;

    for (int idx = t; idx < 96*64; idx += 256)
        ws[idx/64][idx%64] = g_qkv_wf[(size_t)head*96*64 + idx];
    if (t < 96) bsm[t] = g_qkv_bf[head*96 + t];
    for (int idx = t; idx < 64*64; idx += 256) {
        int c = idx / 64, p = idx % 64;
        xs[c][p] = g_xi[((size_t)b*HDD + c)*NNN + p0 + p];
    }
    __syncthreads();

    #pragma unroll 4
    for (int j = 0; j < 24; j++) {
        int idx = t + j*256;
        int oc = idx / 64, p = idx % 64;
        float acc = bsm[oc];
        #pragma unroll
        for (int c = 0; c < 64; c++) acc += ws[oc][c] * xs[c][p];
        int n = p0 + p;
        if (oc < 16)      g_q[((size_t)b*NNN + n)*KDD + oc]        = acc;
        else if (oc < 32) g_k[((size_t)b*NNN + n)*KDD + (oc - 16)] = acc;
        else              g_v[((size_t)b*NNN + n)*DDD + (oc - 32)] = acc;
    }
}

// ---------------- tf32 MMA flash attention ----------------
// 128 threads (4 warps), each warp owns 16 query rows of a 64-query tile.
// Per 64-key tile: S via m16n8k8 tf32 mma, online softmax in accumulator
// fragments (quad shfl reductions), P->A fragments via shfl, O += P@V via mma.
__global__ __launch_bounds__(128) void attn_mma(const float* __restrict__ attn_bias, int head)
{
    __shared__ unsigned ksT[16][72];   // K^T (tf32 bits): [c][key]
    __shared__ unsigned vsm[64][72];   // V   (tf32 bits): [key][d]
    __shared__ float bias_s[64];

    int b  = blockIdx.x / 25;
    int q0 = (blockIdx.x % 25) * 64;
    int t    = threadIdx.x;
    int w    = t >> 5;
    int lane = t & 31;
    int g    = lane >> 2;      // groupID (row within m16 half)
    int qd   = lane & 3;       // threadID in group

    // Q operand fragments (persist whole kernel)
    unsigned aQ[2][4];
    {
        int r0 = q0 + w*16 + g, r1 = r0 + 8;
        const float* qb = g_q + (size_t)b*NNN*KDD;
        #pragma unroll
        for (int ks = 0; ks < 2; ks++) {
            aQ[ks][0] = f2tf32(qb[(size_t)r0*KDD + ks*8 + qd]);
            aQ[ks][1] = f2tf32(qb[(size_t)r1*KDD + ks*8 + qd]);
            aQ[ks][2] = f2tf32(qb[(size_t)r0*KDD + ks*8 + qd + 4]);
            aQ[ks][3] = f2tf32(qb[(size_t)r1*KDD + ks*8 + qd + 4]);
        }
    }

    float Oa[8][4];
    #pragma unroll
    for (int nt = 0; nt < 8; nt++)
        #pragma unroll
        for (int j = 0; j < 4; j++) Oa[nt][j] = 0.f;
    float m0 = -1e30f, m1 = -1e30f, l0 = 0.f, l1 = 0.f;

    for (int k0 = 0; k0 < NNN; k0 += 64) {
        // ---- stage K^T (tf32) ----
        for (int idx = t; idx < 256; idx += 128) {         // 256 float4 = 64 keys x 16c
            int kk = idx >> 2, c4 = (idx & 3) * 4;
            float4 kv = *(const float4*)&g_k[((size_t)b*NNN + k0 + kk)*KDD + c4];
            ksT[c4+0][kk] = f2tf32(kv.x);
            ksT[c4+1][kk] = f2tf32(kv.y);
            ksT[c4+2][kk] = f2tf32(kv.z);
            ksT[c4+3][kk] = f2tf32(kv.w);
        }
        // ---- stage V (tf32) ----
        for (int idx = t; idx < 1024; idx += 128) {        // 1024 float4 = 64 keys x 64d
            int kk = idx >> 4, d4 = (idx & 15) * 4;
            float4 vv = *(const float4*)&g_v[((size_t)b*NNN + k0 + kk)*DDD + d4];
            vsm[kk][d4+0] = f2tf32(vv.x);
            vsm[kk][d4+1] = f2tf32(vv.y);
            vsm[kk][d4+2] = f2tf32(vv.z);
            vsm[kk][d4+3] = f2tf32(vv.w);
        }
        if (t < 64) bias_s[t] = attn_bias[head*NNN + k0 + t];
        __syncthreads();

        // ---- S = Q K^T ----
        float Sv[8][4];
        #pragma unroll
        for (int nt = 0; nt < 8; nt++) {
            float acc[4] = {0.f, 0.f, 0.f, 0.f};
            #pragma unroll
            for (int ks = 0; ks < 2; ks++) {
                unsigned b0 = ksT[ks*8 + qd    ][nt*8 + g];
                unsigned b1 = ksT[ks*8 + qd + 4][nt*8 + g];
                mma_tf32(acc, aQ[ks], b0, b1);
            }
            float2 bb = *(const float2*)&bias_s[nt*8 + 2*qd];
            Sv[nt][0] = acc[0] + bb.x;
            Sv[nt][1] = acc[1] + bb.y;
            Sv[nt][2] = acc[2] + bb.x;
            Sv[nt][3] = acc[3] + bb.y;
        }

        // ---- online softmax (rows r0 = g, r1 = g+8 of this warp) ----
        float mx0 = -1e30f, mx1 = -1e30f;
        #pragma unroll
        for (int nt = 0; nt < 8; nt++) {
            mx0 = fmaxf(mx0, fmaxf(Sv[nt][0], Sv[nt][1]));
            mx1 = fmaxf(mx1, fmaxf(Sv[nt][2], Sv[nt][3]));
        }
        mx0 = fmaxf(mx0, __shfl_xor_sync(0xffffffffu, mx0, 1));
        mx0 = fmaxf(mx0, __shfl_xor_sync(0xffffffffu, mx0, 2));
        mx1 = fmaxf(mx1, __shfl_xor_sync(0xffffffffu, mx1, 1));
        mx1 = fmaxf(mx1, __shfl_xor_sync(0xffffffffu, mx1, 2));

        float nm0 = fmaxf(m0, mx0), nm1 = fmaxf(m1, mx1);
        float f0 = __expf(m0 - nm0), f1 = __expf(m1 - nm1);

        unsigned P[8][4];
        float sum0 = 0.f, sum1 = 0.f;
        #pragma unroll
        for (int nt = 0; nt < 8; nt++) {
            float p0 = __expf(Sv[nt][0] - nm0);
            float p1 = __expf(Sv[nt][1] - nm0);
            float p2 = __expf(Sv[nt][2] - nm1);
            float p3 = __expf(Sv[nt][3] - nm1);
            sum0 += p0 + p1;
            sum1 += p2 + p3;
            P[nt][0] = f2tf32(p0); P[nt][1] = f2tf32(p1);
            P[nt][2] = f2tf32(p2); P[nt][3] = f2tf32(p3);
        }
        sum0 += __shfl_xor_sync(0xffffffffu, sum0, 1);
        sum0 += __shfl_xor_sync(0xffffffffu, sum0, 2);
        sum1 += __shfl_xor_sync(0xffffffffu, sum1, 1);
        sum1 += __shfl_xor_sync(0xffffffffu, sum1, 2);

        l0 = l0 * f0 + sum0;  m0 = nm0;
        l1 = l1 * f1 + sum1;  m1 = nm1;

        #pragma unroll
        for (int nt = 0; nt < 8; nt++) {
            Oa[nt][0] *= f0; Oa[nt][1] *= f0;
            Oa[nt][2] *= f1; Oa[nt][3] *= f1;
        }

        // ---- O += P V ----
        int srcA = (lane & ~3) | (qd >> 1);
        int srcB = srcA + 2;
        #pragma unroll
        for (int ks = 0; ks < 8; ks++) {
            // rearrange C-fragment cols {2q,2q+1} -> A-fragment cols {q, q+4}
            unsigned t0 = __shfl_sync(0xffffffffu, P[ks][0], srcA);
            unsigned t1 = __shfl_sync(0xffffffffu, P[ks][1], srcA);
            unsigned t2 = __shfl_sync(0xffffffffu, P[ks][2], srcA);
            unsigned t3 = __shfl_sync(0xffffffffu, P[ks][3], srcA);
            unsigned u0 = __shfl_sync(0xffffffffu, P[ks][0], srcB);
            unsigned u1 = __shfl_sync(0xffffffffu, P[ks][1], srcB);
            unsigned u2 = __shfl_sync(0xffffffffu, P[ks][2], srcB);
            unsigned u3 = __shfl_sync(0xffffffffu, P[ks][3], srcB);
            unsigned aP[4];
            aP[0] = (qd & 1) ? t1 : t0;
            aP[1] = (qd & 1) ? t3 : t2;
            aP[2] = (qd & 1) ? u1 : u0;
            aP[3] = (qd & 1) ? u3 : u2;
            #pragma unroll
            for (int nt = 0; nt < 8; nt++) {
                unsigned b0 = vsm[ks*8 + qd    ][nt*8 + g];
                unsigned b1 = vsm[ks*8 + qd + 4][nt*8 + g];
                mma_tf32(Oa[nt], aP, b0, b1);
            }
        }
        __syncthreads();
    }

    // ---- epilogue: normalize + write cat (B,N,256) and prev (B,64,N) ----
    float inv0 = 1.f / l0, inv1 = 1.f / l1;
    int n0 = q0 + w*16 + g, n1 = n0 + 8;
    #pragma unroll
    for (int nt = 0; nt < 8; nt++) {
        int d = nt*8 + 2*qd;
        float o00 = Oa[nt][0] * inv0, o01 = Oa[nt][1] * inv0;
        float o10 = Oa[nt][2] * inv1, o11 = Oa[nt][3] * inv1;
        float2* c0 = (float2*)&g_cat[((size_t)b*NNN + n0)*DIMC + head*DDD + d];
        float2* c1 = (float2*)&g_cat[((size_t)b*NNN + n1)*DIMC + head*DDD + d];
        *c0 = make_float2(o00, o01);
        *c1 = make_float2(o10, o11);
        g_prev[((size_t)b*HDD + d    )*NNN + n0] = o00;
        g_prev[((size_t)b*HDD + d + 1)*NNN + n0] = o01;
        g_prev[((size_t)b*HDD + d    )*NNN + n1] = o10;
        g_prev[((size_t)b*HDD + d + 1)*NNN + n1] = o11;
    }
}

// ---------------- final proj (256x256) + folded BN + ReLU ----------------
__global__ __launch_bounds__(256) void proj_kernel(float* __restrict__ out)
{
    __shared__ float wsm[64][65];
    __shared__ float xsm[64][65];

    int pt = blockIdx.x % 400;        // position tile (B*25)
    int ot = blockIdx.x / 400;        // out-channel tile (0..3)
    int b  = pt / 25;
    int p0 = (pt % 25) * 64;
    int o0 = ot * 64;

    int t = threadIdx.x;
    int to = t >> 4, tp = t & 15;
    int o4 = to*4, p4 = tp*4;

    float acc[4][4];
    #pragma unroll
    for (int i = 0; i < 4; i++)
        #pragma unroll
        for (int j = 0; j < 4; j++) acc[i][j] = 0.f;

    for (int c0 = 0; c0 < DIMC; c0 += 64) {
        for (int idx = t; idx < 64*64; idx += 256) {
            int o = idx >> 6, c = idx & 63;
            wsm[o][c] = g_p_wf[(o0+o)*DIMC + c0 + c];
        }
        for (int idx = t; idx < 64*64; idx += 256) {
            int p = idx >> 6, c = idx & 63;
            xsm[c][p] = g_cat[((size_t)b*NNN + p0 + p)*DIMC + c0 + c];
        }
        __syncthreads();

        #pragma unroll 8
        for (int c = 0; c < 64; c++) {
            float a0 = wsm[o4+0][c], a1 = wsm[o4+1][c], a2 = wsm[o4+2][c], a3 = wsm[o4+3][c];
            float b0 = xsm[c][p4+0], b1 = xsm[c][p4+1], b2 = xsm[c][p4+2], b3 = xsm[c][p4+3];
            acc[0][0] += a0*b0; acc[0][1] += a0*b1; acc[0][2] += a0*b2; acc[0][3] += a0*b3;
            acc[1][0] += a1*b0; acc[1][1] += a1*b1; acc[1][2] += a1*b2; acc[1][3] += a1*b3;
            acc[2][0] += a2*b0; acc[2][1] += a2*b1; acc[2][2] += a2*b2; acc[2][3] += a2*b3;
            acc[3][0] += a3*b0; acc[3][1] += a3*b1; acc[3][2] += a3*b2; acc[3][3] += a3*b3;
        }
        __syncthreads();
    }

    #pragma unroll
    for (int i = 0; i < 4; i++) {
        int o = o0 + o4 + i;
        float bb = g_p_bf[o];
        #pragma unroll
        for (int j = 0; j < 4; j++) {
            int n = p0 + p4 + j;
            float v = acc[i][j] + bb;
            out[((size_t)b*DIMC + o)*NNN + n] = fmaxf(v, 0.f);
        }
    }
}

// ---------------- launch ----------------
extern "C" void kernel_launch(void* const* d_in, const int* in_sizes, int n_in,
                              void* d_out, int out_size)
{
    const float* x    = (const float*)d_in[0];
    const float* dw_w = (const float*)d_in[1];
    const float* dw_g = (const float*)d_in[2];
    const float* dw_b = (const float*)d_in[3];
    const float* dw_m = (const float*)d_in[4];
    const float* dw_v = (const float*)d_in[5];
    const float* q_w  = (const float*)d_in[6];
    const float* q_g  = (const float*)d_in[7];
    const float* q_b  = (const float*)d_in[8];
    const float* q_m  = (const float*)d_in[9];
    const float* q_v  = (const float*)d_in[10];
    const float* k_w  = (const float*)d_in[11];
    const float* k_g  = (const float*)d_in[12];
    const float* k_b  = (const float*)d_in[13];
    const float* k_m  = (const float*)d_in[14];
    const float* k_v  = (const float*)d_in[15];
    const float* v_w  = (const float*)d_in[16];
    const float* v_g  = (const float*)d_in[17];
    const float* v_b  = (const float*)d_in[18];
    const float* v_m  = (const float*)d_in[19];
    const float* v_v  = (const float*)d_in[20];
    const float* p_w  = (const float*)d_in[21];
    const float* p_g  = (const float*)d_in[22];
    const float* p_b  = (const float*)d_in[23];
    const float* p_m  = (const float*)d_in[24];
    const float* p_v  = (const float*)d_in[25];
    const float* attn_bias = (const float*)d_in[26];

    prep_fold<<<64, 256>>>(dw_w, dw_g, dw_b, dw_m, dw_v,
                           q_w, q_g, q_b, q_m, q_v,
                           k_w, k_g, k_b, k_m, k_v,
                           v_w, v_g, v_b, v_m, v_v,
                           p_w, p_g, p_b, p_m, p_v);

    for (int i = 0; i < NHH; i++) {
        dwconv_bn<<<(BBB*HDD*NNN)/256, 256>>>(x, i, i > 0 ? 1 : 0);
        qkv_proj<<<BBB*25, 256>>>(i);
        attn_mma<<<BBB*25, 128>>>(attn_bias, i);
    }

    proj_kernel<<<4*400, 256>>>((float*)d_out);
}

// round 3
// speedup vs baseline: 3.3964x; 1.7193x over previous
#include <cuda_runtime.h>
#include <math.h>

#define NHH   4
#define HDD   64
#define KDD   16
#define DDD   64
#define NNN   1600
#define BBB   16
#define HIMG  40
#define WIMG  40
#define DIMC  256
#define EPSB  1e-5f
#define SCALEQ 0.25f

// ---------------- device scratch ----------------
__device__ float g_xi  [BBB*HDD*NNN];
__device__ float g_q   [BBB*NNN*KDD];
__device__ float g_k   [BBB*NNN*KDD];
__device__ float g_v   [BBB*NNN*DDD];
__device__ float g_prev[BBB*HDD*NNN];
__device__ float g_cat [BBB*NNN*DIMC];
__device__ float g_dw_wf[NHH*HDD*25];
__device__ float g_dw_bf[NHH*HDD];
__device__ float g_qkv_wf[NHH*96*HDD];
__device__ float g_qkv_bf[NHH*96];
__device__ float g_p_wf[DIMC*DIMC];
__device__ float g_p_bf[DIMC];

// ---------------- helpers ----------------
__device__ __forceinline__ unsigned f2tf32(float f) {
    unsigned u; asm("cvt.rna.tf32.f32 %0, %1;" : "=r"(u) : "f"(f)); return u;
}
__device__ __forceinline__ float tf32r(float f) {          // round fp32 -> nearest tf32 value
    return __uint_as_float(f2tf32(f));
}
__device__ __forceinline__ void mma_tf32(float c[4], const unsigned a[4],
                                         unsigned b0, unsigned b1) {
    asm volatile("mma.sync.aligned.m16n8k8.row.col.f32.tf32.tf32.f32 "
        "{%0,%1,%2,%3}, {%4,%5,%6,%7}, {%8,%9}, {%0,%1,%2,%3};"
        : "+f"(c[0]), "+f"(c[1]), "+f"(c[2]), "+f"(c[3])
        : "r"(a[0]), "r"(a[1]), "r"(a[2]), "r"(a[3]), "r"(b0), "r"(b1));
}
__device__ __forceinline__ void cp16(void* dst, const void* src) {
    unsigned d = (unsigned)__cvta_generic_to_shared(dst);
    asm volatile("cp.async.cg.shared.global [%0], [%1], 16;" :: "r"(d), "l"(src));
}
#define CP_COMMIT asm volatile("cp.async.commit_group;" ::: "memory")
#define CP_WAIT1  asm volatile("cp.async.wait_group 1;"  ::: "memory")

// ---------------- fold BN into weights (element-parallel) ----------------
__global__ void prep_fold(
    const float* dw_w, const float* dw_g, const float* dw_b, const float* dw_m, const float* dw_v,
    const float* q_w,  const float* q_g,  const float* q_b,  const float* q_m,  const float* q_v,
    const float* k_w,  const float* k_g,  const float* k_b,  const float* k_m,  const float* k_v,
    const float* v_w,  const float* v_g,  const float* v_b,  const float* v_m,  const float* v_v,
    const float* p_w,  const float* p_g,  const float* p_b,  const float* p_m,  const float* p_v)
{
    int t = blockIdx.x * blockDim.x + threadIdx.x;
    int stride = gridDim.x * blockDim.x;

    for (int idx = t; idx < NHH*HDD*25; idx += stride) {
        int ch = idx / 25;
        float s = dw_g[ch] * rsqrtf(dw_v[ch] + EPSB);
        g_dw_wf[idx] = dw_w[idx] * s;
    }
    for (int ch = t; ch < NHH*HDD; ch += stride) {
        float s = dw_g[ch] * rsqrtf(dw_v[ch] + EPSB);
        g_dw_bf[ch] = dw_b[ch] - s * dw_m[ch];
    }
    for (int idx = t; idx < NHH*96*HDD; idx += stride) {
        int r = idx / HDD, c = idx % HDD;
        int i = r / 96, oc = r % 96;
        float s; const float* w;
        if (oc < 16) {
            int j = i*KDD + oc;
            s = q_g[j] * rsqrtf(q_v[j] + EPSB) * SCALEQ;
            w = q_w + (size_t)j * HDD;
        } else if (oc < 32) {
            int j = i*KDD + (oc - 16);
            s = k_g[j] * rsqrtf(k_v[j] + EPSB);
            w = k_w + (size_t)j * HDD;
        } else {
            int j = i*DDD + (oc - 32);
            s = v_g[j] * rsqrtf(v_v[j] + EPSB);
            w = v_w + (size_t)j * HDD;
        }
        g_qkv_wf[idx] = w[c] * s;
    }
    for (int r = t; r < NHH*96; r += stride) {
        int i = r / 96, oc = r % 96;
        float s, bias;
        if (oc < 16) {
            int j = i*KDD + oc;
            s = q_g[j] * rsqrtf(q_v[j] + EPSB);
            bias = (q_b[j] - s * q_m[j]) * SCALEQ;
        } else if (oc < 32) {
            int j = i*KDD + (oc - 16);
            s = k_g[j] * rsqrtf(k_v[j] + EPSB);
            bias = k_b[j] - s * k_m[j];
        } else {
            int j = i*DDD + (oc - 32);
            s = v_g[j] * rsqrtf(v_v[j] + EPSB);
            bias = v_b[j] - s * v_m[j];
        }
        g_qkv_bf[r] = bias;
    }
    for (int idx = t; idx < DIMC*DIMC; idx += stride) {
        int o = idx / DIMC;
        float s = p_g[o] * rsqrtf(p_v[o] + EPSB);
        g_p_wf[idx] = tf32r(p_w[idx] * s);          // pre-round for tf32 MMA
    }
    for (int o = t; o < DIMC; o += stride) {
        float s = p_g[o] * rsqrtf(p_v[o] + EPSB);
        g_p_bf[o] = p_b[o] - s * p_m[o];
    }
}

// ---------------- depthwise 5x5 conv + folded BN + prev add ----------------
__global__ __launch_bounds__(256) void dwconv_bn(const float* __restrict__ x, int head, int addprev)
{
    int idx = blockIdx.x * 256 + threadIdx.x;
    if (idx >= BBB*HDD*NNN) return;
    int n = idx % NNN;
    int c = (idx / NNN) % HDD;
    int b = idx / (NNN * HDD);
    int h = n / WIMG, w = n % WIMG;

    const float* xin = x + ((size_t)b * DIMC + head*HDD + c) * NNN;
    const float* wf  = g_dw_wf + (head*HDD + c) * 25;
    float acc = g_dw_bf[head*HDD + c];

    #pragma unroll
    for (int dy = 0; dy < 5; dy++) {
        int hh = h + dy - 2;
        if ((unsigned)hh >= (unsigned)HIMG) continue;
        #pragma unroll
        for (int dx = 0; dx < 5; dx++) {
            int ww = w + dx - 2;
            if ((unsigned)ww >= (unsigned)WIMG) continue;
            acc += wf[dy*5 + dx] * xin[hh*WIMG + ww];
        }
    }
    if (addprev) acc += g_prev[((size_t)b*HDD + c)*NNN + n];
    g_xi[((size_t)b*HDD + c)*NNN + n] = acc;
}

// ---------------- QKV projection (96x64 GEMM, 6x4 register blocking) ----------------
// Outputs are rounded to tf32 so attention can consume raw bits exactly.
__global__ __launch_bounds__(256) void qkv_proj(int head)
{
    __shared__ float xs[64][68];
    __shared__ float ws[96][64];
    __shared__ float bsm[96];

    int b  = blockIdx.x / 25;
    int p0 = (blockIdx.x % 25) * 64;
    int t  = threadIdx.x;

    for (int idx = t; idx < 96*64; idx += 256)
        ws[idx/64][idx%64] = g_qkv_wf[(size_t)head*96*64 + idx];
    if (t < 96) bsm[t] = g_qkv_bf[head*96 + t];
    for (int idx = t; idx < 64*64; idx += 256) {
        int c = idx / 64, p = idx % 64;
        xs[c][p] = g_xi[((size_t)b*HDD + c)*NNN + p0 + p];
    }
    __syncthreads();

    int to  = t >> 4;           // 0..15 -> 6 out-channels each
    int tp  = t & 15;           // 0..15 -> 4 positions each
    int oc0 = to * 6, pl = tp * 4;

    float acc[6][4];
    #pragma unroll
    for (int i = 0; i < 6; i++) {
        float bb = bsm[oc0 + i];
        #pragma unroll
        for (int j = 0; j < 4; j++) acc[i][j] = bb;
    }

    #pragma unroll 8
    for (int c = 0; c < 64; c++) {
        float4 xv = *(const float4*)&xs[c][pl];
        #pragma unroll
        for (int i = 0; i < 6; i++) {
            float w = ws[oc0 + i][c];
            acc[i][0] += w * xv.x;
            acc[i][1] += w * xv.y;
            acc[i][2] += w * xv.z;
            acc[i][3] += w * xv.w;
        }
    }

    #pragma unroll
    for (int i = 0; i < 6; i++) {
        int oc = oc0 + i;
        #pragma unroll
        for (int j = 0; j < 4; j++) {
            int n = p0 + pl + j;
            float val = tf32r(acc[i][j]);
            if (oc < 16)      g_q[((size_t)b*NNN + n)*KDD + oc]        = val;
            else if (oc < 32) g_k[((size_t)b*NNN + n)*KDD + (oc - 16)] = val;
            else              g_v[((size_t)b*NNN + n)*DDD + (oc - 32)] = val;
        }
    }
}

// ---------------- tf32 MMA flash attention, cp.async double-buffered ----------------
#define KSTR 20     // K tile row stride (floats) -> conflict-free for (g*20+qd)%32
#define VSTR 72     // V tile row stride (floats) -> conflict-free for (qd*8+g)%32

__global__ __launch_bounds__(128) void attn_mma(const float* __restrict__ attn_bias, int head)
{
    __shared__ unsigned ksm[2][64*KSTR];
    __shared__ unsigned vsm[2][64*VSTR];
    __shared__ float    bism[2][64];

    int b  = blockIdx.x / 25;
    int q0 = (blockIdx.x % 25) * 64;
    int t    = threadIdx.x;
    int w    = t >> 5;
    int lane = t & 31;
    int g    = lane >> 2;
    int qd   = lane & 3;

    const float* kbase = g_k + (size_t)b*NNN*KDD;
    const float* vbase = g_v + (size_t)b*NNN*DDD;
    const float* bbase = attn_bias + head*NNN;

    // Q operand fragments (q values already tf32-rounded by qkv_proj)
    unsigned aQ[2][4];
    {
        int r0 = q0 + w*16 + g, r1 = r0 + 8;
        const float* qb = g_q + (size_t)b*NNN*KDD;
        #pragma unroll
        for (int ks = 0; ks < 2; ks++) {
            aQ[ks][0] = __float_as_uint(qb[(size_t)r0*KDD + ks*8 + qd]);
            aQ[ks][1] = __float_as_uint(qb[(size_t)r1*KDD + ks*8 + qd]);
            aQ[ks][2] = __float_as_uint(qb[(size_t)r0*KDD + ks*8 + qd + 4]);
            aQ[ks][3] = __float_as_uint(qb[(size_t)r1*KDD + ks*8 + qd + 4]);
        }
    }

    float Oa[8][4];
    #pragma unroll
    for (int nt = 0; nt < 8; nt++)
        #pragma unroll
        for (int j = 0; j < 4; j++) Oa[nt][j] = 0.f;
    float m0 = -1e30f, m1 = -1e30f, l0 = 0.f, l1 = 0.f;

    // ---- prefetch tile 0 ----
    {
        int k0 = 0;
        for (int i = t; i < 256; i += 128) {
            int row = i >> 2, ch = i & 3;
            cp16(&ksm[0][row*KSTR + ch*4], &kbase[(k0 + row)*KDD + ch*4]);
        }
        for (int i = t; i < 1024; i += 128) {
            int row = i >> 4, ch = i & 15;
            cp16(&vsm[0][row*VSTR + ch*4], &vbase[(size_t)(k0 + row)*DDD + ch*4]);
        }
        if (t < 16) cp16(&bism[0][t*4], &bbase[k0 + t*4]);
        CP_COMMIT;
    }

    for (int kt = 0; kt < 25; kt++) {
        int buf = kt & 1;
        if (kt + 1 < 25) {
            int k0 = (kt + 1) * 64, nb = buf ^ 1;
            for (int i = t; i < 256; i += 128) {
                int row = i >> 2, ch = i & 3;
                cp16(&ksm[nb][row*KSTR + ch*4], &kbase[(k0 + row)*KDD + ch*4]);
            }
            for (int i = t; i < 1024; i += 128) {
                int row = i >> 4, ch = i & 15;
                cp16(&vsm[nb][row*VSTR + ch*4], &vbase[(size_t)(k0 + row)*DDD + ch*4]);
            }
            if (t < 16) cp16(&bism[nb][t*4], &bbase[k0 + t*4]);
        }
        CP_COMMIT;
        CP_WAIT1;
        __syncthreads();

        // ---- S = Q K^T ----
        float Sv[8][4];
        #pragma unroll
        for (int nt = 0; nt < 8; nt++) {
            float acc[4] = {0.f, 0.f, 0.f, 0.f};
            #pragma unroll
            for (int ks = 0; ks < 2; ks++) {
                unsigned b0 = ksm[buf][(nt*8 + g)*KSTR + ks*8 + qd];
                unsigned b1 = ksm[buf][(nt*8 + g)*KSTR + ks*8 + qd + 4];
                mma_tf32(acc, aQ[ks], b0, b1);
            }
            float2 bb = *(const float2*)&bism[buf][nt*8 + 2*qd];
            Sv[nt][0] = acc[0] + bb.x;
            Sv[nt][1] = acc[1] + bb.y;
            Sv[nt][2] = acc[2] + bb.x;
            Sv[nt][3] = acc[3] + bb.y;
        }

        // ---- online softmax ----
        float mx0 = -1e30f, mx1 = -1e30f;
        #pragma unroll
        for (int nt = 0; nt < 8; nt++) {
            mx0 = fmaxf(mx0, fmaxf(Sv[nt][0], Sv[nt][1]));
            mx1 = fmaxf(mx1, fmaxf(Sv[nt][2], Sv[nt][3]));
        }
        mx0 = fmaxf(mx0, __shfl_xor_sync(0xffffffffu, mx0, 1));
        mx0 = fmaxf(mx0, __shfl_xor_sync(0xffffffffu, mx0, 2));
        mx1 = fmaxf(mx1, __shfl_xor_sync(0xffffffffu, mx1, 1));
        mx1 = fmaxf(mx1, __shfl_xor_sync(0xffffffffu, mx1, 2));

        float nm0 = fmaxf(m0, mx0), nm1 = fmaxf(m1, mx1);
        float f0 = __expf(m0 - nm0), f1 = __expf(m1 - nm1);

        unsigned P[8][4];
        float sum0 = 0.f, sum1 = 0.f;
        #pragma unroll
        for (int nt = 0; nt < 8; nt++) {
            float p0 = __expf(Sv[nt][0] - nm0);
            float p1 = __expf(Sv[nt][1] - nm0);
            float p2 = __expf(Sv[nt][2] - nm1);
            float p3 = __expf(Sv[nt][3] - nm1);
            sum0 += p0 + p1;
            sum1 += p2 + p3;
            P[nt][0] = f2tf32(p0); P[nt][1] = f2tf32(p1);
            P[nt][2] = f2tf32(p2); P[nt][3] = f2tf32(p3);
        }
        sum0 += __shfl_xor_sync(0xffffffffu, sum0, 1);
        sum0 += __shfl_xor_sync(0xffffffffu, sum0, 2);
        sum1 += __shfl_xor_sync(0xffffffffu, sum1, 1);
        sum1 += __shfl_xor_sync(0xffffffffu, sum1, 2);

        l0 = l0 * f0 + sum0;  m0 = nm0;
        l1 = l1 * f1 + sum1;  m1 = nm1;

        #pragma unroll
        for (int nt = 0; nt < 8; nt++) {
            Oa[nt][0] *= f0; Oa[nt][1] *= f0;
            Oa[nt][2] *= f1; Oa[nt][3] *= f1;
        }

        // ---- O += P V ----
        int srcA = (lane & ~3) | (qd >> 1);
        int srcB = srcA + 2;
        #pragma unroll
        for (int ks = 0; ks < 8; ks++) {
            unsigned t0 = __shfl_sync(0xffffffffu, P[ks][0], srcA);
            unsigned t1 = __shfl_sync(0xffffffffu, P[ks][1], srcA);
            unsigned t2 = __shfl_sync(0xffffffffu, P[ks][2], srcA);
            unsigned t3 = __shfl_sync(0xffffffffu, P[ks][3], srcA);
            unsigned u0 = __shfl_sync(0xffffffffu, P[ks][0], srcB);
            unsigned u1 = __shfl_sync(0xffffffffu, P[ks][1], srcB);
            unsigned u2 = __shfl_sync(0xffffffffu, P[ks][2], srcB);
            unsigned u3 = __shfl_sync(0xffffffffu, P[ks][3], srcB);
            unsigned aP[4];
            aP[0] = (qd & 1) ? t1 : t0;
            aP[1] = (qd & 1) ? t3 : t2;
            aP[2] = (qd & 1) ? u1 : u0;
            aP[3] = (qd & 1) ? u3 : u2;
            #pragma unroll
            for (int nt = 0; nt < 8; nt++) {
                unsigned b0 = vsm[buf][(ks*8 + qd    )*VSTR + nt*8 + g];
                unsigned b1 = vsm[buf][(ks*8 + qd + 4)*VSTR + nt*8 + g];
                mma_tf32(Oa[nt], aP, b0, b1);
            }
        }
        __syncthreads();
    }

    // ---- epilogue ----
    float inv0 = 1.f / l0, inv1 = 1.f / l1;
    int n0 = q0 + w*16 + g, n1 = n0 + 8;
    #pragma unroll
    for (int nt = 0; nt < 8; nt++) {
        int d = nt*8 + 2*qd;
        float o00 = Oa[nt][0] * inv0, o01 = Oa[nt][1] * inv0;
        float o10 = Oa[nt][2] * inv1, o11 = Oa[nt][3] * inv1;
        // cat: tf32-rounded (consumed by proj MMA); prev: full precision
        float2* c0 = (float2*)&g_cat[((size_t)b*NNN + n0)*DIMC + head*DDD + d];
        float2* c1 = (float2*)&g_cat[((size_t)b*NNN + n1)*DIMC + head*DDD + d];
        *c0 = make_float2(tf32r(o00), tf32r(o01));
        *c1 = make_float2(tf32r(o10), tf32r(o11));
        g_prev[((size_t)b*HDD + d    )*NNN + n0] = o00;
        g_prev[((size_t)b*HDD + d + 1)*NNN + n0] = o01;
        g_prev[((size_t)b*HDD + d    )*NNN + n1] = o10;
        g_prev[((size_t)b*HDD + d + 1)*NNN + n1] = o11;
    }
}

// ---------------- final proj: tf32 MMA, 64och x 160pos tiles, K=256 ----------------
#define PSLAB 16
#define XSTR  20
#define WSTR  20

__global__ __launch_bounds__(256) void proj_mma(float* __restrict__ out)
{
    __shared__ unsigned xsm[2][160*XSTR];
    __shared__ unsigned wsm[2][64*WSTR];

    int bi = blockIdx.x;
    int b  = bi / 40;
    int r  = bi % 40;
    int p0 = (r / 4) * 160;
    int o0 = (r % 4) * 64;

    int t    = threadIdx.x;
    int wid  = t >> 5;
    int lane = t & 31;
    int g    = lane >> 2;
    int qd   = lane & 3;
    int wo   = wid & 3;        // 4 x 16 out-channels
    int wp   = wid >> 2;       // 2 x 80 positions

    const float* xb = g_cat + (size_t)b*NNN*DIMC;

    float Oa[10][4];
    #pragma unroll
    for (int nt = 0; nt < 10; nt++)
        #pragma unroll
        for (int j = 0; j < 4; j++) Oa[nt][j] = 0.f;

    // prefetch slab 0
    {
        for (int i = t; i < 256; i += 256) {
            int row = i >> 2, ch = i & 3;
            cp16(&wsm[0][row*WSTR + ch*4], &g_p_wf[(o0 + row)*DIMC + ch*4]);
        }
        for (int i = t; i < 640; i += 256) {
            int row = i >> 2, ch = i & 3;
            cp16(&xsm[0][row*XSTR + ch*4], &xb[(size_t)(p0 + row)*DIMC + ch*4]);
        }
        CP_COMMIT;
    }

    for (int s = 0; s < 16; s++) {
        int buf = s & 1;
        if (s + 1 < 16) {
            int c0 = (s + 1) * PSLAB, nb = buf ^ 1;
            for (int i = t; i < 256; i += 256) {
                int row = i >> 2, ch = i & 3;
                cp16(&wsm[nb][row*WSTR + ch*4], &g_p_wf[(o0 + row)*DIMC + c0 + ch*4]);
            }
            for (int i = t; i < 640; i += 256) {
                int row = i >> 2, ch = i & 3;
                cp16(&xsm[nb][row*XSTR + ch*4], &xb[(size_t)(p0 + row)*DIMC + c0 + ch*4]);
            }
        }
        CP_COMMIT;
        CP_WAIT1;
        __syncthreads();

        #pragma unroll
        for (int ks = 0; ks < 2; ks++) {
            unsigned a[4];
            a[0] = wsm[buf][(wo*16 + g    )*WSTR + ks*8 + qd];
            a[1] = wsm[buf][(wo*16 + g + 8)*WSTR + ks*8 + qd];
            a[2] = wsm[buf][(wo*16 + g    )*WSTR + ks*8 + qd + 4];
            a[3] = wsm[buf][(wo*16 + g + 8)*WSTR + ks*8 + qd + 4];
            #pragma unroll
            for (int nt = 0; nt < 10; nt++) {
                unsigned b0 = xsm[buf][(wp*80 + nt*8 + g)*XSTR + ks*8 + qd];
                unsigned b1 = xsm[buf][(wp*80 + nt*8 + g)*XSTR + ks*8 + qd + 4];
                mma_tf32(Oa[nt], a, b0, b1);
            }
        }
        __syncthreads();
    }

    int orow0 = o0 + wo*16 + g, orow1 = orow0 + 8;
    float bb0 = g_p_bf[orow0], bb1 = g_p_bf[orow1];
    #pragma unroll
    for (int nt = 0; nt < 10; nt++) {
        int n = p0 + wp*80 + nt*8 + 2*qd;
        float v00 = fmaxf(Oa[nt][0] + bb0, 0.f);
        float v01 = fmaxf(Oa[nt][1] + bb0, 0.f);
        float v10 = fmaxf(Oa[nt][2] + bb1, 0.f);
        float v11 = fmaxf(Oa[nt][3] + bb1, 0.f);
        *(float2*)&out[((size_t)b*DIMC + orow0)*NNN + n] = make_float2(v00, v01);
        *(float2*)&out[((size_t)b*DIMC + orow1)*NNN + n] = make_float2(v10, v11);
    }
}

// ---------------- launch ----------------
extern "C" void kernel_launch(void* const* d_in, const int* in_sizes, int n_in,
                              void* d_out, int out_size)
{
    const float* x    = (const float*)d_in[0];
    const float* dw_w = (const float*)d_in[1];
    const float* dw_g = (const float*)d_in[2];
    const float* dw_b = (const float*)d_in[3];
    const float* dw_m = (const float*)d_in[4];
    const float* dw_v = (const float*)d_in[5];
    const float* q_w  = (const float*)d_in[6];
    const float* q_g  = (const float*)d_in[7];
    const float* q_b  = (const float*)d_in[8];
    const float* q_m  = (const float*)d_in[9];
    const float* q_v  = (const float*)d_in[10];
    const float* k_w  = (const float*)d_in[11];
    const float* k_g  = (const float*)d_in[12];
    const float* k_b  = (const float*)d_in[13];
    const float* k_m  = (const float*)d_in[14];
    const float* k_v  = (const float*)d_in[15];
    const float* v_w  = (const float*)d_in[16];
    const float* v_g  = (const float*)d_in[17];
    const float* v_b  = (const float*)d_in[18];
    const float* v_m  = (const float*)d_in[19];
    const float* v_v  = (const float*)d_in[20];
    const float* p_w  = (const float*)d_in[21];
    const float* p_g  = (const float*)d_in[22];
    const float* p_b  = (const float*)d_in[23];
    const float* p_m  = (const float*)d_in[24];
    const float* p_v  = (const float*)d_in[25];
    const float* attn_bias = (const float*)d_in[26];

    prep_fold<<<128, 256>>>(dw_w, dw_g, dw_b, dw_m, dw_v,
                            q_w, q_g, q_b, q_m, q_v,
                            k_w, k_g, k_b, k_m, k_v,
                            v_w, v_g, v_b, v_m, v_v,
                            p_w, p_g, p_b, p_m, p_v);

    for (int i = 0; i < NHH; i++) {
        dwconv_bn<<<(BBB*HDD*NNN)/256, 256>>>(x, i, i > 0 ? 1 : 0);
        qkv_proj<<<BBB*25, 256>>>(i);
        attn_mma<<<BBB*25, 128>>>(attn_bias, i);
    }

    proj_mma<<<640, 256>>>((float*)d_out);
}

// round 4
// speedup vs baseline: 4.4218x; 1.3019x over previous
#include <cuda_runtime.h>
#include <cuda_fp16.h>
#include <math.h>

#define NHH   4
#define HDD   64
#define KDD   16
#define DDD   64
#define NNN   1600
#define BBB   16
#define HIMG  40
#define WIMG  40
#define DIMC  256
#define EPSB  1e-5f
#define SCALEQ 0.25f

// ---------------- device scratch ----------------
__device__ float  g_conv[BBB*DIMC*NNN];      // all-head conv output (B,256,N)
__device__ __half g_qh [BBB*NNN*KDD];        // (B,N,16) half
__device__ __half g_kh [BBB*NNN*KDD];        // (B,N,16) half
__device__ __half g_vT [BBB*DDD*NNN];        // (B,64,N) half (transposed V)
__device__ float  g_prev[BBB*HDD*NNN];       // (B,64,N) float
__device__ __half g_cath[BBB*NNN*DIMC];      // (B,N,256) half
__device__ float  g_dw_wf[NHH*HDD*25];
__device__ float  g_dw_bf[NHH*HDD];
__device__ float  g_qkv_wf[NHH*96*HDD];
__device__ float  g_qkv_bf[NHH*96];
__device__ __half g_p_wh[DIMC*DIMC];
__device__ float  g_p_bf[DIMC];

// ---------------- helpers ----------------
__device__ __forceinline__ unsigned packh2(float a, float b) {
    __half2 h = __floats2half2_rn(a, b);
    return *(unsigned*)&h;
}
__device__ __forceinline__ void mma_f16(float c[4], const unsigned a[4],
                                        unsigned b0, unsigned b1) {
    asm volatile("mma.sync.aligned.m16n8k16.row.col.f32.f16.f16.f32 "
        "{%0,%1,%2,%3}, {%4,%5,%6,%7}, {%8,%9}, {%0,%1,%2,%3};"
        : "+f"(c[0]), "+f"(c[1]), "+f"(c[2]), "+f"(c[3])
        : "r"(a[0]), "r"(a[1]), "r"(a[2]), "r"(a[3]), "r"(b0), "r"(b1));
}
__device__ __forceinline__ void cp16(void* dst, const void* src) {
    unsigned d = (unsigned)__cvta_generic_to_shared(dst);
    asm volatile("cp.async.cg.shared.global [%0], [%1], 16;" :: "r"(d), "l"(src));
}
#define CP_COMMIT asm volatile("cp.async.commit_group;" ::: "memory")
#define CP_WAIT1  asm volatile("cp.async.wait_group 1;"  ::: "memory")

// ---------------- fold BN into weights ----------------
__global__ void prep_fold(
    const float* dw_w, const float* dw_g, const float* dw_b, const float* dw_m, const float* dw_v,
    const float* q_w,  const float* q_g,  const float* q_b,  const float* q_m,  const float* q_v,
    const float* k_w,  const float* k_g,  const float* k_b,  const float* k_m,  const float* k_v,
    const float* v_w,  const float* v_g,  const float* v_b,  const float* v_m,  const float* v_v,
    const float* p_w,  const float* p_g,  const float* p_b,  const float* p_m,  const float* p_v)
{
    int t = blockIdx.x * blockDim.x + threadIdx.x;
    int stride = gridDim.x * blockDim.x;

    for (int idx = t; idx < NHH*HDD*25; idx += stride) {
        int ch = idx / 25;
        float s = dw_g[ch] * rsqrtf(dw_v[ch] + EPSB);
        g_dw_wf[idx] = dw_w[idx] * s;
    }
    for (int ch = t; ch < NHH*HDD; ch += stride) {
        float s = dw_g[ch] * rsqrtf(dw_v[ch] + EPSB);
        g_dw_bf[ch] = dw_b[ch] - s * dw_m[ch];
    }
    for (int idx = t; idx < NHH*96*HDD; idx += stride) {
        int r = idx / HDD, c = idx % HDD;
        int i = r / 96, oc = r % 96;
        float s; const float* w;
        if (oc < 16) {
            int j = i*KDD + oc;
            s = q_g[j] * rsqrtf(q_v[j] + EPSB) * SCALEQ;
            w = q_w + (size_t)j * HDD;
        } else if (oc < 32) {
            int j = i*KDD + (oc - 16);
            s = k_g[j] * rsqrtf(k_v[j] + EPSB);
            w = k_w + (size_t)j * HDD;
        } else {
            int j = i*DDD + (oc - 32);
            s = v_g[j] * rsqrtf(v_v[j] + EPSB);
            w = v_w + (size_t)j * HDD;
        }
        g_qkv_wf[idx] = w[c] * s;
    }
    for (int r = t; r < NHH*96; r += stride) {
        int i = r / 96, oc = r % 96;
        float s, bias;
        if (oc < 16) {
            int j = i*KDD + oc;
            s = q_g[j] * rsqrtf(q_v[j] + EPSB);
            bias = (q_b[j] - s * q_m[j]) * SCALEQ;
        } else if (oc < 32) {
            int j = i*KDD + (oc - 16);
            s = k_g[j] * rsqrtf(k_v[j] + EPSB);
            bias = k_b[j] - s * k_m[j];
        } else {
            int j = i*DDD + (oc - 32);
            s = v_g[j] * rsqrtf(v_v[j] + EPSB);
            bias = v_b[j] - s * v_m[j];
        }
        g_qkv_bf[r] = bias;
    }
    for (int idx = t; idx < DIMC*DIMC; idx += stride) {
        int o = idx / DIMC;
        float s = p_g[o] * rsqrtf(p_v[o] + EPSB);
        g_p_wh[idx] = __float2half_rn(p_w[idx] * s);
    }
    for (int o = t; o < DIMC; o += stride) {
        float s = p_g[o] * rsqrtf(p_v[o] + EPSB);
        g_p_bf[o] = p_b[o] - s * p_m[o];
    }
}

// ---------------- all-head depthwise 5x5 conv + folded BN ----------------
__global__ __launch_bounds__(256) void dwconv_all(const float* __restrict__ x)
{
    int idx = blockIdx.x * 256 + threadIdx.x;
    if (idx >= BBB*DIMC*NNN) return;
    int n = idx % NNN;
    int c = (idx / NNN) % DIMC;      // global channel: head = c>>6
    int b = idx / (NNN * DIMC);
    int h = n / WIMG, w = n % WIMG;

    const float* xin = x + ((size_t)b * DIMC + c) * NNN;
    const float* wf  = g_dw_wf + c * 25;
    float acc = g_dw_bf[c];

    #pragma unroll
    for (int dy = 0; dy < 5; dy++) {
        int hh = h + dy - 2;
        if ((unsigned)hh >= (unsigned)HIMG) continue;
        #pragma unroll
        for (int dx = 0; dx < 5; dx++) {
            int ww = w + dx - 2;
            if ((unsigned)ww >= (unsigned)WIMG) continue;
            acc += wf[dy*5 + dx] * xin[hh*WIMG + ww];
        }
    }
    g_conv[((size_t)b*DIMC + c)*NNN + n] = acc;
}

// ---------------- QKV projection (+ fused prev add), half outputs ----------------
__global__ __launch_bounds__(256) void qkv_proj(int head, int addprev)
{
    __shared__ float xs[64][68];
    __shared__ float ws[96][64];
    __shared__ float bsm[96];

    int b  = blockIdx.x / 25;
    int p0 = (blockIdx.x % 25) * 64;
    int t  = threadIdx.x;

    for (int idx = t; idx < 96*64; idx += 256)
        ws[idx/64][idx%64] = g_qkv_wf[(size_t)head*96*64 + idx];
    if (t < 96) bsm[t] = g_qkv_bf[head*96 + t];
    for (int idx = t; idx < 64*64; idx += 256) {
        int c = idx / 64, p = idx % 64;
        float v = g_conv[((size_t)b*DIMC + head*HDD + c)*NNN + p0 + p];
        if (addprev) v += g_prev[((size_t)b*HDD + c)*NNN + p0 + p];
        xs[c][p] = v;
    }
    __syncthreads();

    int to  = t >> 4;
    int tp  = t & 15;
    int oc0 = to * 6, pl = tp * 4;

    float acc[6][4];
    #pragma unroll
    for (int i = 0; i < 6; i++) {
        float bb = bsm[oc0 + i];
        #pragma unroll
        for (int j = 0; j < 4; j++) acc[i][j] = bb;
    }

    #pragma unroll 8
    for (int c = 0; c < 64; c++) {
        float4 xv = *(const float4*)&xs[c][pl];
        #pragma unroll
        for (int i = 0; i < 6; i++) {
            float w = ws[oc0 + i][c];
            acc[i][0] += w * xv.x;
            acc[i][1] += w * xv.y;
            acc[i][2] += w * xv.z;
            acc[i][3] += w * xv.w;
        }
    }

    #pragma unroll
    for (int i = 0; i < 6; i++) {
        int oc = oc0 + i;
        #pragma unroll
        for (int j = 0; j < 4; j++) {
            int n = p0 + pl + j;
            __half hv = __float2half_rn(acc[i][j]);
            if (oc < 16)      g_qh[((size_t)b*NNN + n)*KDD + oc]        = hv;
            else if (oc < 32) g_kh[((size_t)b*NNN + n)*KDD + (oc - 16)] = hv;
            else              g_vT[((size_t)b*DDD + (oc - 32))*NNN + n] = hv;
        }
    }
}

// ---------------- fp16 MMA flash attention, cp.async double-buffered ----------------
#define KSTRH 24    // K tile row stride in halves (12 words: conflict-free g*12+qd)
#define VSTRH 72    // V^T tile row stride in halves (36 words: conflict-free g*36+qd)

__global__ __launch_bounds__(128) void attn_mma(const float* __restrict__ attn_bias, int head)
{
    __shared__ __align__(16) __half ksm[2][64*KSTRH];
    __shared__ __align__(16) __half vsm[2][64*VSTRH];
    __shared__ __align__(16) float  bism[2][64];

    int b  = blockIdx.x / 25;
    int q0 = (blockIdx.x % 25) * 64;
    int t    = threadIdx.x;
    int w    = t >> 5;
    int lane = t & 31;
    int g    = lane >> 2;
    int qd   = lane & 3;

    const __half* kbase = g_kh + (size_t)b*NNN*KDD;
    const __half* vbase = g_vT + (size_t)b*DDD*NNN;
    const float*  bbase = attn_bias + head*NNN;

    // Q operand fragments (m16n8k16 A layout)
    unsigned aQ[4];
    {
        int r0 = q0 + w*16 + g, r1 = r0 + 8;
        const __half* qb = g_qh + (size_t)b*NNN*KDD;
        aQ[0] = *(const unsigned*)&qb[(size_t)r0*KDD + 2*qd];
        aQ[1] = *(const unsigned*)&qb[(size_t)r1*KDD + 2*qd];
        aQ[2] = *(const unsigned*)&qb[(size_t)r0*KDD + 2*qd + 8];
        aQ[3] = *(const unsigned*)&qb[(size_t)r1*KDD + 2*qd + 8];
    }

    float Oa[8][4];
    #pragma unroll
    for (int nt = 0; nt < 8; nt++)
        #pragma unroll
        for (int j = 0; j < 4; j++) Oa[nt][j] = 0.f;
    float m0 = -1e30f, m1 = -1e30f, l0 = 0.f, l1 = 0.f;

    // ---- prefetch tile 0 ----
    {
        for (int i = t; i < 128; i += 128) {                     // K: 64 keys x 16c half
            int key = i >> 1, c8 = (i & 1) * 8;
            cp16(&ksm[0][key*KSTRH + c8], &kbase[(size_t)key*KDD + c8]);
        }
        for (int i = t; i < 512; i += 128) {                     // V^T: 64 d x 64 keys half
            int d = i >> 3, ch = i & 7;
            cp16(&vsm[0][d*VSTRH + ch*8], &vbase[(size_t)d*NNN + ch*8]);
        }
        if (t < 16) cp16(&bism[0][t*4], &bbase[t*4]);
        CP_COMMIT;
    }

    for (int kt = 0; kt < 25; kt++) {
        int buf = kt & 1;
        if (kt + 1 < 25) {
            int k0 = (kt + 1) * 64, nb = buf ^ 1;
            for (int i = t; i < 128; i += 128) {
                int key = i >> 1, c8 = (i & 1) * 8;
                cp16(&ksm[nb][key*KSTRH + c8], &kbase[(size_t)(k0 + key)*KDD + c8]);
            }
            for (int i = t; i < 512; i += 128) {
                int d = i >> 3, ch = i & 7;
                cp16(&vsm[nb][d*VSTRH + ch*8], &vbase[(size_t)d*NNN + k0 + ch*8]);
            }
            if (t < 16) cp16(&bism[nb][t*4], &bbase[k0 + t*4]);
        }
        CP_COMMIT;
        CP_WAIT1;
        __syncthreads();

        // ---- S = Q K^T : one m16n8k16 per 8-key tile ----
        float Sv[8][4];
        #pragma unroll
        for (int nt = 0; nt < 8; nt++) {
            float acc[4] = {0.f, 0.f, 0.f, 0.f};
            unsigned b0 = *(const unsigned*)&ksm[buf][(nt*8 + g)*KSTRH + 2*qd];
            unsigned b1 = *(const unsigned*)&ksm[buf][(nt*8 + g)*KSTRH + 2*qd + 8];
            mma_f16(acc, aQ, b0, b1);
            float2 bb = *(const float2*)&bism[buf][nt*8 + 2*qd];
            Sv[nt][0] = acc[0] + bb.x;
            Sv[nt][1] = acc[1] + bb.y;
            Sv[nt][2] = acc[2] + bb.x;
            Sv[nt][3] = acc[3] + bb.y;
        }

        // ---- online softmax ----
        float mx0 = -1e30f, mx1 = -1e30f;
        #pragma unroll
        for (int nt = 0; nt < 8; nt++) {
            mx0 = fmaxf(mx0, fmaxf(Sv[nt][0], Sv[nt][1]));
            mx1 = fmaxf(mx1, fmaxf(Sv[nt][2], Sv[nt][3]));
        }
        mx0 = fmaxf(mx0, __shfl_xor_sync(0xffffffffu, mx0, 1));
        mx0 = fmaxf(mx0, __shfl_xor_sync(0xffffffffu, mx0, 2));
        mx1 = fmaxf(mx1, __shfl_xor_sync(0xffffffffu, mx1, 1));
        mx1 = fmaxf(mx1, __shfl_xor_sync(0xffffffffu, mx1, 2));

        float nm0 = fmaxf(m0, mx0), nm1 = fmaxf(m1, mx1);
        float f0 = __expf(m0 - nm0), f1 = __expf(m1 - nm1);

        float sum0 = 0.f, sum1 = 0.f;
        #pragma unroll
        for (int nt = 0; nt < 8; nt++) {
            Sv[nt][0] = __expf(Sv[nt][0] - nm0);
            Sv[nt][1] = __expf(Sv[nt][1] - nm0);
            Sv[nt][2] = __expf(Sv[nt][2] - nm1);
            Sv[nt][3] = __expf(Sv[nt][3] - nm1);
            sum0 += Sv[nt][0] + Sv[nt][1];
            sum1 += Sv[nt][2] + Sv[nt][3];
        }
        sum0 += __shfl_xor_sync(0xffffffffu, sum0, 1);
        sum0 += __shfl_xor_sync(0xffffffffu, sum0, 2);
        sum1 += __shfl_xor_sync(0xffffffffu, sum1, 1);
        sum1 += __shfl_xor_sync(0xffffffffu, sum1, 2);

        l0 = l0 * f0 + sum0;  m0 = nm0;
        l1 = l1 * f1 + sum1;  m1 = nm1;

        #pragma unroll
        for (int nt = 0; nt < 8; nt++) {
            Oa[nt][0] *= f0; Oa[nt][1] *= f0;
            Oa[nt][2] *= f1; Oa[nt][3] *= f1;
        }

        // ---- pack P to fp16 A-fragments (no shuffles needed!) ----
        unsigned Ph[4][4];
        #pragma unroll
        for (int kc = 0; kc < 4; kc++) {
            Ph[kc][0] = packh2(Sv[2*kc  ][0], Sv[2*kc  ][1]);
            Ph[kc][1] = packh2(Sv[2*kc  ][2], Sv[2*kc  ][3]);
            Ph[kc][2] = packh2(Sv[2*kc+1][0], Sv[2*kc+1][1]);
            Ph[kc][3] = packh2(Sv[2*kc+1][2], Sv[2*kc+1][3]);
        }

        // ---- O += P V ----
        #pragma unroll
        for (int nt = 0; nt < 8; nt++) {
            int drow = (nt*8 + g) * VSTRH;
            #pragma unroll
            for (int kc = 0; kc < 4; kc++) {
                unsigned b0 = *(const unsigned*)&vsm[buf][drow + kc*16 + 2*qd];
                unsigned b1 = *(const unsigned*)&vsm[buf][drow + kc*16 + 2*qd + 8];
                mma_f16(Oa[nt], Ph[kc], b0, b1);
            }
        }
        __syncthreads();
    }

    // ---- epilogue: cat (half) + prev (float) ----
    float inv0 = 1.f / l0, inv1 = 1.f / l1;
    int n0 = q0 + w*16 + g, n1 = n0 + 8;
    #pragma unroll
    for (int nt = 0; nt < 8; nt++) {
        int d = nt*8 + 2*qd;
        float o00 = Oa[nt][0] * inv0, o01 = Oa[nt][1] * inv0;
        float o10 = Oa[nt][2] * inv1, o11 = Oa[nt][3] * inv1;
        *(__half2*)&g_cath[((size_t)b*NNN + n0)*DIMC + head*DDD + d] = __floats2half2_rn(o00, o01);
        *(__half2*)&g_cath[((size_t)b*NNN + n1)*DIMC + head*DDD + d] = __floats2half2_rn(o10, o11);
        g_prev[((size_t)b*HDD + d    )*NNN + n0] = o00;
        g_prev[((size_t)b*HDD + d + 1)*NNN + n0] = o01;
        g_prev[((size_t)b*HDD + d    )*NNN + n1] = o10;
        g_prev[((size_t)b*HDD + d + 1)*NNN + n1] = o11;
    }
}

// ---------------- final proj: fp16 MMA, 64och x 160pos tiles, K=256 ----------------
#define PSTRH 24    // 12 words per 16-half row -> conflict-free

__global__ __launch_bounds__(256) void proj_mma(float* __restrict__ out)
{
    __shared__ __align__(16) __half xsm[2][160*PSTRH];
    __shared__ __align__(16) __half wsm[2][64*PSTRH];

    int bi = blockIdx.x;
    int b  = bi / 40;
    int r  = bi % 40;
    int p0 = (r / 4) * 160;
    int o0 = (r % 4) * 64;

    int t    = threadIdx.x;
    int wid  = t >> 5;
    int lane = t & 31;
    int g    = lane >> 2;
    int qd   = lane & 3;
    int wo   = wid & 3;
    int wp   = wid >> 2;

    const __half* xb = g_cath + (size_t)b*NNN*DIMC;

    float Oa[10][4];
    #pragma unroll
    for (int nt = 0; nt < 10; nt++)
        #pragma unroll
        for (int j = 0; j < 4; j++) Oa[nt][j] = 0.f;

    // prefetch slab 0 (16 channels)
    {
        for (int i = t; i < 128; i += 256) {
            int row = i >> 1, c8 = (i & 1) * 8;
            cp16(&wsm[0][row*PSTRH + c8], &g_p_wh[(o0 + row)*DIMC + c8]);
        }
        for (int i = t; i < 320; i += 256) {
            int row = i >> 1, c8 = (i & 1) * 8;
            cp16(&xsm[0][row*PSTRH + c8], &xb[(size_t)(p0 + row)*DIMC + c8]);
        }
        CP_COMMIT;
    }

    for (int s = 0; s < 16; s++) {
        int buf = s & 1;
        if (s + 1 < 16) {
            int c0 = (s + 1) * 16, nb = buf ^ 1;
            for (int i = t; i < 128; i += 256) {
                int row = i >> 1, c8 = (i & 1) * 8;
                cp16(&wsm[nb][row*PSTRH + c8], &g_p_wh[(o0 + row)*DIMC + c0 + c8]);
            }
            for (int i = t; i < 320; i += 256) {
                int row = i >> 1, c8 = (i & 1) * 8;
                cp16(&xsm[nb][row*PSTRH + c8], &xb[(size_t)(p0 + row)*DIMC + c0 + c8]);
            }
        }
        CP_COMMIT;
        CP_WAIT1;
        __syncthreads();

        unsigned a[4];
        a[0] = *(const unsigned*)&wsm[buf][(wo*16 + g    )*PSTRH + 2*qd];
        a[1] = *(const unsigned*)&wsm[buf][(wo*16 + g + 8)*PSTRH + 2*qd];
        a[2] = *(const unsigned*)&wsm[buf][(wo*16 + g    )*PSTRH + 2*qd + 8];
        a[3] = *(const unsigned*)&wsm[buf][(wo*16 + g + 8)*PSTRH + 2*qd + 8];
        #pragma unroll
        for (int nt = 0; nt < 10; nt++) {
            unsigned b0 = *(const unsigned*)&xsm[buf][(wp*80 + nt*8 + g)*PSTRH + 2*qd];
            unsigned b1 = *(const unsigned*)&xsm[buf][(wp*80 + nt*8 + g)*PSTRH + 2*qd + 8];
            mma_f16(Oa[nt], a, b0, b1);
        }
        __syncthreads();
    }

    int orow0 = o0 + wo*16 + g, orow1 = orow0 + 8;
    float bb0 = g_p_bf[orow0], bb1 = g_p_bf[orow1];
    #pragma unroll
    for (int nt = 0; nt < 10; nt++) {
        int n = p0 + wp*80 + nt*8 + 2*qd;
        float v00 = fmaxf(Oa[nt][0] + bb0, 0.f);
        float v01 = fmaxf(Oa[nt][1] + bb0, 0.f);
        float v10 = fmaxf(Oa[nt][2] + bb1, 0.f);
        float v11 = fmaxf(Oa[nt][3] + bb1, 0.f);
        *(float2*)&out[((size_t)b*DIMC + orow0)*NNN + n] = make_float2(v00, v01);
        *(float2*)&out[((size_t)b*DIMC + orow1)*NNN + n] = make_float2(v10, v11);
    }
}

// ---------------- launch ----------------
extern "C" void kernel_launch(void* const* d_in, const int* in_sizes, int n_in,
                              void* d_out, int out_size)
{
    const float* x    = (const float*)d_in[0];
    const float* dw_w = (const float*)d_in[1];
    const float* dw_g = (const float*)d_in[2];
    const float* dw_b = (const float*)d_in[3];
    const float* dw_m = (const float*)d_in[4];
    const float* dw_v = (const float*)d_in[5];
    const float* q_w  = (const float*)d_in[6];
    const float* q_g  = (const float*)d_in[7];
    const float* q_b  = (const float*)d_in[8];
    const float* q_m  = (const float*)d_in[9];
    const float* q_v  = (const float*)d_in[10];
    const float* k_w  = (const float*)d_in[11];
    const float* k_g  = (const float*)d_in[12];
    const float* k_b  = (const float*)d_in[13];
    const float* k_m  = (const float*)d_in[14];
    const float* k_v  = (const float*)d_in[15];
    const float* v_w  = (const float*)d_in[16];
    const float* v_g  = (const float*)d_in[17];
    const float* v_b  = (const float*)d_in[18];
    const float* v_m  = (const float*)d_in[19];
    const float* v_v  = (const float*)d_in[20];
    const float* p_w  = (const float*)d_in[21];
    const float* p_g  = (const float*)d_in[22];
    const float* p_b  = (const float*)d_in[23];
    const float* p_m  = (const float*)d_in[24];
    const float* p_v  = (const float*)d_in[25];
    const float* attn_bias = (const float*)d_in[26];

    prep_fold<<<128, 256>>>(dw_w, dw_g, dw_b, dw_m, dw_v,
                            q_w, q_g, q_b, q_m, q_v,
                            k_w, k_g, k_b, k_m, k_v,
                            v_w, v_g, v_b, v_m, v_v,
                            p_w, p_g, p_b, p_m, p_v);

    dwconv_all<<<(BBB*DIMC*NNN)/256, 256>>>(x);

    for (int i = 0; i < NHH; i++) {
        qkv_proj<<<BBB*25, 256>>>(i, i > 0 ? 1 : 0);
        attn_mma<<<BBB*25, 128>>>(attn_bias, i);
    }

    proj_mma<<<640, 256>>>((float*)d_out);
}

// round 5
// speedup vs baseline: 5.4095x; 1.2234x over previous
#include <cuda_runtime.h>
#include <cuda_fp16.h>
#include <math.h>

#define NHH   4
#define HDD   64
#define KDD   16
#define DDD   64
#define NNN   1600
#define BBB   16
#define HIMG  40
#define WIMG  40
#define DIMC  256
#define EPSB  1e-5f
#define SCALEQ 0.25f

// ---------------- device scratch ----------------
__device__ float  g_conv[BBB*DIMC*NNN];      // conv output (B,256,N) fp32
__device__ __half g_qh [BBB*NNN*KDD];        // (B,N,16)
__device__ __half g_kh [BBB*NNN*KDD];        // (B,N,16)
__device__ __half g_vT [BBB*DDD*NNN];        // (B,64,N)
__device__ float  g_prev[BBB*HDD*NNN];       // (B,64,N) fp32
__device__ __half g_cath[BBB*NNN*DIMC];      // (B,N,256)
__device__ float  g_dw_wf[NHH*HDD*25];
__device__ float  g_dw_bf[NHH*HDD];
__device__ __half g_qkv_wh[NHH*96*HDD];      // folded half weights
__device__ float  g_qkv_bf[NHH*96];
__device__ __half g_p_wh[DIMC*DIMC];
__device__ float  g_p_bf[DIMC];

// ---------------- helpers ----------------
__device__ __forceinline__ unsigned packh2(float a, float b) {
    __half2 h = __floats2half2_rn(a, b);
    return *(unsigned*)&h;
}
__device__ __forceinline__ void mma_f16(float c[4], const unsigned a[4],
                                        unsigned b0, unsigned b1) {
    asm volatile("mma.sync.aligned.m16n8k16.row.col.f32.f16.f16.f32 "
        "{%0,%1,%2,%3}, {%4,%5,%6,%7}, {%8,%9}, {%0,%1,%2,%3};"
        : "+f"(c[0]), "+f"(c[1]), "+f"(c[2]), "+f"(c[3])
        : "r"(a[0]), "r"(a[1]), "r"(a[2]), "r"(a[3]), "r"(b0), "r"(b1));
}
__device__ __forceinline__ void ldsm4(unsigned& r0, unsigned& r1, unsigned& r2, unsigned& r3,
                                      unsigned addr) {
    asm volatile("ldmatrix.sync.aligned.m8n8.x4.shared.b16 {%0,%1,%2,%3}, [%4];"
        : "=r"(r0), "=r"(r1), "=r"(r2), "=r"(r3) : "r"(addr));
}
__device__ __forceinline__ void cp16(void* dst, const void* src) {
    unsigned d = (unsigned)__cvta_generic_to_shared(dst);
    asm volatile("cp.async.cg.shared.global [%0], [%1], 16;" :: "r"(d), "l"(src));
}
#define CP_COMMIT asm volatile("cp.async.commit_group;" ::: "memory")
#define CP_WAIT1  asm volatile("cp.async.wait_group 1;"  ::: "memory")
#define CP_WAIT0  asm volatile("cp.async.wait_group 0;"  ::: "memory")

// ---------------- fold BN into weights ----------------
__global__ void prep_fold(
    const float* dw_w, const float* dw_g, const float* dw_b, const float* dw_m, const float* dw_v,
    const float* q_w,  const float* q_g,  const float* q_b,  const float* q_m,  const float* q_v,
    const float* k_w,  const float* k_g,  const float* k_b,  const float* k_m,  const float* k_v,
    const float* v_w,  const float* v_g,  const float* v_b,  const float* v_m,  const float* v_v,
    const float* p_w,  const float* p_g,  const float* p_b,  const float* p_m,  const float* p_v)
{
    int t = blockIdx.x * blockDim.x + threadIdx.x;
    int stride = gridDim.x * blockDim.x;

    for (int idx = t; idx < NHH*HDD*25; idx += stride) {
        int ch = idx / 25;
        float s = dw_g[ch] * rsqrtf(dw_v[ch] + EPSB);
        g_dw_wf[idx] = dw_w[idx] * s;
    }
    for (int ch = t; ch < NHH*HDD; ch += stride) {
        float s = dw_g[ch] * rsqrtf(dw_v[ch] + EPSB);
        g_dw_bf[ch] = dw_b[ch] - s * dw_m[ch];
    }
    for (int idx = t; idx < NHH*96*HDD; idx += stride) {
        int r = idx / HDD, c = idx % HDD;
        int i = r / 96, oc = r % 96;
        float s; const float* w;
        if (oc < 16) {
            int j = i*KDD + oc;
            s = q_g[j] * rsqrtf(q_v[j] + EPSB) * SCALEQ;
            w = q_w + (size_t)j * HDD;
        } else if (oc < 32) {
            int j = i*KDD + (oc - 16);
            s = k_g[j] * rsqrtf(k_v[j] + EPSB);
            w = k_w + (size_t)j * HDD;
        } else {
            int j = i*DDD + (oc - 32);
            s = v_g[j] * rsqrtf(v_v[j] + EPSB);
            w = v_w + (size_t)j * HDD;
        }
        g_qkv_wh[idx] = __float2half_rn(w[c] * s);
    }
    for (int r = t; r < NHH*96; r += stride) {
        int i = r / 96, oc = r % 96;
        float s, bias;
        if (oc < 16) {
            int j = i*KDD + oc;
            s = q_g[j] * rsqrtf(q_v[j] + EPSB);
            bias = (q_b[j] - s * q_m[j]) * SCALEQ;
        } else if (oc < 32) {
            int j = i*KDD + (oc - 16);
            s = k_g[j] * rsqrtf(k_v[j] + EPSB);
            bias = k_b[j] - s * k_m[j];
        } else {
            int j = i*DDD + (oc - 32);
            s = v_g[j] * rsqrtf(v_v[j] + EPSB);
            bias = v_b[j] - s * v_m[j];
        }
        g_qkv_bf[r] = bias;
    }
    for (int idx = t; idx < DIMC*DIMC; idx += stride) {
        int o = idx / DIMC;
        float s = p_g[o] * rsqrtf(p_v[o] + EPSB);
        g_p_wh[idx] = __float2half_rn(p_w[idx] * s);
    }
    for (int o = t; o < DIMC; o += stride) {
        float s = p_g[o] * rsqrtf(p_v[o] + EPSB);
        g_p_bf[o] = p_b[o] - s * p_m[o];
    }
}

// ---------------- all-head depthwise 5x5 conv + folded BN ----------------
__global__ __launch_bounds__(256) void dwconv_all(const float* __restrict__ x)
{
    int idx = blockIdx.x * 256 + threadIdx.x;
    if (idx >= BBB*DIMC*NNN) return;
    int n = idx % NNN;
    int c = (idx / NNN) % DIMC;
    int b = idx / (NNN * DIMC);
    int h = n / WIMG, w = n % WIMG;

    const float* xin = x + ((size_t)b * DIMC + c) * NNN;
    const float* wf  = g_dw_wf + c * 25;
    float acc = g_dw_bf[c];

    #pragma unroll
    for (int dy = 0; dy < 5; dy++) {
        int hh = h + dy - 2;
        if ((unsigned)hh >= (unsigned)HIMG) continue;
        #pragma unroll
        for (int dx = 0; dx < 5; dx++) {
            int ww = w + dx - 2;
            if ((unsigned)ww >= (unsigned)WIMG) continue;
            acc += wf[dy*5 + dx] * xin[hh*WIMG + ww];
        }
    }
    g_conv[((size_t)b*DIMC + c)*NNN + n] = acc;
}

// ---------------- QKV projection via fp16 MMA (+ fused prev add) ----------------
// Block: 256 threads (8 warps), one (b, 64-pos tile). Warp w owns n-tile w (8 pos),
// computes all 96 out-channels (6 m16 tiles) over K=64.
__global__ __launch_bounds__(256) void qkv_mma(int head, int addprev)
{
    __shared__ __align__(16) __half wsh[96*72];   // [oc][c], stride 72 halves
    __shared__ __align__(16) __half xsh[64*72];   // [pos][c], stride 72 halves

    int b  = blockIdx.x / 25;
    int p0 = (blockIdx.x % 25) * 64;
    int t  = threadIdx.x;
    int wp   = t >> 5;
    int lane = t & 31;
    int g    = lane >> 2;
    int qd   = lane & 3;

    // stage weights (half, cp.async)
    for (int i = t; i < 768; i += 256) {
        int row = i >> 3, c8 = (i & 7) * 8;
        cp16(&wsh[row*72 + c8], &g_qkv_wh[(size_t)head*96*64 + row*64 + c8]);
    }
    CP_COMMIT;

    // stage x transposed: conv (c-major) + prev -> xsh[pos][c] half
    {
        int c  = t >> 2;
        int ps = (t & 3) * 16;
        const float* cb = g_conv + ((size_t)b*DIMC + head*HDD + c)*NNN + p0 + ps;
        const float* pb = g_prev + ((size_t)b*HDD + c)*NNN + p0 + ps;
        #pragma unroll
        for (int j4 = 0; j4 < 4; j4++) {
            float4 f = *(const float4*)&cb[j4*4];
            if (addprev) {
                float4 pv = *(const float4*)&pb[j4*4];
                f.x += pv.x; f.y += pv.y; f.z += pv.z; f.w += pv.w;
            }
            xsh[(ps + j4*4 + 0)*72 + c] = __float2half_rn(f.x);
            xsh[(ps + j4*4 + 1)*72 + c] = __float2half_rn(f.y);
            xsh[(ps + j4*4 + 2)*72 + c] = __float2half_rn(f.z);
            xsh[(ps + j4*4 + 3)*72 + c] = __float2half_rn(f.w);
        }
    }
    CP_WAIT0;
    __syncthreads();

    int n0 = wp * 8;
    float acc[6][4];
    #pragma unroll
    for (int mt = 0; mt < 6; mt++)
        #pragma unroll
        for (int j = 0; j < 4; j++) acc[mt][j] = 0.f;

    #pragma unroll
    for (int ks = 0; ks < 4; ks++) {
        unsigned b0 = *(const unsigned*)&xsh[(n0 + g)*72 + ks*16 + 2*qd];
        unsigned b1 = *(const unsigned*)&xsh[(n0 + g)*72 + ks*16 + 2*qd + 8];
        #pragma unroll
        for (int mt = 0; mt < 6; mt++) {
            unsigned a[4];
            a[0] = *(const unsigned*)&wsh[(mt*16 + g    )*72 + ks*16 + 2*qd];
            a[1] = *(const unsigned*)&wsh[(mt*16 + g + 8)*72 + ks*16 + 2*qd];
            a[2] = *(const unsigned*)&wsh[(mt*16 + g    )*72 + ks*16 + 2*qd + 8];
            a[3] = *(const unsigned*)&wsh[(mt*16 + g + 8)*72 + ks*16 + 2*qd + 8];
            mma_f16(acc[mt], a, b0, b1);
        }
    }

    // epilogue
    int n = p0 + n0 + 2*qd;
    #pragma unroll
    for (int mt = 0; mt < 6; mt++) {
        int oc0 = mt*16 + g, oc1 = oc0 + 8;
        float bb0 = g_qkv_bf[head*96 + oc0];
        float bb1 = g_qkv_bf[head*96 + oc1];
        float v00 = acc[mt][0] + bb0, v01 = acc[mt][1] + bb0;
        float v10 = acc[mt][2] + bb1, v11 = acc[mt][3] + bb1;
        if (mt == 0) {
            g_qh[((size_t)b*NNN + n    )*KDD + oc0] = __float2half_rn(v00);
            g_qh[((size_t)b*NNN + n + 1)*KDD + oc0] = __float2half_rn(v01);
            g_qh[((size_t)b*NNN + n    )*KDD + oc1] = __float2half_rn(v10);
            g_qh[((size_t)b*NNN + n + 1)*KDD + oc1] = __float2half_rn(v11);
        } else if (mt == 1) {
            int k0 = oc0 - 16, k1 = oc1 - 16;
            g_kh[((size_t)b*NNN + n    )*KDD + k0] = __float2half_rn(v00);
            g_kh[((size_t)b*NNN + n + 1)*KDD + k0] = __float2half_rn(v01);
            g_kh[((size_t)b*NNN + n    )*KDD + k1] = __float2half_rn(v10);
            g_kh[((size_t)b*NNN + n + 1)*KDD + k1] = __float2half_rn(v11);
        } else {
            int d0 = oc0 - 32, d1 = oc1 - 32;
            *(__half2*)&g_vT[((size_t)b*DDD + d0)*NNN + n] = __floats2half2_rn(v00, v01);
            *(__half2*)&g_vT[((size_t)b*DDD + d1)*NNN + n] = __floats2half2_rn(v10, v11);
        }
    }
}

// ---------------- fp16 MMA flash attention, ldmatrix + cp.async ----------------
#define KSTRH 24
#define VSTRH 72

__global__ __launch_bounds__(128) void attn_mma(const float* __restrict__ attn_bias, int head)
{
    __shared__ __align__(16) __half ksm[2][64*KSTRH];
    __shared__ __align__(16) __half vsm[2][64*VSTRH];
    __shared__ __align__(16) float  bism[2][64];

    int b  = blockIdx.x / 25;
    int q0 = (blockIdx.x % 25) * 64;
    int t    = threadIdx.x;
    int w    = t >> 5;
    int lane = t & 31;
    int g    = lane >> 2;
    int qd   = lane & 3;
    int mi   = lane >> 3;     // ldmatrix matrix index
    int mr   = lane & 7;      // ldmatrix row within matrix

    const __half* kbase = g_kh + (size_t)b*NNN*KDD;
    const __half* vbase = g_vT + (size_t)b*DDD*NNN;
    const float*  bbase = attn_bias + head*NNN;

    // ldmatrix per-thread base addresses (both buffers)
    unsigned kofs = ((((mi>>1)*8 + mr)*KSTRH) + (mi & 1)*8) * 2;
    unsigned vofs = ((mr*VSTRH) + mi*8) * 2;
    unsigned kAddr[2], vAddr[2];
    kAddr[0] = (unsigned)__cvta_generic_to_shared(&ksm[0][0]) + kofs;
    kAddr[1] = (unsigned)__cvta_generic_to_shared(&ksm[1][0]) + kofs;
    vAddr[0] = (unsigned)__cvta_generic_to_shared(&vsm[0][0]) + vofs;
    vAddr[1] = (unsigned)__cvta_generic_to_shared(&vsm[1][0]) + vofs;

    // Q operand fragments
    unsigned aQ[4];
    {
        int r0 = q0 + w*16 + g, r1 = r0 + 8;
        const __half* qb = g_qh + (size_t)b*NNN*KDD;
        aQ[0] = *(const unsigned*)&qb[(size_t)r0*KDD + 2*qd];
        aQ[1] = *(const unsigned*)&qb[(size_t)r1*KDD + 2*qd];
        aQ[2] = *(const unsigned*)&qb[(size_t)r0*KDD + 2*qd + 8];
        aQ[3] = *(const unsigned*)&qb[(size_t)r1*KDD + 2*qd + 8];
    }

    float Oa[8][4];
    #pragma unroll
    for (int nt = 0; nt < 8; nt++)
        #pragma unroll
        for (int j = 0; j < 4; j++) Oa[nt][j] = 0.f;
    float m0 = -1e30f, m1 = -1e30f, l0 = 0.f, l1 = 0.f;

    // prefetch tile 0
    {
        for (int i = t; i < 128; i += 128) {
            int key = i >> 1, c8 = (i & 1) * 8;
            cp16(&ksm[0][key*KSTRH + c8], &kbase[(size_t)key*KDD + c8]);
        }
        for (int i = t; i < 512; i += 128) {
            int d = i >> 3, ch = i & 7;
            cp16(&vsm[0][d*VSTRH + ch*8], &vbase[(size_t)d*NNN + ch*8]);
        }
        if (t < 16) cp16(&bism[0][t*4], &bbase[t*4]);
        CP_COMMIT;
    }

    for (int kt = 0; kt < 25; kt++) {
        int buf = kt & 1;
        if (kt + 1 < 25) {
            int k0 = (kt + 1) * 64, nb = buf ^ 1;
            for (int i = t; i < 128; i += 128) {
                int key = i >> 1, c8 = (i & 1) * 8;
                cp16(&ksm[nb][key*KSTRH + c8], &kbase[(size_t)(k0 + key)*KDD + c8]);
            }
            for (int i = t; i < 512; i += 128) {
                int d = i >> 3, ch = i & 7;
                cp16(&vsm[nb][d*VSTRH + ch*8], &vbase[(size_t)d*NNN + k0 + ch*8]);
            }
            if (t < 16) cp16(&bism[nb][t*4], &bbase[k0 + t*4]);
        }
        CP_COMMIT;
        CP_WAIT1;
        __syncthreads();

        // ---- S = Q K^T via ldmatrix (2 n-tiles per x4) ----
        float Sv[8][4];
        #pragma unroll
        for (int j = 0; j < 4; j++) {
            unsigned r0, r1, r2, r3;
            ldsm4(r0, r1, r2, r3, kAddr[buf] + j*(16*KSTRH*2));
            Sv[2*j  ][0] = Sv[2*j  ][1] = Sv[2*j  ][2] = Sv[2*j  ][3] = 0.f;
            Sv[2*j+1][0] = Sv[2*j+1][1] = Sv[2*j+1][2] = Sv[2*j+1][3] = 0.f;
            mma_f16(Sv[2*j  ], aQ, r0, r1);
            mma_f16(Sv[2*j+1], aQ, r2, r3);
        }
        #pragma unroll
        for (int nt = 0; nt < 8; nt++) {
            float2 bb = *(const float2*)&bism[buf][nt*8 + 2*qd];
            Sv[nt][0] += bb.x;  Sv[nt][1] += bb.y;
            Sv[nt][2] += bb.x;  Sv[nt][3] += bb.y;
        }

        // ---- online softmax ----
        float mx0 = -1e30f, mx1 = -1e30f;
        #pragma unroll
        for (int nt = 0; nt < 8; nt++) {
            mx0 = fmaxf(mx0, fmaxf(Sv[nt][0], Sv[nt][1]));
            mx1 = fmaxf(mx1, fmaxf(Sv[nt][2], Sv[nt][3]));
        }
        mx0 = fmaxf(mx0, __shfl_xor_sync(0xffffffffu, mx0, 1));
        mx0 = fmaxf(mx0, __shfl_xor_sync(0xffffffffu, mx0, 2));
        mx1 = fmaxf(mx1, __shfl_xor_sync(0xffffffffu, mx1, 1));
        mx1 = fmaxf(mx1, __shfl_xor_sync(0xffffffffu, mx1, 2));

        float nm0 = fmaxf(m0, mx0), nm1 = fmaxf(m1, mx1);
        float f0 = __expf(m0 - nm0), f1 = __expf(m1 - nm1);

        float sum0 = 0.f, sum1 = 0.f;
        #pragma unroll
        for (int nt = 0; nt < 8; nt++) {
            Sv[nt][0] = __expf(Sv[nt][0] - nm0);
            Sv[nt][1] = __expf(Sv[nt][1] - nm0);
            Sv[nt][2] = __expf(Sv[nt][2] - nm1);
            Sv[nt][3] = __expf(Sv[nt][3] - nm1);
            sum0 += Sv[nt][0] + Sv[nt][1];
            sum1 += Sv[nt][2] + Sv[nt][3];
        }
        sum0 += __shfl_xor_sync(0xffffffffu, sum0, 1);
        sum0 += __shfl_xor_sync(0xffffffffu, sum0, 2);
        sum1 += __shfl_xor_sync(0xffffffffu, sum1, 1);
        sum1 += __shfl_xor_sync(0xffffffffu, sum1, 2);

        l0 = l0 * f0 + sum0;  m0 = nm0;
        l1 = l1 * f1 + sum1;  m1 = nm1;

        #pragma unroll
        for (int nt = 0; nt < 8; nt++) {
            Oa[nt][0] *= f0; Oa[nt][1] *= f0;
            Oa[nt][2] *= f1; Oa[nt][3] *= f1;
        }

        // ---- pack P to fp16 A-fragments ----
        unsigned Ph[4][4];
        #pragma unroll
        for (int kc = 0; kc < 4; kc++) {
            Ph[kc][0] = packh2(Sv[2*kc  ][0], Sv[2*kc  ][1]);
            Ph[kc][1] = packh2(Sv[2*kc  ][2], Sv[2*kc  ][3]);
            Ph[kc][2] = packh2(Sv[2*kc+1][0], Sv[2*kc+1][1]);
            Ph[kc][3] = packh2(Sv[2*kc+1][2], Sv[2*kc+1][3]);
        }

        // ---- O += P V via ldmatrix ----
        #pragma unroll
        for (int nt = 0; nt < 8; nt++) {
            unsigned base = vAddr[buf] + nt*(8*VSTRH*2);
            unsigned c0, c1, c2, c3;
            ldsm4(c0, c1, c2, c3, base);
            mma_f16(Oa[nt], Ph[0], c0, c1);
            mma_f16(Oa[nt], Ph[1], c2, c3);
            ldsm4(c0, c1, c2, c3, base + 64);
            mma_f16(Oa[nt], Ph[2], c0, c1);
            mma_f16(Oa[nt], Ph[3], c2, c3);
        }
        __syncthreads();
    }

    // ---- epilogue ----
    float inv0 = 1.f / l0, inv1 = 1.f / l1;
    int n0 = q0 + w*16 + g, n1 = n0 + 8;
    #pragma unroll
    for (int nt = 0; nt < 8; nt++) {
        int d = nt*8 + 2*qd;
        float o00 = Oa[nt][0] * inv0, o01 = Oa[nt][1] * inv0;
        float o10 = Oa[nt][2] * inv1, o11 = Oa[nt][3] * inv1;
        *(__half2*)&g_cath[((size_t)b*NNN + n0)*DIMC + head*DDD + d] = __floats2half2_rn(o00, o01);
        *(__half2*)&g_cath[((size_t)b*NNN + n1)*DIMC + head*DDD + d] = __floats2half2_rn(o10, o11);
        g_prev[((size_t)b*HDD + d    )*NNN + n0] = o00;
        g_prev[((size_t)b*HDD + d + 1)*NNN + n0] = o01;
        g_prev[((size_t)b*HDD + d    )*NNN + n1] = o10;
        g_prev[((size_t)b*HDD + d + 1)*NNN + n1] = o11;
    }
}

// ---------------- final proj: fp16 MMA, 64och x 160pos tiles, K=256 ----------------
#define PSTRH 24

__global__ __launch_bounds__(256) void proj_mma(float* __restrict__ out)
{
    __shared__ __align__(16) __half xsm[2][160*PSTRH];
    __shared__ __align__(16) __half wsm[2][64*PSTRH];

    int bi = blockIdx.x;
    int b  = bi / 40;
    int r  = bi % 40;
    int p0 = (r / 4) * 160;
    int o0 = (r % 4) * 64;

    int t    = threadIdx.x;
    int wid  = t >> 5;
    int lane = t & 31;
    int g    = lane >> 2;
    int qd   = lane & 3;
    int wo   = wid & 3;
    int wp   = wid >> 2;

    const __half* xb = g_cath + (size_t)b*NNN*DIMC;

    float Oa[10][4];
    #pragma unroll
    for (int nt = 0; nt < 10; nt++)
        #pragma unroll
        for (int j = 0; j < 4; j++) Oa[nt][j] = 0.f;

    {
        for (int i = t; i < 128; i += 256) {
            int row = i >> 1, c8 = (i & 1) * 8;
            cp16(&wsm[0][row*PSTRH + c8], &g_p_wh[(o0 + row)*DIMC + c8]);
        }
        for (int i = t; i < 320; i += 256) {
            int row = i >> 1, c8 = (i & 1) * 8;
            cp16(&xsm[0][row*PSTRH + c8], &xb[(size_t)(p0 + row)*DIMC + c8]);
        }
        CP_COMMIT;
    }

    for (int s = 0; s < 16; s++) {
        int buf = s & 1;
        if (s + 1 < 16) {
            int c0 = (s + 1) * 16, nb = buf ^ 1;
            for (int i = t; i < 128; i += 256) {
                int row = i >> 1, c8 = (i & 1) * 8;
                cp16(&wsm[nb][row*PSTRH + c8], &g_p_wh[(o0 + row)*DIMC + c0 + c8]);
            }
            for (int i = t; i < 320; i += 256) {
                int row = i >> 1, c8 = (i & 1) * 8;
                cp16(&xsm[nb][row*PSTRH + c8], &xb[(size_t)(p0 + row)*DIMC + c0 + c8]);
            }
        }
        CP_COMMIT;
        CP_WAIT1;
        __syncthreads();

        unsigned a[4];
        a[0] = *(const unsigned*)&wsm[buf][(wo*16 + g    )*PSTRH + 2*qd];
        a[1] = *(const unsigned*)&wsm[buf][(wo*16 + g + 8)*PSTRH + 2*qd];
        a[2] = *(const unsigned*)&wsm[buf][(wo*16 + g    )*PSTRH + 2*qd + 8];
        a[3] = *(const unsigned*)&wsm[buf][(wo*16 + g + 8)*PSTRH + 2*qd + 8];
        #pragma unroll
        for (int nt = 0; nt < 10; nt++) {
            unsigned b0 = *(const unsigned*)&xsm[buf][(wp*80 + nt*8 + g)*PSTRH + 2*qd];
            unsigned b1 = *(const unsigned*)&xsm[buf][(wp*80 + nt*8 + g)*PSTRH + 2*qd + 8];
            mma_f16(Oa[nt], a, b0, b1);
        }
        __syncthreads();
    }

    int orow0 = o0 + wo*16 + g, orow1 = orow0 + 8;
    float bb0 = g_p_bf[orow0], bb1 = g_p_bf[orow1];
    #pragma unroll
    for (int nt = 0; nt < 10; nt++) {
        int n = p0 + wp*80 + nt*8 + 2*qd;
        float v00 = fmaxf(Oa[nt][0] + bb0, 0.f);
        float v01 = fmaxf(Oa[nt][1] + bb0, 0.f);
        float v10 = fmaxf(Oa[nt][2] + bb1, 0.f);
        float v11 = fmaxf(Oa[nt][3] + bb1, 0.f);
        *(float2*)&out[((size_t)b*DIMC + orow0)*NNN + n] = make_float2(v00, v01);
        *(float2*)&out[((size_t)b*DIMC + orow1)*NNN + n] = make_float2(v10, v11);
    }
}

// ---------------- launch ----------------
extern "C" void kernel_launch(void* const* d_in, const int* in_sizes, int n_in,
                              void* d_out, int out_size)
{
    const float* x    = (const float*)d_in[0];
    const float* dw_w = (const float*)d_in[1];
    const float* dw_g = (const float*)d_in[2];
    const float* dw_b = (const float*)d_in[3];
    const float* dw_m = (const float*)d_in[4];
    const float* dw_v = (const float*)d_in[5];
    const float* q_w  = (const float*)d_in[6];
    const float* q_g  = (const float*)d_in[7];
    const float* q_b  = (const float*)d_in[8];
    const float* q_m  = (const float*)d_in[9];
    const float* q_v  = (const float*)d_in[10];
    const float* k_w  = (const float*)d_in[11];
    const float* k_g  = (const float*)d_in[12];
    const float* k_b  = (const float*)d_in[13];
    const float* k_m  = (const float*)d_in[14];
    const float* k_v  = (const float*)d_in[15];
    const float* v_w  = (const float*)d_in[16];
    const float* v_g  = (const float*)d_in[17];
    const float* v_b  = (const float*)d_in[18];
    const float* v_m  = (const float*)d_in[19];
    const float* v_v  = (const float*)d_in[20];
    const float* p_w  = (const float*)d_in[21];
    const float* p_g  = (const float*)d_in[22];
    const float* p_b  = (const float*)d_in[23];
    const float* p_m  = (const float*)d_in[24];
    const float* p_v  = (const float*)d_in[25];
    const float* attn_bias = (const float*)d_in[26];

    prep_fold<<<128, 256>>>(dw_w, dw_g, dw_b, dw_m, dw_v,
                            q_w, q_g, q_b, q_m, q_v,
                            k_w, k_g, k_b, k_m, k_v,
                            v_w, v_g, v_b, v_m, v_v,
                            p_w, p_g, p_b, p_m, p_v);

    dwconv_all<<<(BBB*DIMC*NNN)/256, 256>>>(x);

    for (int i = 0; i < NHH; i++) {
        qkv_mma<<<BBB*25, 256>>>(i, i > 0 ? 1 : 0);
        attn_mma<<<BBB*25, 128>>>(attn_bias, i);
    }

    proj_mma<<<640, 256>>>((float*)d_out);
}

// round 7
// speedup vs baseline: 5.9549x; 1.1008x over previous
#include <cuda_runtime.h>
#include <cuda_fp16.h>
#include <math.h>

#define NHH   4
#define HDD   64
#define KDD   16
#define DDD   64
#define NNN   1600
#define BBB   16
#define HIMG  40
#define WIMG  40
#define DIMC  256
#define EPSB  1e-5f
#define SCALEQ 0.25f
#define L2E   1.4426950408889634f

// ---------------- device scratch ----------------
__device__ float    g_conv[BBB*DIMC*NNN];
__device__ __half   g_qh [BBB*NNN*KDD];
__device__ __half   g_kh [BBB*NNN*KDD];
__device__ __half   g_vT [BBB*DDD*NNN];
__device__ float    g_prev[BBB*HDD*NNN];
__device__ __half   g_cath[BBB*NNN*DIMC];
__device__ float    g_dw_wf[NHH*HDD*25];
__device__ float    g_dw_bf[NHH*HDD];
__device__ __half   g_qkv_wh[NHH*96*HDD];
__device__ float    g_qkv_bf[NHH*96];
__device__ __half   g_p_wh[DIMC*DIMC];
__device__ float    g_p_bf[DIMC];
__device__ unsigned g_kmaxu[NHH*BBB];     // max ||k||^2 per (head,b), float bits
__device__ float    g_bmax[NHH];          // max(bias)*log2e per head

// ---------------- helpers ----------------
__device__ __forceinline__ float ex2(float x) {
    float r; asm("ex2.approx.f32 %0, %1;" : "=f"(r) : "f"(x)); return r;
}
__device__ __forceinline__ unsigned packh2(float a, float b) {
    __half2 h = __floats2half2_rn(a, b);
    return *(unsigned*)&h;
}
__device__ __forceinline__ void mma_f16(float c[4], const unsigned a[4],
                                        unsigned b0, unsigned b1) {
    asm volatile("mma.sync.aligned.m16n8k16.row.col.f32.f16.f16.f32 "
        "{%0,%1,%2,%3}, {%4,%5,%6,%7}, {%8,%9}, {%0,%1,%2,%3};"
        : "+f"(c[0]), "+f"(c[1]), "+f"(c[2]), "+f"(c[3])
        : "r"(a[0]), "r"(a[1]), "r"(a[2]), "r"(a[3]), "r"(b0), "r"(b1));
}
__device__ __forceinline__ void ldsm4(unsigned& r0, unsigned& r1, unsigned& r2, unsigned& r3,
                                      unsigned addr) {
    asm volatile("ldmatrix.sync.aligned.m8n8.x4.shared.b16 {%0,%1,%2,%3}, [%4];"
        : "=r"(r0), "=r"(r1), "=r"(r2), "=r"(r3) : "r"(addr));
}
__device__ __forceinline__ void cp16(void* dst, const void* src) {
    unsigned d = (unsigned)__cvta_generic_to_shared(dst);
    asm volatile("cp.async.cg.shared.global [%0], [%1], 16;" :: "r"(d), "l"(src));
}
#define CP_COMMIT asm volatile("cp.async.commit_group;" ::: "memory")
#define CP_WAIT1  asm volatile("cp.async.wait_group 1;"  ::: "memory")
#define CP_WAIT0  asm volatile("cp.async.wait_group 0;"  ::: "memory")

// ---------------- fold BN into weights + bias-max + kmax reset ----------------
__global__ void prep_fold(
    const float* dw_w, const float* dw_g, const float* dw_b, const float* dw_m, const float* dw_v,
    const float* q_w,  const float* q_g,  const float* q_b,  const float* q_m,  const float* q_v,
    const float* k_w,  const float* k_g,  const float* k_b,  const float* k_m,  const float* k_v,
    const float* v_w,  const float* v_g,  const float* v_b,  const float* v_m,  const float* v_v,
    const float* p_w,  const float* p_g,  const float* p_b,  const float* p_m,  const float* p_v,
    const float* attn_bias)
{
    int t = blockIdx.x * blockDim.x + threadIdx.x;
    int stride = gridDim.x * blockDim.x;

    for (int idx = t; idx < NHH*HDD*25; idx += stride) {
        int ch = idx / 25;
        float s = dw_g[ch] * rsqrtf(dw_v[ch] + EPSB);
        g_dw_wf[idx] = dw_w[idx] * s;
    }
    for (int ch = t; ch < NHH*HDD; ch += stride) {
        float s = dw_g[ch] * rsqrtf(dw_v[ch] + EPSB);
        g_dw_bf[ch] = dw_b[ch] - s * dw_m[ch];
    }
    for (int idx = t; idx < NHH*96*HDD; idx += stride) {
        int r = idx / HDD, c = idx % HDD;
        int i = r / 96, oc = r % 96;
        float s; const float* w;
        if (oc < 16) {
            int j = i*KDD + oc;
            s = q_g[j] * rsqrtf(q_v[j] + EPSB) * (SCALEQ * L2E);   // log2e folded into q
            w = q_w + (size_t)j * HDD;
        } else if (oc < 32) {
            int j = i*KDD + (oc - 16);
            s = k_g[j] * rsqrtf(k_v[j] + EPSB);
            w = k_w + (size_t)j * HDD;
        } else {
            int j = i*DDD + (oc - 32);
            s = v_g[j] * rsqrtf(v_v[j] + EPSB);
            w = v_w + (size_t)j * HDD;
        }
        g_qkv_wh[idx] = __float2half_rn(w[c] * s);
    }
    for (int r = t; r < NHH*96; r += stride) {
        int i = r / 96, oc = r % 96;
        float s, bias;
        if (oc < 16) {
            int j = i*KDD + oc;
            s = q_g[j] * rsqrtf(q_v[j] + EPSB);
            bias = (q_b[j] - s * q_m[j]) * (SCALEQ * L2E);
        } else if (oc < 32) {
            int j = i*KDD + (oc - 16);
            s = k_g[j] * rsqrtf(k_v[j] + EPSB);
            bias = k_b[j] - s * k_m[j];
        } else {
            int j = i*DDD + (oc - 32);
            s = v_g[j] * rsqrtf(v_v[j] + EPSB);
            bias = v_b[j] - s * v_m[j];
        }
        g_qkv_bf[r] = bias;
    }
    for (int idx = t; idx < DIMC*DIMC; idx += stride) {
        int o = idx / DIMC;
        float s = p_g[o] * rsqrtf(p_v[o] + EPSB);
        g_p_wh[idx] = __float2half_rn(p_w[idx] * s);
    }
    for (int o = t; o < DIMC; o += stride) {
        float s = p_g[o] * rsqrtf(p_v[o] + EPSB);
        g_p_bf[o] = p_b[o] - s * p_m[o];
    }

    // block 0: reset kmax + compute per-head bias max (warp per head)
    if (blockIdx.x == 0) {
        int tt = threadIdx.x;
        if (tt < NHH*BBB) g_kmaxu[tt] = 0u;
        int wrp = tt >> 5, ln = tt & 31;
        if (wrp < NHH) {
            float mx = -1e30f;
            for (int n = ln; n < NNN; n += 32)
                mx = fmaxf(mx, attn_bias[wrp*NNN + n]);
            #pragma unroll
            for (int msk = 16; msk; msk >>= 1)
                mx = fmaxf(mx, __shfl_xor_sync(0xffffffffu, mx, msk));
            if (ln == 0) g_bmax[wrp] = mx * L2E;
        }
    }
}

// ---------------- all-head depthwise 5x5 conv + folded BN ----------------
__global__ __launch_bounds__(256) void dwconv_all(const float* __restrict__ x)
{
    int idx = blockIdx.x * 256 + threadIdx.x;
    if (idx >= BBB*DIMC*NNN) return;
    int n = idx % NNN;
    int c = (idx / NNN) % DIMC;
    int b = idx / (NNN * DIMC);
    int h = n / WIMG, w = n % WIMG;

    const float* xin = x + ((size_t)b * DIMC + c) * NNN;
    const float* wf  = g_dw_wf + c * 25;
    float acc = g_dw_bf[c];

    #pragma unroll
    for (int dy = 0; dy < 5; dy++) {
        int hh = h + dy - 2;
        if ((unsigned)hh >= (unsigned)HIMG) continue;
        #pragma unroll
        for (int dx = 0; dx < 5; dx++) {
            int ww = w + dx - 2;
            if ((unsigned)ww >= (unsigned)WIMG) continue;
            acc += wf[dy*5 + dx] * xin[hh*WIMG + ww];
        }
    }
    g_conv[((size_t)b*DIMC + c)*NNN + n] = acc;
}

// ---------------- QKV projection via fp16 MMA (+ fused prev add + k-norm max) ----------------
__global__ __launch_bounds__(256) void qkv_mma(int head, int addprev)
{
    __shared__ __align__(16) __half wsh[96*72];   // [oc][c]
    __shared__ __align__(16) __half xsh[64*72];   // [pos][c], swizzled: c ^ (8*((pos>>4)&3))

    int b  = blockIdx.x / 25;
    int p0 = (blockIdx.x % 25) * 64;
    int t  = threadIdx.x;
    int wp   = t >> 5;
    int lane = t & 31;
    int g    = lane >> 2;
    int qd   = lane & 3;

    for (int i = t; i < 768; i += 256) {
        int row = i >> 3, c8 = (i & 7) * 8;
        cp16(&wsh[row*72 + c8], &g_qkv_wh[(size_t)head*96*64 + row*64 + c8]);
    }
    CP_COMMIT;

    // stage x transposed with XOR swizzle (conflict-free STS)
    {
        int c  = t >> 2;
        int i4 = t & 3;                 // pos block: 16*i4
        int cX = c ^ (i4 << 3);
        const float* cb = g_conv + ((size_t)b*DIMC + head*HDD + c)*NNN + p0 + i4*16;
        const float* pb = g_prev + ((size_t)b*HDD + c)*NNN + p0 + i4*16;
        #pragma unroll
        for (int j4 = 0; j4 < 4; j4++) {
            float4 f = *(const float4*)&cb[j4*4];
            if (addprev) {
                float4 pv = *(const float4*)&pb[j4*4];
                f.x += pv.x; f.y += pv.y; f.z += pv.z; f.w += pv.w;
            }
            int pbase = i4*16 + j4*4;
            xsh[(pbase + 0)*72 + cX] = __float2half_rn(f.x);
            xsh[(pbase + 1)*72 + cX] = __float2half_rn(f.y);
            xsh[(pbase + 2)*72 + cX] = __float2half_rn(f.z);
            xsh[(pbase + 3)*72 + cX] = __float2half_rn(f.w);
        }
    }
    CP_WAIT0;
    __syncthreads();

    int n0 = wp * 8;
    int cXor = ((wp >> 1) & 3) << 3;
    float acc[6][4];
    #pragma unroll
    for (int mt = 0; mt < 6; mt++)
        #pragma unroll
        for (int j = 0; j < 4; j++) acc[mt][j] = 0.f;

    #pragma unroll
    for (int ks = 0; ks < 4; ks++) {
        unsigned b0 = *(const unsigned*)&xsh[(n0 + g)*72 + ((ks*16 + 2*qd    ) ^ cXor)];
        unsigned b1 = *(const unsigned*)&xsh[(n0 + g)*72 + ((ks*16 + 2*qd + 8) ^ cXor)];
        #pragma unroll
        for (int mt = 0; mt < 6; mt++) {
            unsigned a[4];
            a[0] = *(const unsigned*)&wsh[(mt*16 + g    )*72 + ks*16 + 2*qd];
            a[1] = *(const unsigned*)&wsh[(mt*16 + g + 8)*72 + ks*16 + 2*qd];
            a[2] = *(const unsigned*)&wsh[(mt*16 + g    )*72 + ks*16 + 2*qd + 8];
            a[3] = *(const unsigned*)&wsh[(mt*16 + g + 8)*72 + ks*16 + 2*qd + 8];
            mma_f16(acc[mt], a, b0, b1);
        }
    }

    // epilogue + capture ||k||^2 partials
    float kn0 = 0.f, kn1 = 0.f;
    int n = p0 + n0 + 2*qd;
    #pragma unroll
    for (int mt = 0; mt < 6; mt++) {
        int oc0 = mt*16 + g, oc1 = oc0 + 8;
        float bb0 = g_qkv_bf[head*96 + oc0];
        float bb1 = g_qkv_bf[head*96 + oc1];
        float v00 = acc[mt][0] + bb0, v01 = acc[mt][1] + bb0;
        float v10 = acc[mt][2] + bb1, v11 = acc[mt][3] + bb1;
        if (mt == 0) {
            g_qh[((size_t)b*NNN + n    )*KDD + oc0] = __float2half_rn(v00);
            g_qh[((size_t)b*NNN + n + 1)*KDD + oc0] = __float2half_rn(v01);
            g_qh[((size_t)b*NNN + n    )*KDD + oc1] = __float2half_rn(v10);
            g_qh[((size_t)b*NNN + n + 1)*KDD + oc1] = __float2half_rn(v11);
        } else if (mt == 1) {
            int k0 = oc0 - 16, k1 = oc1 - 16;
            g_kh[((size_t)b*NNN + n    )*KDD + k0] = __float2half_rn(v00);
            g_kh[((size_t)b*NNN + n + 1)*KDD + k0] = __float2half_rn(v01);
            g_kh[((size_t)b*NNN + n    )*KDD + k1] = __float2half_rn(v10);
            g_kh[((size_t)b*NNN + n + 1)*KDD + k1] = __float2half_rn(v11);
            kn0 = v00*v00 + v10*v10;    // pos n
            kn1 = v01*v01 + v11*v11;    // pos n+1
        } else {
            int d0 = oc0 - 32, d1 = oc1 - 32;
            *(__half2*)&g_vT[((size_t)b*DDD + d0)*NNN + n] = __floats2half2_rn(v00, v01);
            *(__half2*)&g_vT[((size_t)b*DDD + d1)*NNN + n] = __floats2half2_rn(v10, v11);
        }
    }

    // reduce ||k||^2 over channels (g: lanes xor 4,8,16), then max over positions
    #pragma unroll
    for (int msk = 4; msk <= 16; msk <<= 1) {
        kn0 += __shfl_xor_sync(0xffffffffu, kn0, msk);
        kn1 += __shfl_xor_sync(0xffffffffu, kn1, msk);
    }
    float kmx = fmaxf(kn0, kn1);
    kmx = fmaxf(kmx, __shfl_xor_sync(0xffffffffu, kmx, 1));
    kmx = fmaxf(kmx, __shfl_xor_sync(0xffffffffu, kmx, 2));
    if (lane == 0)
        atomicMax(&g_kmaxu[head*BBB + b], __float_as_uint(kmx));
}

// ---------------- fp16 MMA flash attention, static-shift softmax ----------------
#define KSTRH 24
#define VSTRH 72

__global__ __launch_bounds__(128) void attn_mma(const float* __restrict__ attn_bias, int head)
{
    __shared__ __align__(16) __half ksm[2][64*KSTRH];
    __shared__ __align__(16) __half vsm[2][64*VSTRH];
    __shared__ __align__(16) float  bism[2][64];

    int b  = blockIdx.x / 25;
    int q0 = (blockIdx.x % 25) * 64;
    int t    = threadIdx.x;
    int w    = t >> 5;
    int lane = t & 31;
    int g    = lane >> 2;
    int qd   = lane & 3;
    int mi   = lane >> 3;
    int mr   = lane & 7;

    const __half* kbase = g_kh + (size_t)b*NNN*KDD;
    const __half* vbase = g_vT + (size_t)b*DDD*NNN;
    const float*  bbase = attn_bias + head*NNN;

    unsigned kofs = ((((mi>>1)*8 + mr)*KSTRH) + (mi & 1)*8) * 2;
    unsigned vofs = ((mr*VSTRH) + mi*8) * 2;
    unsigned kAddr[2], vAddr[2];
    kAddr[0] = (unsigned)__cvta_generic_to_shared(&ksm[0][0]) + kofs;
    kAddr[1] = (unsigned)__cvta_generic_to_shared(&ksm[1][0]) + kofs;
    vAddr[0] = (unsigned)__cvta_generic_to_shared(&vsm[0][0]) + vofs;
    vAddr[1] = (unsigned)__cvta_generic_to_shared(&vsm[1][0]) + vofs;

    // Q fragments (log2e pre-folded)
    unsigned aQ[4];
    {
        int r0 = q0 + w*16 + g, r1 = r0 + 8;
        const __half* qb = g_qh + (size_t)b*NNN*KDD;
        aQ[0] = *(const unsigned*)&qb[(size_t)r0*KDD + 2*qd];
        aQ[1] = *(const unsigned*)&qb[(size_t)r1*KDD + 2*qd];
        aQ[2] = *(const unsigned*)&qb[(size_t)r0*KDD + 2*qd + 8];
        aQ[3] = *(const unsigned*)&qb[(size_t)r1*KDD + 2*qd + 8];
    }

    // static shifts: m_r = ||q'_r|| * max||k|| + maxbias*log2e - 8
    float m0, m1;
    {
        float q2_0 = 0.f, q2_1 = 0.f;
        #pragma unroll
        for (int i = 0; i < 4; i++) {
            float2 f = __half22float2(*(__half2*)&aQ[i]);
            float ss = f.x*f.x + f.y*f.y;
            if (i & 1) q2_1 += ss; else q2_0 += ss;
        }
        q2_0 += __shfl_xor_sync(0xffffffffu, q2_0, 1);
        q2_0 += __shfl_xor_sync(0xffffffffu, q2_0, 2);
        q2_1 += __shfl_xor_sync(0xffffffffu, q2_1, 1);
        q2_1 += __shfl_xor_sync(0xffffffffu, q2_1, 2);
        float kmax2 = __uint_as_float(g_kmaxu[head*BBB + b]);
        float bmax  = g_bmax[head];
        m0 = sqrtf(q2_0 * kmax2) + bmax - 8.f;
        m1 = sqrtf(q2_1 * kmax2) + bmax - 8.f;
    }

    float Oa[8][4];
    #pragma unroll
    for (int nt = 0; nt < 8; nt++)
        #pragma unroll
        for (int j = 0; j < 4; j++) Oa[nt][j] = 0.f;
    float l0 = 0.f, l1 = 0.f;

    // prefetch tile 0
    {
        for (int i = t; i < 128; i += 128) {
            int key = i >> 1, c8 = (i & 1) * 8;
            cp16(&ksm[0][key*KSTRH + c8], &kbase[(size_t)key*KDD + c8]);
        }
        for (int i = t; i < 512; i += 128) {
            int d = i >> 3, ch = i & 7;
            cp16(&vsm[0][d*VSTRH + ch*8], &vbase[(size_t)d*NNN + ch*8]);
        }
        if (t < 16) cp16(&bism[0][t*4], &bbase[t*4]);
        CP_COMMIT;
    }

    for (int kt = 0; kt < 25; kt++) {
        int buf = kt & 1;
        if (kt + 1 < 25) {
            int k0 = (kt + 1) * 64, nb = buf ^ 1;
            for (int i = t; i < 128; i += 128) {
                int key = i >> 1, c8 = (i & 1) * 8;
                cp16(&ksm[nb][key*KSTRH + c8], &kbase[(size_t)(k0 + key)*KDD + c8]);
            }
            for (int i = t; i < 512; i += 128) {
                int d = i >> 3, ch = i & 7;
                cp16(&vsm[nb][d*VSTRH + ch*8], &vbase[(size_t)d*NNN + k0 + ch*8]);
            }
            if (t < 16) cp16(&bism[nb][t*4], &bbase[k0 + t*4]);
        }
        CP_COMMIT;
        CP_WAIT1;
        __syncthreads();

        // ---- S' = Q'K^T + bias*log2e - m  (bias & shift folded into accumulator init) ----
        float Sv[8][4];
        #pragma unroll
        for (int j = 0; j < 4; j++) {
            float2 bbA = *(const float2*)&bism[buf][(2*j  )*8 + 2*qd];
            float2 bbB = *(const float2*)&bism[buf][(2*j+1)*8 + 2*qd];
            Sv[2*j  ][0] = fmaf(bbA.x, L2E, -m0);
            Sv[2*j  ][1] = fmaf(bbA.y, L2E, -m0);
            Sv[2*j  ][2] = fmaf(bbA.x, L2E, -m1);
            Sv[2*j  ][3] = fmaf(bbA.y, L2E, -m1);
            Sv[2*j+1][0] = fmaf(bbB.x, L2E, -m0);
            Sv[2*j+1][1] = fmaf(bbB.y, L2E, -m0);
            Sv[2*j+1][2] = fmaf(bbB.x, L2E, -m1);
            Sv[2*j+1][3] = fmaf(bbB.y, L2E, -m1);
            unsigned r0, r1, r2, r3;
            ldsm4(r0, r1, r2, r3, kAddr[buf] + j*(16*KSTRH*2));
            mma_f16(Sv[2*j  ], aQ, r0, r1);
            mma_f16(Sv[2*j+1], aQ, r2, r3);
        }

        // ---- P = 2^S', accumulate partial row sums, pack to fp16 ----
        unsigned Ph[4][4];
        #pragma unroll
        for (int kc = 0; kc < 4; kc++) {
            float pA0 = ex2(Sv[2*kc  ][0]);
            float pA1 = ex2(Sv[2*kc  ][1]);
            float pA2 = ex2(Sv[2*kc  ][2]);
            float pA3 = ex2(Sv[2*kc  ][3]);
            float pB0 = ex2(Sv[2*kc+1][0]);
            float pB1 = ex2(Sv[2*kc+1][1]);
            float pB2 = ex2(Sv[2*kc+1][2]);
            float pB3 = ex2(Sv[2*kc+1][3]);
            l0 += pA0 + pA1 + pB0 + pB1;
            l1 += pA2 + pA3 + pB2 + pB3;
            Ph[kc][0] = packh2(pA0, pA1);
            Ph[kc][1] = packh2(pA2, pA3);
            Ph[kc][2] = packh2(pB0, pB1);
            Ph[kc][3] = packh2(pB2, pB3);
        }

        // ---- O += P V (independent across tiles — no rescale) ----
        #pragma unroll
        for (int nt = 0; nt < 8; nt++) {
            unsigned base = vAddr[buf] + nt*(8*VSTRH*2);
            unsigned c0, c1, c2, c3;
            ldsm4(c0, c1, c2, c3, base);
            mma_f16(Oa[nt], Ph[0], c0, c1);
            mma_f16(Oa[nt], Ph[1], c2, c3);
            ldsm4(c0, c1, c2, c3, base + 64);
            mma_f16(Oa[nt], Ph[2], c0, c1);
            mma_f16(Oa[nt], Ph[3], c2, c3);
        }
        __syncthreads();
    }

    // ---- final row-sum reduce + epilogue ----
    l0 += __shfl_xor_sync(0xffffffffu, l0, 1);
    l0 += __shfl_xor_sync(0xffffffffu, l0, 2);
    l1 += __shfl_xor_sync(0xffffffffu, l1, 1);
    l1 += __shfl_xor_sync(0xffffffffu, l1, 2);
    float inv0 = 1.f / l0, inv1 = 1.f / l1;
    int n0 = q0 + w*16 + g, n1 = n0 + 8;
    #pragma unroll
    for (int nt = 0; nt < 8; nt++) {
        int d = nt*8 + 2*qd;
        float o00 = Oa[nt][0] * inv0, o01 = Oa[nt][1] * inv0;
        float o10 = Oa[nt][2] * inv1, o11 = Oa[nt][3] * inv1;
        *(__half2*)&g_cath[((size_t)b*NNN + n0)*DIMC + head*DDD + d] = __floats2half2_rn(o00, o01);
        *(__half2*)&g_cath[((size_t)b*NNN + n1)*DIMC + head*DDD + d] = __floats2half2_rn(o10, o11);
        g_prev[((size_t)b*HDD + d    )*NNN + n0] = o00;
        g_prev[((size_t)b*HDD + d + 1)*NNN + n0] = o01;
        g_prev[((size_t)b*HDD + d    )*NNN + n1] = o10;
        g_prev[((size_t)b*HDD + d + 1)*NNN + n1] = o11;
    }
}

// ---------------- final proj: fp16 MMA ----------------
#define PSTRH 24

__global__ __launch_bounds__(256) void proj_mma(float* __restrict__ out)
{
    __shared__ __align__(16) __half xsm[2][160*PSTRH];
    __shared__ __align__(16) __half wsm[2][64*PSTRH];

    int bi = blockIdx.x;
    int b  = bi / 40;
    int r  = bi % 40;
    int p0 = (r / 4) * 160;
    int o0 = (r % 4) * 64;

    int t    = threadIdx.x;
    int wid  = t >> 5;
    int lane = t & 31;
    int g    = lane >> 2;
    int qd   = lane & 3;
    int wo   = wid & 3;
    int wp   = wid >> 2;

    const __half* xb = g_cath + (size_t)b*NNN*DIMC;

    float Oa[10][4];
    #pragma unroll
    for (int nt = 0; nt < 10; nt++)
        #pragma unroll
        for (int j = 0; j < 4; j++) Oa[nt][j] = 0.f;

    {
        for (int i = t; i < 128; i += 256) {
            int row = i >> 1, c8 = (i & 1) * 8;
            cp16(&wsm[0][row*PSTRH + c8], &g_p_wh[(o0 + row)*DIMC + c8]);
        }
        for (int i = t; i < 320; i += 256) {
            int row = i >> 1, c8 = (i & 1) * 8;
            cp16(&xsm[0][row*PSTRH + c8], &xb[(size_t)(p0 + row)*DIMC + c8]);
        }
        CP_COMMIT;
    }

    for (int s = 0; s < 16; s++) {
        int buf = s & 1;
        if (s + 1 < 16) {
            int c0 = (s + 1) * 16, nb = buf ^ 1;
            for (int i = t; i < 128; i += 256) {
                int row = i >> 1, c8 = (i & 1) * 8;
                cp16(&wsm[nb][row*PSTRH + c8], &g_p_wh[(o0 + row)*DIMC + c0 + c8]);
            }
            for (int i = t; i < 320; i += 256) {
                int row = i >> 1, c8 = (i & 1) * 8;
                cp16(&xsm[nb][row*PSTRH + c8], &xb[(size_t)(p0 + row)*DIMC + c0 + c8]);
            }
        }
        CP_COMMIT;
        CP_WAIT1;
        __syncthreads();

        unsigned a[4];
        a[0] = *(const unsigned*)&wsm[buf][(wo*16 + g    )*PSTRH + 2*qd];
        a[1] = *(const unsigned*)&wsm[buf][(wo*16 + g + 8)*PSTRH + 2*qd];
        a[2] = *(const unsigned*)&wsm[buf][(wo*16 + g    )*PSTRH + 2*qd + 8];
        a[3] = *(const unsigned*)&wsm[buf][(wo*16 + g + 8)*PSTRH + 2*qd + 8];
        #pragma unroll
        for (int nt = 0; nt < 10; nt++) {
            unsigned b0 = *(const unsigned*)&xsm[buf][(wp*80 + nt*8 + g)*PSTRH + 2*qd];
            unsigned b1 = *(const unsigned*)&xsm[buf][(wp*80 + nt*8 + g)*PSTRH + 2*qd + 8];
            mma_f16(Oa[nt], a, b0, b1);
        }
        __syncthreads();
    }

    int orow0 = o0 + wo*16 + g, orow1 = orow0 + 8;
    float bb0 = g_p_bf[orow0], bb1 = g_p_bf[orow1];
    #pragma unroll
    for (int nt = 0; nt < 10; nt++) {
        int n = p0 + wp*80 + nt*8 + 2*qd;
        float v00 = fmaxf(Oa[nt][0] + bb0, 0.f);
        float v01 = fmaxf(Oa[nt][1] + bb0, 0.f);
        float v10 = fmaxf(Oa[nt][2] + bb1, 0.f);
        float v11 = fmaxf(Oa[nt][3] + bb1, 0.f);
        *(float2*)&out[((size_t)b*DIMC + orow0)*NNN + n] = make_float2(v00, v01);
        *(float2*)&out[((size_t)b*DIMC + orow1)*NNN + n] = make_float2(v10, v11);
    }
}

// ---------------- launch ----------------
extern "C" void kernel_launch(void* const* d_in, const int* in_sizes, int n_in,
                              void* d_out, int out_size)
{
    const float* x    = (const float*)d_in[0];
    const float* dw_w = (const float*)d_in[1];
    const float* dw_g = (const float*)d_in[2];
    const float* dw_b = (const float*)d_in[3];
    const float* dw_m = (const float*)d_in[4];
    const float* dw_v = (const float*)d_in[5];
    const float* q_w  = (const float*)d_in[6];
    const float* q_g  = (const float*)d_in[7];
    const float* q_b  = (const float*)d_in[8];
    const float* q_m  = (const float*)d_in[9];
    const float* q_v  = (const float*)d_in[10];
    const float* k_w  = (const float*)d_in[11];
    const float* k_g  = (const float*)d_in[12];
    const float* k_b  = (const float*)d_in[13];
    const float* k_m  = (const float*)d_in[14];
    const float* k_v  = (const float*)d_in[15];
    const float* v_w  = (const float*)d_in[16];
    const float* v_g  = (const float*)d_in[17];
    const float* v_b  = (const float*)d_in[18];
    const float* v_m  = (const float*)d_in[19];
    const float* v_v  = (const float*)d_in[20];
    const float* p_w  = (const float*)d_in[21];
    const float* p_g  = (const float*)d_in[22];
    const float* p_b  = (const float*)d_in[23];
    const float* p_m  = (const float*)d_in[24];
    const float* p_v  = (const float*)d_in[25];
    const float* attn_bias = (const float*)d_in[26];

    prep_fold<<<128, 256>>>(dw_w, dw_g, dw_b, dw_m, dw_v,
                            q_w, q_g, q_b, q_m, q_v,
                            k_w, k_g, k_b, k_m, k_v,
                            v_w, v_g, v_b, v_m, v_v,
                            p_w, p_g, p_b, p_m, p_v, attn_bias);

    dwconv_all<<<(BBB*DIMC*NNN)/256, 256>>>(x);

    for (int i = 0; i < NHH; i++) {
        qkv_mma<<<BBB*25, 256>>>(i, i > 0 ? 1 : 0);
        attn_mma<<<BBB*25, 128>>>(attn_bias, i);
    }

    proj_mma<<<640, 256>>>((float*)d_out);
}

// round 8
// speedup vs baseline: 6.6035x; 1.1089x over previous
#include <cuda_runtime.h>
#include <cuda_fp16.h>
#include <math.h>

#define NHH   4
#define HDD   64
#define KDD   16
#define DDD   64
#define NNN   1600
#define BBB   16
#define HIMG  40
#define WIMG  40
#define DIMC  256
#define EPSB  1e-5f
#define SCALEQ 0.25f
#define L2E   1.4426950408889634f

// ---------------- device scratch ----------------
__device__ float    g_conv[BBB*DIMC*NNN];
__device__ __half   g_qh [BBB*NNN*KDD];
__device__ __half   g_kh [BBB*NNN*KDD];
__device__ __half   g_vT [BBB*DDD*NNN];
__device__ float    g_prev[BBB*HDD*NNN];
__device__ __half   g_cath[BBB*NNN*DIMC];
__device__ float    g_dw_wf[NHH*HDD*25];
__device__ float    g_dw_bf[NHH*HDD];
__device__ __half   g_qkv_wh[NHH*96*HDD];
__device__ float    g_qkv_bf[NHH*96];
__device__ __half   g_p_wh[DIMC*DIMC];
__device__ float    g_p_bf[DIMC];
__device__ unsigned g_kmaxu[NHH*BBB];
__device__ float    g_bmax[NHH];

// ---------------- helpers ----------------
__device__ __forceinline__ float ex2(float x) {
    float r; asm("ex2.approx.f32 %0, %1;" : "=f"(r) : "f"(x)); return r;
}
__device__ __forceinline__ unsigned packh2(float a, float b) {
    __half2 h = __floats2half2_rn(a, b);
    return *(unsigned*)&h;
}
__device__ __forceinline__ void mma_f16(float c[4], const unsigned a[4],
                                        unsigned b0, unsigned b1) {
    asm volatile("mma.sync.aligned.m16n8k16.row.col.f32.f16.f16.f32 "
        "{%0,%1,%2,%3}, {%4,%5,%6,%7}, {%8,%9}, {%0,%1,%2,%3};"
        : "+f"(c[0]), "+f"(c[1]), "+f"(c[2]), "+f"(c[3])
        : "r"(a[0]), "r"(a[1]), "r"(a[2]), "r"(a[3]), "r"(b0), "r"(b1));
}
__device__ __forceinline__ void ldsm4(unsigned& r0, unsigned& r1, unsigned& r2, unsigned& r3,
                                      unsigned addr) {
    asm volatile("ldmatrix.sync.aligned.m8n8.x4.shared.b16 {%0,%1,%2,%3}, [%4];"
        : "=r"(r0), "=r"(r1), "=r"(r2), "=r"(r3) : "r"(addr));
}
__device__ __forceinline__ void cp16(void* dst, const void* src) {
    unsigned d = (unsigned)__cvta_generic_to_shared(dst);
    asm volatile("cp.async.cg.shared.global [%0], [%1], 16;" :: "r"(d), "l"(src));
}
#define CP_COMMIT asm volatile("cp.async.commit_group;" ::: "memory")
#define CP_WAIT1  asm volatile("cp.async.wait_group 1;"  ::: "memory")
#define CP_WAIT0  asm volatile("cp.async.wait_group 0;"  ::: "memory")

// ---------------- fold BN into weights + bias-max + kmax reset ----------------
__global__ void prep_fold(
    const float* dw_w, const float* dw_g, const float* dw_b, const float* dw_m, const float* dw_v,
    const float* q_w,  const float* q_g,  const float* q_b,  const float* q_m,  const float* q_v,
    const float* k_w,  const float* k_g,  const float* k_b,  const float* k_m,  const float* k_v,
    const float* v_w,  const float* v_g,  const float* v_b,  const float* v_m,  const float* v_v,
    const float* p_w,  const float* p_g,  const float* p_b,  const float* p_m,  const float* p_v,
    const float* attn_bias)
{
    int t = blockIdx.x * blockDim.x + threadIdx.x;
    int stride = gridDim.x * blockDim.x;

    for (int idx = t; idx < NHH*HDD*25; idx += stride) {
        int ch = idx / 25;
        float s = dw_g[ch] * rsqrtf(dw_v[ch] + EPSB);
        g_dw_wf[idx] = dw_w[idx] * s;
    }
    for (int ch = t; ch < NHH*HDD; ch += stride) {
        float s = dw_g[ch] * rsqrtf(dw_v[ch] + EPSB);
        g_dw_bf[ch] = dw_b[ch] - s * dw_m[ch];
    }
    for (int idx = t; idx < NHH*96*HDD; idx += stride) {
        int r = idx / HDD, c = idx % HDD;
        int i = r / 96, oc = r % 96;
        float s; const float* w;
        if (oc < 16) {
            int j = i*KDD + oc;
            s = q_g[j] * rsqrtf(q_v[j] + EPSB) * (SCALEQ * L2E);
            w = q_w + (size_t)j * HDD;
        } else if (oc < 32) {
            int j = i*KDD + (oc - 16);
            s = k_g[j] * rsqrtf(k_v[j] + EPSB);
            w = k_w + (size_t)j * HDD;
        } else {
            int j = i*DDD + (oc - 32);
            s = v_g[j] * rsqrtf(v_v[j] + EPSB);
            w = v_w + (size_t)j * HDD;
        }
        g_qkv_wh[idx] = __float2half_rn(w[c] * s);
    }
    for (int r = t; r < NHH*96; r += stride) {
        int i = r / 96, oc = r % 96;
        float s, bias;
        if (oc < 16) {
            int j = i*KDD + oc;
            s = q_g[j] * rsqrtf(q_v[j] + EPSB);
            bias = (q_b[j] - s * q_m[j]) * (SCALEQ * L2E);
        } else if (oc < 32) {
            int j = i*KDD + (oc - 16);
            s = k_g[j] * rsqrtf(k_v[j] + EPSB);
            bias = k_b[j] - s * k_m[j];
        } else {
            int j = i*DDD + (oc - 32);
            s = v_g[j] * rsqrtf(v_v[j] + EPSB);
            bias = v_b[j] - s * v_m[j];
        }
        g_qkv_bf[r] = bias;
    }
    for (int idx = t; idx < DIMC*DIMC; idx += stride) {
        int o = idx / DIMC;
        float s = p_g[o] * rsqrtf(p_v[o] + EPSB);
        g_p_wh[idx] = __float2half_rn(p_w[idx] * s);
    }
    for (int o = t; o < DIMC; o += stride) {
        float s = p_g[o] * rsqrtf(p_v[o] + EPSB);
        g_p_bf[o] = p_b[o] - s * p_m[o];
    }

    if (blockIdx.x == 0) {
        int tt = threadIdx.x;
        if (tt < NHH*BBB) g_kmaxu[tt] = 0u;
        int wrp = tt >> 5, ln = tt & 31;
        if (wrp < NHH) {
            float mx = -1e30f;
            for (int n = ln; n < NNN; n += 32)
                mx = fmaxf(mx, attn_bias[wrp*NNN + n]);
            #pragma unroll
            for (int msk = 16; msk; msk >>= 1)
                mx = fmaxf(mx, __shfl_xor_sync(0xffffffffu, mx, msk));
            if (ln == 0) g_bmax[wrp] = mx * L2E;
        }
    }
}

// ---------------- depthwise 5x5 conv, 4 outputs/thread (sliding window) ----------------
__global__ __launch_bounds__(256) void dwconv_all(const float* __restrict__ x)
{
    int idx = blockIdx.x * 256 + threadIdx.x;     // BBB*DIMC*400 threads
    int n4 = idx % 400;
    int c  = (idx / 400) % DIMC;
    int b  = idx / (400 * DIMC);
    int h  = n4 / 10, w0 = (n4 % 10) * 4;

    const float* xin = x + ((size_t)b * DIMC + c) * NNN;
    const float* wf  = g_dw_wf + c * 25;
    float bias = g_dw_bf[c];
    float a0 = bias, a1 = bias, a2 = bias, a3 = bias;

    #pragma unroll
    for (int dy = 0; dy < 5; dy++) {
        int hh = h + dy - 2;
        if ((unsigned)hh >= (unsigned)HIMG) continue;
        const float* row = xin + hh*WIMG;
        float v[8];
        #pragma unroll
        for (int j = 0; j < 8; j++) {
            int ww = w0 - 2 + j;
            v[j] = ((unsigned)ww < (unsigned)WIMG) ? row[ww] : 0.f;
        }
        #pragma unroll
        for (int dx = 0; dx < 5; dx++) {
            float wt = wf[dy*5 + dx];
            a0 += wt*v[dx];   a1 += wt*v[dx+1];
            a2 += wt*v[dx+2]; a3 += wt*v[dx+3];
        }
    }
    *(float4*)&g_conv[((size_t)b*DIMC + c)*NNN + h*WIMG + w0] = make_float4(a0, a1, a2, a3);
}

// ---------------- QKV projection via fp16 MMA (+ fused prev add + k-norm max) ----------------
__global__ __launch_bounds__(256) void qkv_mma(int head, int addprev)
{
    __shared__ __align__(16) __half wsh[96*72];
    __shared__ __align__(16) __half xsh[64*72];

    int b  = blockIdx.x / 25;
    int p0 = (blockIdx.x % 25) * 64;
    int t  = threadIdx.x;
    int wp   = t >> 5;
    int lane = t & 31;
    int g    = lane >> 2;
    int qd   = lane & 3;

    for (int i = t; i < 768; i += 256) {
        int row = i >> 3, c8 = (i & 7) * 8;
        cp16(&wsh[row*72 + c8], &g_qkv_wh[(size_t)head*96*64 + row*64 + c8]);
    }
    CP_COMMIT;

    {
        int c  = t >> 2;
        int i4 = t & 3;
        int cX = c ^ (i4 << 3);
        const float* cb = g_conv + ((size_t)b*DIMC + head*HDD + c)*NNN + p0 + i4*16;
        const float* pb = g_prev + ((size_t)b*HDD + c)*NNN + p0 + i4*16;
        #pragma unroll
        for (int j4 = 0; j4 < 4; j4++) {
            float4 f = *(const float4*)&cb[j4*4];
            if (addprev) {
                float4 pv = *(const float4*)&pb[j4*4];
                f.x += pv.x; f.y += pv.y; f.z += pv.z; f.w += pv.w;
            }
            int pbase = i4*16 + j4*4;
            xsh[(pbase + 0)*72 + cX] = __float2half_rn(f.x);
            xsh[(pbase + 1)*72 + cX] = __float2half_rn(f.y);
            xsh[(pbase + 2)*72 + cX] = __float2half_rn(f.z);
            xsh[(pbase + 3)*72 + cX] = __float2half_rn(f.w);
        }
    }
    CP_WAIT0;
    __syncthreads();

    int n0 = wp * 8;
    int cXor = ((wp >> 1) & 3) << 3;
    float acc[6][4];
    #pragma unroll
    for (int mt = 0; mt < 6; mt++)
        #pragma unroll
        for (int j = 0; j < 4; j++) acc[mt][j] = 0.f;

    #pragma unroll
    for (int ks = 0; ks < 4; ks++) {
        unsigned b0 = *(const unsigned*)&xsh[(n0 + g)*72 + ((ks*16 + 2*qd    ) ^ cXor)];
        unsigned b1 = *(const unsigned*)&xsh[(n0 + g)*72 + ((ks*16 + 2*qd + 8) ^ cXor)];
        #pragma unroll
        for (int mt = 0; mt < 6; mt++) {
            unsigned a[4];
            a[0] = *(const unsigned*)&wsh[(mt*16 + g    )*72 + ks*16 + 2*qd];
            a[1] = *(const unsigned*)&wsh[(mt*16 + g + 8)*72 + ks*16 + 2*qd];
            a[2] = *(const unsigned*)&wsh[(mt*16 + g    )*72 + ks*16 + 2*qd + 8];
            a[3] = *(const unsigned*)&wsh[(mt*16 + g + 8)*72 + ks*16 + 2*qd + 8];
            mma_f16(acc[mt], a, b0, b1);
        }
    }

    float kn0 = 0.f, kn1 = 0.f;
    int n = p0 + n0 + 2*qd;
    #pragma unroll
    for (int mt = 0; mt < 6; mt++) {
        int oc0 = mt*16 + g, oc1 = oc0 + 8;
        float bb0 = g_qkv_bf[head*96 + oc0];
        float bb1 = g_qkv_bf[head*96 + oc1];
        float v00 = acc[mt][0] + bb0, v01 = acc[mt][1] + bb0;
        float v10 = acc[mt][2] + bb1, v11 = acc[mt][3] + bb1;
        if (mt == 0) {
            g_qh[((size_t)b*NNN + n    )*KDD + oc0] = __float2half_rn(v00);
            g_qh[((size_t)b*NNN + n + 1)*KDD + oc0] = __float2half_rn(v01);
            g_qh[((size_t)b*NNN + n    )*KDD + oc1] = __float2half_rn(v10);
            g_qh[((size_t)b*NNN + n + 1)*KDD + oc1] = __float2half_rn(v11);
        } else if (mt == 1) {
            int k0 = oc0 - 16, k1 = oc1 - 16;
            g_kh[((size_t)b*NNN + n    )*KDD + k0] = __float2half_rn(v00);
            g_kh[((size_t)b*NNN + n + 1)*KDD + k0] = __float2half_rn(v01);
            g_kh[((size_t)b*NNN + n    )*KDD + k1] = __float2half_rn(v10);
            g_kh[((size_t)b*NNN + n + 1)*KDD + k1] = __float2half_rn(v11);
            kn0 = v00*v00 + v10*v10;
            kn1 = v01*v01 + v11*v11;
        } else {
            int d0 = oc0 - 32, d1 = oc1 - 32;
            *(__half2*)&g_vT[((size_t)b*DDD + d0)*NNN + n] = __floats2half2_rn(v00, v01);
            *(__half2*)&g_vT[((size_t)b*DDD + d1)*NNN + n] = __floats2half2_rn(v10, v11);
        }
    }

    #pragma unroll
    for (int msk = 4; msk <= 16; msk <<= 1) {
        kn0 += __shfl_xor_sync(0xffffffffu, kn0, msk);
        kn1 += __shfl_xor_sync(0xffffffffu, kn1, msk);
    }
    float kmx = fmaxf(kn0, kn1);
    kmx = fmaxf(kmx, __shfl_xor_sync(0xffffffffu, kmx, 1));
    kmx = fmaxf(kmx, __shfl_xor_sync(0xffffffffu, kmx, 2));
    if (lane == 0)
        atomicMax(&g_kmaxu[head*BBB + b], __float_as_uint(kmx));
}

// ---------------- fp16 MMA flash attention: 8 warps, key-split pairs ----------------
#define KSTRH 24
#define VSTRH 72

__global__ __launch_bounds__(256) void attn_mma(const float* __restrict__ attn_bias, int head)
{
    __shared__ __align__(16) __half ksm[2][64*KSTRH];
    __shared__ __align__(16) __half vsm[2][64*VSTRH];   // also reused as combine buffer
    __shared__ __align__(16) float  bism[2][64];

    int b  = blockIdx.x / 25;
    int q0 = (blockIdx.x % 25) * 64;
    int t    = threadIdx.x;
    int w    = t >> 5;
    int wq   = w & 3;        // query group (rows wq*16..wq*16+15)
    int kh   = w >> 2;       // key half (0: keys 0-31, 1: keys 32-63)
    int lane = t & 31;
    int g    = lane >> 2;
    int qd   = lane & 3;
    int mi   = lane >> 3;
    int mr   = lane & 7;

    const __half* kbase = g_kh + (size_t)b*NNN*KDD;
    const __half* vbase = g_vT + (size_t)b*DDD*NNN;
    const float*  bbase = attn_bias + head*NNN;

    unsigned kofs = ((((mi>>1)*8 + mr)*KSTRH) + (mi & 1)*8) * 2;
    unsigned vofs = ((mr*VSTRH) + mi*8) * 2;
    unsigned kAddr[2], vAddr[2];
    kAddr[0] = (unsigned)__cvta_generic_to_shared(&ksm[0][0]) + kofs;
    kAddr[1] = (unsigned)__cvta_generic_to_shared(&ksm[1][0]) + kofs;
    vAddr[0] = (unsigned)__cvta_generic_to_shared(&vsm[0][0]) + vofs + kh*64;
    vAddr[1] = (unsigned)__cvta_generic_to_shared(&vsm[1][0]) + vofs + kh*64;

    // Q fragments (log2e pre-folded)
    unsigned aQ[4];
    {
        int r0 = q0 + wq*16 + g, r1 = r0 + 8;
        const __half* qb = g_qh + (size_t)b*NNN*KDD;
        aQ[0] = *(const unsigned*)&qb[(size_t)r0*KDD + 2*qd];
        aQ[1] = *(const unsigned*)&qb[(size_t)r1*KDD + 2*qd];
        aQ[2] = *(const unsigned*)&qb[(size_t)r0*KDD + 2*qd + 8];
        aQ[3] = *(const unsigned*)&qb[(size_t)r1*KDD + 2*qd + 8];
    }

    // static shifts
    float m0, m1;
    {
        float q2_0 = 0.f, q2_1 = 0.f;
        #pragma unroll
        for (int i = 0; i < 4; i++) {
            float2 f = __half22float2(*(__half2*)&aQ[i]);
            float ss = f.x*f.x + f.y*f.y;
            if (i & 1) q2_1 += ss; else q2_0 += ss;
        }
        q2_0 += __shfl_xor_sync(0xffffffffu, q2_0, 1);
        q2_0 += __shfl_xor_sync(0xffffffffu, q2_0, 2);
        q2_1 += __shfl_xor_sync(0xffffffffu, q2_1, 1);
        q2_1 += __shfl_xor_sync(0xffffffffu, q2_1, 2);
        float kmax2 = __uint_as_float(g_kmaxu[head*BBB + b]);
        float bmax  = g_bmax[head];
        m0 = sqrtf(q2_0 * kmax2) + bmax - 8.f;
        m1 = sqrtf(q2_1 * kmax2) + bmax - 8.f;
    }

    float Oa[8][4];
    #pragma unroll
    for (int nt = 0; nt < 8; nt++)
        #pragma unroll
        for (int j = 0; j < 4; j++) Oa[nt][j] = 0.f;
    float l0 = 0.f, l1 = 0.f;

    // prefetch tile 0
    {
        for (int i = t; i < 128; i += 256) {
            int key = i >> 1, c8 = (i & 1) * 8;
            cp16(&ksm[0][key*KSTRH + c8], &kbase[(size_t)key*KDD + c8]);
        }
        for (int i = t; i < 512; i += 256) {
            int d = i >> 3, ch = i & 7;
            cp16(&vsm[0][d*VSTRH + ch*8], &vbase[(size_t)d*NNN + ch*8]);
        }
        if (t < 16) cp16(&bism[0][t*4], &bbase[t*4]);
        CP_COMMIT;
    }

    for (int kt = 0; kt < 25; kt++) {
        int buf = kt & 1;
        if (kt + 1 < 25) {
            int k0 = (kt + 1) * 64, nb = buf ^ 1;
            for (int i = t; i < 128; i += 256) {
                int key = i >> 1, c8 = (i & 1) * 8;
                cp16(&ksm[nb][key*KSTRH + c8], &kbase[(size_t)(k0 + key)*KDD + c8]);
            }
            for (int i = t; i < 512; i += 256) {
                int d = i >> 3, ch = i & 7;
                cp16(&vsm[nb][d*VSTRH + ch*8], &vbase[(size_t)d*NNN + k0 + ch*8]);
            }
            if (t < 16) cp16(&bism[nb][t*4], &bbase[k0 + t*4]);
        }
        CP_COMMIT;
        CP_WAIT1;
        __syncthreads();

        // ---- S' for this warp's 32 keys (2 ldsm4 chunks) ----
        float Sv[4][4];
        #pragma unroll
        for (int jj = 0; jj < 2; jj++) {
            float2 bbA = *(const float2*)&bism[buf][kh*32 + jj*16     + 2*qd];
            float2 bbB = *(const float2*)&bism[buf][kh*32 + jj*16 + 8 + 2*qd];
            Sv[2*jj  ][0] = fmaf(bbA.x, L2E, -m0);
            Sv[2*jj  ][1] = fmaf(bbA.y, L2E, -m0);
            Sv[2*jj  ][2] = fmaf(bbA.x, L2E, -m1);
            Sv[2*jj  ][3] = fmaf(bbA.y, L2E, -m1);
            Sv[2*jj+1][0] = fmaf(bbB.x, L2E, -m0);
            Sv[2*jj+1][1] = fmaf(bbB.y, L2E, -m0);
            Sv[2*jj+1][2] = fmaf(bbB.x, L2E, -m1);
            Sv[2*jj+1][3] = fmaf(bbB.y, L2E, -m1);
            unsigned r0, r1, r2, r3;
            ldsm4(r0, r1, r2, r3, kAddr[buf] + (kh*2 + jj)*(16*KSTRH*2));
            mma_f16(Sv[2*jj  ], aQ, r0, r1);
            mma_f16(Sv[2*jj+1], aQ, r2, r3);
        }

        // ---- P = 2^S', partial row sums, pack ----
        unsigned Ph[2][4];
        #pragma unroll
        for (int kc = 0; kc < 2; kc++) {
            float pA0 = ex2(Sv[2*kc  ][0]);
            float pA1 = ex2(Sv[2*kc  ][1]);
            float pA2 = ex2(Sv[2*kc  ][2]);
            float pA3 = ex2(Sv[2*kc  ][3]);
            float pB0 = ex2(Sv[2*kc+1][0]);
            float pB1 = ex2(Sv[2*kc+1][1]);
            float pB2 = ex2(Sv[2*kc+1][2]);
            float pB3 = ex2(Sv[2*kc+1][3]);
            l0 += pA0 + pA1 + pB0 + pB1;
            l1 += pA2 + pA3 + pB2 + pB3;
            Ph[kc][0] = packh2(pA0, pA1);
            Ph[kc][1] = packh2(pA2, pA3);
            Ph[kc][2] = packh2(pB0, pB1);
            Ph[kc][3] = packh2(pB2, pB3);
        }

        // ---- O += P V over this warp's 32 keys ----
        #pragma unroll
        for (int nt = 0; nt < 8; nt++) {
            unsigned c0, c1, c2, c3;
            ldsm4(c0, c1, c2, c3, vAddr[buf] + nt*(8*VSTRH*2));
            mma_f16(Oa[nt], Ph[0], c0, c1);
            mma_f16(Oa[nt], Ph[1], c2, c3);
        }
        __syncthreads();
    }

    // ---- cross-half combine via smem (reuse vsm region) ----
    float* cbuf = (float*)&vsm[0][0];     // 18432B available, need 17408B
    if (kh == 1) {
        int base = (wq*32 + lane) * 34;
        #pragma unroll
        for (int nt = 0; nt < 8; nt++) {
            cbuf[base + nt*4 + 0] = Oa[nt][0];
            cbuf[base + nt*4 + 1] = Oa[nt][1];
            cbuf[base + nt*4 + 2] = Oa[nt][2];
            cbuf[base + nt*4 + 3] = Oa[nt][3];
        }
        cbuf[base + 32] = l0;
        cbuf[base + 33] = l1;
    }
    __syncthreads();
    if (kh == 0) {
        int base = (wq*32 + lane) * 34;
        #pragma unroll
        for (int nt = 0; nt < 8; nt++) {
            Oa[nt][0] += cbuf[base + nt*4 + 0];
            Oa[nt][1] += cbuf[base + nt*4 + 1];
            Oa[nt][2] += cbuf[base + nt*4 + 2];
            Oa[nt][3] += cbuf[base + nt*4 + 3];
        }
        l0 += cbuf[base + 32];
        l1 += cbuf[base + 33];

        l0 += __shfl_xor_sync(0xffffffffu, l0, 1);
        l0 += __shfl_xor_sync(0xffffffffu, l0, 2);
        l1 += __shfl_xor_sync(0xffffffffu, l1, 1);
        l1 += __shfl_xor_sync(0xffffffffu, l1, 2);
        float inv0 = 1.f / l0, inv1 = 1.f / l1;
        int n0 = q0 + wq*16 + g, n1 = n0 + 8;
        #pragma unroll
        for (int nt = 0; nt < 8; nt++) {
            int d = nt*8 + 2*qd;
            float o00 = Oa[nt][0] * inv0, o01 = Oa[nt][1] * inv0;
            float o10 = Oa[nt][2] * inv1, o11 = Oa[nt][3] * inv1;
            *(__half2*)&g_cath[((size_t)b*NNN + n0)*DIMC + head*DDD + d] = __floats2half2_rn(o00, o01);
            *(__half2*)&g_cath[((size_t)b*NNN + n1)*DIMC + head*DDD + d] = __floats2half2_rn(o10, o11);
            g_prev[((size_t)b*HDD + d    )*NNN + n0] = o00;
            g_prev[((size_t)b*HDD + d + 1)*NNN + n0] = o01;
            g_prev[((size_t)b*HDD + d    )*NNN + n1] = o10;
            g_prev[((size_t)b*HDD + d + 1)*NNN + n1] = o11;
        }
    }
}

// ---------------- final proj: fp16 MMA ----------------
#define PSTRH 24

__global__ __launch_bounds__(256) void proj_mma(float* __restrict__ out)
{
    __shared__ __align__(16) __half xsm[2][160*PSTRH];
    __shared__ __align__(16) __half wsm[2][64*PSTRH];

    int bi = blockIdx.x;
    int b  = bi / 40;
    int r  = bi % 40;
    int p0 = (r / 4) * 160;
    int o0 = (r % 4) * 64;

    int t    = threadIdx.x;
    int wid  = t >> 5;
    int lane = t & 31;
    int g    = lane >> 2;
    int qd   = lane & 3;
    int wo   = wid & 3;
    int wp   = wid >> 2;

    const __half* xb = g_cath + (size_t)b*NNN*DIMC;

    float Oa[10][4];
    #pragma unroll
    for (int nt = 0; nt < 10; nt++)
        #pragma unroll
        for (int j = 0; j < 4; j++) Oa[nt][j] = 0.f;

    {
        for (int i = t; i < 128; i += 256) {
            int row = i >> 1, c8 = (i & 1) * 8;
            cp16(&wsm[0][row*PSTRH + c8], &g_p_wh[(o0 + row)*DIMC + c8]);
        }
        for (int i = t; i < 320; i += 256) {
            int row = i >> 1, c8 = (i & 1) * 8;
            cp16(&xsm[0][row*PSTRH + c8], &xb[(size_t)(p0 + row)*DIMC + c8]);
        }
        CP_COMMIT;
    }

    for (int s = 0; s < 16; s++) {
        int buf = s & 1;
        if (s + 1 < 16) {
            int c0 = (s + 1) * 16, nb = buf ^ 1;
            for (int i = t; i < 128; i += 256) {
                int row = i >> 1, c8 = (i & 1) * 8;
                cp16(&wsm[nb][row*PSTRH + c8], &g_p_wh[(o0 + row)*DIMC + c0 + c8]);
            }
            for (int i = t; i < 320; i += 256) {
                int row = i >> 1, c8 = (i & 1) * 8;
                cp16(&xsm[nb][row*PSTRH + c8], &xb[(size_t)(p0 + row)*DIMC + c0 + c8]);
            }
        }
        CP_COMMIT;
        CP_WAIT1;
        __syncthreads();

        unsigned a[4];
        a[0] = *(const unsigned*)&wsm[buf][(wo*16 + g    )*PSTRH + 2*qd];
        a[1] = *(const unsigned*)&wsm[buf][(wo*16 + g + 8)*PSTRH + 2*qd];
        a[2] = *(const unsigned*)&wsm[buf][(wo*16 + g    )*PSTRH + 2*qd + 8];
        a[3] = *(const unsigned*)&wsm[buf][(wo*16 + g + 8)*PSTRH + 2*qd + 8];
        #pragma unroll
        for (int nt = 0; nt < 10; nt++) {
            unsigned b0 = *(const unsigned*)&xsm[buf][(wp*80 + nt*8 + g)*PSTRH + 2*qd];
            unsigned b1 = *(const unsigned*)&xsm[buf][(wp*80 + nt*8 + g)*PSTRH + 2*qd + 8];
            mma_f16(Oa[nt], a, b0, b1);
        }
        __syncthreads();
    }

    int orow0 = o0 + wo*16 + g, orow1 = orow0 + 8;
    float bb0 = g_p_bf[orow0], bb1 = g_p_bf[orow1];
    #pragma unroll
    for (int nt = 0; nt < 10; nt++) {
        int n = p0 + wp*80 + nt*8 + 2*qd;
        float v00 = fmaxf(Oa[nt][0] + bb0, 0.f);
        float v01 = fmaxf(Oa[nt][1] + bb0, 0.f);
        float v10 = fmaxf(Oa[nt][2] + bb1, 0.f);
        float v11 = fmaxf(Oa[nt][3] + bb1, 0.f);
        *(float2*)&out[((size_t)b*DIMC + orow0)*NNN + n] = make_float2(v00, v01);
        *(float2*)&out[((size_t)b*DIMC + orow1)*NNN + n] = make_float2(v10, v11);
    }
}

// ---------------- launch ----------------
extern "C" void kernel_launch(void* const* d_in, const int* in_sizes, int n_in,
                              void* d_out, int out_size)
{
    const float* x    = (const float*)d_in[0];
    const float* dw_w = (const float*)d_in[1];
    const float* dw_g = (const float*)d_in[2];
    const float* dw_b = (const float*)d_in[3];
    const float* dw_m = (const float*)d_in[4];
    const float* dw_v = (const float*)d_in[5];
    const float* q_w  = (const float*)d_in[6];
    const float* q_g  = (const float*)d_in[7];
    const float* q_b  = (const float*)d_in[8];
    const float* q_m  = (const float*)d_in[9];
    const float* q_v  = (const float*)d_in[10];
    const float* k_w  = (const float*)d_in[11];
    const float* k_g  = (const float*)d_in[12];
    const float* k_b  = (const float*)d_in[13];
    const float* k_m  = (const float*)d_in[14];
    const float* k_v  = (const float*)d_in[15];
    const float* v_w  = (const float*)d_in[16];
    const float* v_g  = (const float*)d_in[17];
    const float* v_b  = (const float*)d_in[18];
    const float* v_m  = (const float*)d_in[19];
    const float* v_v  = (const float*)d_in[20];
    const float* p_w  = (const float*)d_in[21];
    const float* p_g  = (const float*)d_in[22];
    const float* p_b  = (const float*)d_in[23];
    const float* p_m  = (const float*)d_in[24];
    const float* p_v  = (const float*)d_in[25];
    const float* attn_bias = (const float*)d_in[26];

    prep_fold<<<128, 256>>>(dw_w, dw_g, dw_b, dw_m, dw_v,
                            q_w, q_g, q_b, q_m, q_v,
                            k_w, k_g, k_b, k_m, k_v,
                            v_w, v_g, v_b, v_m, v_v,
                            p_w, p_g, p_b, p_m, p_v, attn_bias);

    dwconv_all<<<(BBB*DIMC*400)/256, 256>>>(x);

    for (int i = 0; i < NHH; i++) {
        qkv_mma<<<BBB*25, 256>>>(i, i > 0 ? 1 : 0);
        attn_mma<<<BBB*25, 256>>>(attn_bias, i);
    }

    proj_mma<<<640, 256>>>((float*)d_out);
}

// round 9
// speedup vs baseline: 7.2650x; 1.1002x over previous
#include <cuda_runtime.h>
#include <cuda_fp16.h>
#include <math.h>

#define NHH   4
#define HDD   64
#define KDD   16
#define DDD   64
#define NNN   1600
#define BBB   16
#define HIMG  40
#define WIMG  40
#define DIMC  256
#define EPSB  1e-5f
#define SCALEQ 0.25f
#define L2E   1.4426950408889634f

// ---------------- device scratch ----------------
__device__ float    g_conv[BBB*DIMC*NNN];
__device__ __half   g_qh [BBB*NNN*KDD];
__device__ __half   g_kh [BBB*NNN*KDD];
__device__ __half   g_vT [BBB*DDD*NNN];
__device__ float    g_prev[BBB*HDD*NNN];
__device__ __half   g_cath[BBB*NNN*DIMC];
__device__ float    g_dw_wf[NHH*HDD*25];
__device__ float    g_dw_bf[NHH*HDD];
__device__ __half   g_qkv_wh[NHH*96*HDD];
__device__ float    g_qkv_bf[NHH*96];
__device__ __half   g_p_wh[DIMC*DIMC];
__device__ float    g_p_bf[DIMC];
__device__ unsigned g_kmaxu[NHH*BBB];
__device__ float    g_bmax[NHH];

// ---------------- helpers ----------------
__device__ __forceinline__ float ex2(float x) {
    float r; asm("ex2.approx.f32 %0, %1;" : "=f"(r) : "f"(x)); return r;
}
__device__ __forceinline__ unsigned packh2(float a, float b) {
    __half2 h = __floats2half2_rn(a, b);
    return *(unsigned*)&h;
}
__device__ __forceinline__ void mma_f16(float c[4], const unsigned a[4],
                                        unsigned b0, unsigned b1) {
    asm volatile("mma.sync.aligned.m16n8k16.row.col.f32.f16.f16.f32 "
        "{%0,%1,%2,%3}, {%4,%5,%6,%7}, {%8,%9}, {%0,%1,%2,%3};"
        : "+f"(c[0]), "+f"(c[1]), "+f"(c[2]), "+f"(c[3])
        : "r"(a[0]), "r"(a[1]), "r"(a[2]), "r"(a[3]), "r"(b0), "r"(b1));
}
__device__ __forceinline__ void ldsm4(unsigned& r0, unsigned& r1, unsigned& r2, unsigned& r3,
                                      unsigned addr) {
    asm volatile("ldmatrix.sync.aligned.m8n8.x4.shared.b16 {%0,%1,%2,%3}, [%4];"
        : "=r"(r0), "=r"(r1), "=r"(r2), "=r"(r3) : "r"(addr));
}
__device__ __forceinline__ void cp16(void* dst, const void* src) {
    unsigned d = (unsigned)__cvta_generic_to_shared(dst);
    asm volatile("cp.async.cg.shared.global [%0], [%1], 16;" :: "r"(d), "l"(src));
}
#define CP_COMMIT asm volatile("cp.async.commit_group;" ::: "memory")
#define CP_WAIT1  asm volatile("cp.async.wait_group 1;"  ::: "memory")
#define CP_WAIT0  asm volatile("cp.async.wait_group 0;"  ::: "memory")

// ---------------- fold BN into weights + bias-max + kmax reset ----------------
__global__ void prep_fold(
    const float* dw_w, const float* dw_g, const float* dw_b, const float* dw_m, const float* dw_v,
    const float* q_w,  const float* q_g,  const float* q_b,  const float* q_m,  const float* q_v,
    const float* k_w,  const float* k_g,  const float* k_b,  const float* k_m,  const float* k_v,
    const float* v_w,  const float* v_g,  const float* v_b,  const float* v_m,  const float* v_v,
    const float* p_w,  const float* p_g,  const float* p_b,  const float* p_m,  const float* p_v,
    const float* attn_bias)
{
    int t = blockIdx.x * blockDim.x + threadIdx.x;
    int stride = gridDim.x * blockDim.x;

    for (int idx = t; idx < NHH*HDD*25; idx += stride) {
        int ch = idx / 25;
        float s = dw_g[ch] * rsqrtf(dw_v[ch] + EPSB);
        g_dw_wf[idx] = dw_w[idx] * s;
    }
    for (int ch = t; ch < NHH*HDD; ch += stride) {
        float s = dw_g[ch] * rsqrtf(dw_v[ch] + EPSB);
        g_dw_bf[ch] = dw_b[ch] - s * dw_m[ch];
    }
    for (int idx = t; idx < NHH*96*HDD; idx += stride) {
        int r = idx / HDD, c = idx % HDD;
        int i = r / 96, oc = r % 96;
        float s; const float* w;
        if (oc < 16) {
            int j = i*KDD + oc;
            s = q_g[j] * rsqrtf(q_v[j] + EPSB) * (SCALEQ * L2E);
            w = q_w + (size_t)j * HDD;
        } else if (oc < 32) {
            int j = i*KDD + (oc - 16);
            s = k_g[j] * rsqrtf(k_v[j] + EPSB);
            w = k_w + (size_t)j * HDD;
        } else {
            int j = i*DDD + (oc - 32);
            s = v_g[j] * rsqrtf(v_v[j] + EPSB);
            w = v_w + (size_t)j * HDD;
        }
        g_qkv_wh[idx] = __float2half_rn(w[c] * s);
    }
    for (int r = t; r < NHH*96; r += stride) {
        int i = r / 96, oc = r % 96;
        float s, bias;
        if (oc < 16) {
            int j = i*KDD + oc;
            s = q_g[j] * rsqrtf(q_v[j] + EPSB);
            bias = (q_b[j] - s * q_m[j]) * (SCALEQ * L2E);
        } else if (oc < 32) {
            int j = i*KDD + (oc - 16);
            s = k_g[j] * rsqrtf(k_v[j] + EPSB);
            bias = k_b[j] - s * k_m[j];
        } else {
            int j = i*DDD + (oc - 32);
            s = v_g[j] * rsqrtf(v_v[j] + EPSB);
            bias = v_b[j] - s * v_m[j];
        }
        g_qkv_bf[r] = bias;
    }
    for (int idx = t; idx < DIMC*DIMC; idx += stride) {
        int o = idx / DIMC;
        float s = p_g[o] * rsqrtf(p_v[o] + EPSB);
        g_p_wh[idx] = __float2half_rn(p_w[idx] * s);
    }
    for (int o = t; o < DIMC; o += stride) {
        float s = p_g[o] * rsqrtf(p_v[o] + EPSB);
        g_p_bf[o] = p_b[o] - s * p_m[o];
    }

    if (blockIdx.x == 0) {
        int tt = threadIdx.x;
        if (tt < NHH*BBB) g_kmaxu[tt] = 0u;
        int wrp = tt >> 5, ln = tt & 31;
        if (wrp < NHH) {
            float mx = -1e30f;
            for (int n = ln; n < NNN; n += 32)
                mx = fmaxf(mx, attn_bias[wrp*NNN + n]);
            #pragma unroll
            for (int msk = 16; msk; msk >>= 1)
                mx = fmaxf(mx, __shfl_xor_sync(0xffffffffu, mx, msk));
            if (ln == 0) g_bmax[wrp] = mx * L2E;
        }
    }
}

// ---------------- depthwise 5x5 conv, 4 outputs/thread ----------------
__global__ __launch_bounds__(256) void dwconv_all(const float* __restrict__ x)
{
    int idx = blockIdx.x * 256 + threadIdx.x;
    int n4 = idx % 400;
    int c  = (idx / 400) % DIMC;
    int b  = idx / (400 * DIMC);
    int h  = n4 / 10, w0 = (n4 % 10) * 4;

    const float* xin = x + ((size_t)b * DIMC + c) * NNN;
    const float* wf  = g_dw_wf + c * 25;
    float bias = g_dw_bf[c];
    float a0 = bias, a1 = bias, a2 = bias, a3 = bias;

    #pragma unroll
    for (int dy = 0; dy < 5; dy++) {
        int hh = h + dy - 2;
        if ((unsigned)hh >= (unsigned)HIMG) continue;
        const float* row = xin + hh*WIMG;
        float v[8];
        #pragma unroll
        for (int j = 0; j < 8; j++) {
            int ww = w0 - 2 + j;
            v[j] = ((unsigned)ww < (unsigned)WIMG) ? row[ww] : 0.f;
        }
        #pragma unroll
        for (int dx = 0; dx < 5; dx++) {
            float wt = wf[dy*5 + dx];
            a0 += wt*v[dx];   a1 += wt*v[dx+1];
            a2 += wt*v[dx+2]; a3 += wt*v[dx+3];
        }
    }
    *(float4*)&g_conv[((size_t)b*DIMC + c)*NNN + h*WIMG + w0] = make_float4(a0, a1, a2, a3);
}

// ---------------- QKV projection via fp16 MMA (+ fused prev add + k-norm max) ----------------
__global__ __launch_bounds__(256) void qkv_mma(int head, int addprev)
{
    __shared__ __align__(16) __half wsh[96*72];
    __shared__ __align__(16) __half xsh[64*72];

    int b  = blockIdx.x / 25;
    int p0 = (blockIdx.x % 25) * 64;
    int t  = threadIdx.x;
    int wp   = t >> 5;
    int lane = t & 31;
    int g    = lane >> 2;
    int qd   = lane & 3;

    for (int i = t; i < 768; i += 256) {
        int row = i >> 3, c8 = (i & 7) * 8;
        cp16(&wsh[row*72 + c8], &g_qkv_wh[(size_t)head*96*64 + row*64 + c8]);
    }
    CP_COMMIT;

    {
        int c  = t >> 2;
        int i4 = t & 3;
        int cX = c ^ (i4 << 3);
        const float* cb = g_conv + ((size_t)b*DIMC + head*HDD + c)*NNN + p0 + i4*16;
        const float* pb = g_prev + ((size_t)b*HDD + c)*NNN + p0 + i4*16;
        #pragma unroll
        for (int j4 = 0; j4 < 4; j4++) {
            float4 f = *(const float4*)&cb[j4*4];
            if (addprev) {
                float4 pv = *(const float4*)&pb[j4*4];
                f.x += pv.x; f.y += pv.y; f.z += pv.z; f.w += pv.w;
            }
            int pbase = i4*16 + j4*4;
            xsh[(pbase + 0)*72 + cX] = __float2half_rn(f.x);
            xsh[(pbase + 1)*72 + cX] = __float2half_rn(f.y);
            xsh[(pbase + 2)*72 + cX] = __float2half_rn(f.z);
            xsh[(pbase + 3)*72 + cX] = __float2half_rn(f.w);
        }
    }
    CP_WAIT0;
    __syncthreads();

    int n0 = wp * 8;
    int cXor = ((wp >> 1) & 3) << 3;
    float acc[6][4];
    #pragma unroll
    for (int mt = 0; mt < 6; mt++)
        #pragma unroll
        for (int j = 0; j < 4; j++) acc[mt][j] = 0.f;

    #pragma unroll
    for (int ks = 0; ks < 4; ks++) {
        unsigned b0 = *(const unsigned*)&xsh[(n0 + g)*72 + ((ks*16 + 2*qd    ) ^ cXor)];
        unsigned b1 = *(const unsigned*)&xsh[(n0 + g)*72 + ((ks*16 + 2*qd + 8) ^ cXor)];
        #pragma unroll
        for (int mt = 0; mt < 6; mt++) {
            unsigned a[4];
            a[0] = *(const unsigned*)&wsh[(mt*16 + g    )*72 + ks*16 + 2*qd];
            a[1] = *(const unsigned*)&wsh[(mt*16 + g + 8)*72 + ks*16 + 2*qd];
            a[2] = *(const unsigned*)&wsh[(mt*16 + g    )*72 + ks*16 + 2*qd + 8];
            a[3] = *(const unsigned*)&wsh[(mt*16 + g + 8)*72 + ks*16 + 2*qd + 8];
            mma_f16(acc[mt], a, b0, b1);
        }
    }

    float kn0 = 0.f, kn1 = 0.f;
    int n = p0 + n0 + 2*qd;
    #pragma unroll
    for (int mt = 0; mt < 6; mt++) {
        int oc0 = mt*16 + g, oc1 = oc0 + 8;
        float bb0 = g_qkv_bf[head*96 + oc0];
        float bb1 = g_qkv_bf[head*96 + oc1];
        float v00 = acc[mt][0] + bb0, v01 = acc[mt][1] + bb0;
        float v10 = acc[mt][2] + bb1, v11 = acc[mt][3] + bb1;
        if (mt == 0) {
            g_qh[((size_t)b*NNN + n    )*KDD + oc0] = __float2half_rn(v00);
            g_qh[((size_t)b*NNN + n + 1)*KDD + oc0] = __float2half_rn(v01);
            g_qh[((size_t)b*NNN + n    )*KDD + oc1] = __float2half_rn(v10);
            g_qh[((size_t)b*NNN + n + 1)*KDD + oc1] = __float2half_rn(v11);
        } else if (mt == 1) {
            int k0 = oc0 - 16, k1 = oc1 - 16;
            g_kh[((size_t)b*NNN + n    )*KDD + k0] = __float2half_rn(v00);
            g_kh[((size_t)b*NNN + n + 1)*KDD + k0] = __float2half_rn(v01);
            g_kh[((size_t)b*NNN + n    )*KDD + k1] = __float2half_rn(v10);
            g_kh[((size_t)b*NNN + n + 1)*KDD + k1] = __float2half_rn(v11);
            kn0 = v00*v00 + v10*v10;
            kn1 = v01*v01 + v11*v11;
        } else {
            int d0 = oc0 - 32, d1 = oc1 - 32;
            *(__half2*)&g_vT[((size_t)b*DDD + d0)*NNN + n] = __floats2half2_rn(v00, v01);
            *(__half2*)&g_vT[((size_t)b*DDD + d1)*NNN + n] = __floats2half2_rn(v10, v11);
        }
    }

    #pragma unroll
    for (int msk = 4; msk <= 16; msk <<= 1) {
        kn0 += __shfl_xor_sync(0xffffffffu, kn0, msk);
        kn1 += __shfl_xor_sync(0xffffffffu, kn1, msk);
    }
    float kmx = fmaxf(kn0, kn1);
    kmx = fmaxf(kmx, __shfl_xor_sync(0xffffffffu, kmx, 1));
    kmx = fmaxf(kmx, __shfl_xor_sync(0xffffffffu, kmx, 2));
    if (lane == 0)
        atomicMax(&g_kmaxu[head*BBB + b], __float_as_uint(kmx));
}

// ---------------- fp16 MMA flash attention: ILP-pipelined, 1 sync/tile ----------------
#define KSTRH 24
#define VSTRH 72
#define KBYTES (64*KSTRH*2)    // 3072
#define VBYTES (64*VSTRH*2)    // 9216

__global__ __launch_bounds__(128) void attn_mma(const float* __restrict__ attn_bias, int head)
{
    __shared__ __align__(16) __half ksm[3][64*KSTRH];    //  9216 B
    __shared__ __align__(16) __half vsm[4][64*VSTRH];    // 36864 B
    __shared__ __align__(16) float  bism[3][64];         //   768 B

    int b  = blockIdx.x / 25;
    int q0 = (blockIdx.x % 25) * 64;
    int t    = threadIdx.x;
    int w    = t >> 5;
    int lane = t & 31;
    int g    = lane >> 2;
    int qd   = lane & 3;
    int mi   = lane >> 3;
    int mr   = lane & 7;

    const __half* kbase = g_kh + (size_t)b*NNN*KDD;
    const __half* vbase = g_vT + (size_t)b*DDD*NNN;
    const float*  bbase = attn_bias + head*NNN;

    unsigned ksb = (unsigned)__cvta_generic_to_shared(&ksm[0][0])
                 + ((((mi>>1)*8 + mr)*KSTRH) + (mi & 1)*8) * 2;
    unsigned vsb = (unsigned)__cvta_generic_to_shared(&vsm[0][0])
                 + ((mr*VSTRH) + mi*8) * 2;

    int sk_key = t >> 1, sk_c8 = (t & 1) * 8;   // K staging coords

#define STAGE(KB, VB, K0) do { \
    cp16(&ksm[KB][sk_key*KSTRH + sk_c8], &kbase[(size_t)((K0) + sk_key)*KDD + sk_c8]); \
    _Pragma("unroll") \
    for (int i2 = 0; i2 < 4; i2++) { \
        int dd = (t + i2*128) >> 3, ch = (t + i2*128) & 7; \
        cp16(&vsm[VB][dd*VSTRH + ch*8], &vbase[(size_t)dd*NNN + (K0) + ch*8]); } \
    if (t < 16) cp16(&bism[KB][t*4], &bbase[(K0) + t*4]); \
} while (0)

    // Q fragments (log2e pre-folded)
    unsigned aQ[4];
    {
        int r0 = q0 + w*16 + g, r1 = r0 + 8;
        const __half* qb = g_qh + (size_t)b*NNN*KDD;
        aQ[0] = *(const unsigned*)&qb[(size_t)r0*KDD + 2*qd];
        aQ[1] = *(const unsigned*)&qb[(size_t)r1*KDD + 2*qd];
        aQ[2] = *(const unsigned*)&qb[(size_t)r0*KDD + 2*qd + 8];
        aQ[3] = *(const unsigned*)&qb[(size_t)r1*KDD + 2*qd + 8];
    }

    // static shifts
    float m0, m1;
    {
        float q2_0 = 0.f, q2_1 = 0.f;
        #pragma unroll
        for (int i = 0; i < 4; i++) {
            float2 f = __half22float2(*(__half2*)&aQ[i]);
            float ss = f.x*f.x + f.y*f.y;
            if (i & 1) q2_1 += ss; else q2_0 += ss;
        }
        q2_0 += __shfl_xor_sync(0xffffffffu, q2_0, 1);
        q2_0 += __shfl_xor_sync(0xffffffffu, q2_0, 2);
        q2_1 += __shfl_xor_sync(0xffffffffu, q2_1, 1);
        q2_1 += __shfl_xor_sync(0xffffffffu, q2_1, 2);
        float kmax2 = __uint_as_float(g_kmaxu[head*BBB + b]);
        float bmax  = g_bmax[head];
        m0 = sqrtf(q2_0 * kmax2) + bmax - 8.f;
        m1 = sqrtf(q2_1 * kmax2) + bmax - 8.f;
    }

#define COMPUTE_S(SV, KB1) do { \
    unsigned kA = ksb + (KB1)*KBYTES; \
    const float* bb = bism[KB1]; \
    _Pragma("unroll") \
    for (int j = 0; j < 4; j++) { \
        float2 bbA = *(const float2*)&bb[(2*j)*8 + 2*qd]; \
        float2 bbB = *(const float2*)&bb[(2*j+1)*8 + 2*qd]; \
        SV[2*j  ][0] = fmaf(bbA.x, L2E, -m0); \
        SV[2*j  ][1] = fmaf(bbA.y, L2E, -m0); \
        SV[2*j  ][2] = fmaf(bbA.x, L2E, -m1); \
        SV[2*j  ][3] = fmaf(bbA.y, L2E, -m1); \
        SV[2*j+1][0] = fmaf(bbB.x, L2E, -m0); \
        SV[2*j+1][1] = fmaf(bbB.y, L2E, -m0); \
        SV[2*j+1][2] = fmaf(bbB.x, L2E, -m1); \
        SV[2*j+1][3] = fmaf(bbB.y, L2E, -m1); \
        unsigned r0, r1, r2, r3; \
        ldsm4(r0, r1, r2, r3, kA + j*(16*KSTRH*2)); \
        mma_f16(SV[2*j  ], aQ, r0, r1); \
        mma_f16(SV[2*j+1], aQ, r2, r3); \
    } \
} while (0)

#define SOFTPV(SV, VB) do { \
    unsigned Ph[4][4]; \
    _Pragma("unroll") \
    for (int kc = 0; kc < 4; kc++) { \
        float pA0 = ex2(SV[2*kc  ][0]); \
        float pA1 = ex2(SV[2*kc  ][1]); \
        float pA2 = ex2(SV[2*kc  ][2]); \
        float pA3 = ex2(SV[2*kc  ][3]); \
        float pB0 = ex2(SV[2*kc+1][0]); \
        float pB1 = ex2(SV[2*kc+1][1]); \
        float pB2 = ex2(SV[2*kc+1][2]); \
        float pB3 = ex2(SV[2*kc+1][3]); \
        l0 += pA0 + pA1 + pB0 + pB1; \
        l1 += pA2 + pA3 + pB2 + pB3; \
        Ph[kc][0] = packh2(pA0, pA1); \
        Ph[kc][1] = packh2(pA2, pA3); \
        Ph[kc][2] = packh2(pB0, pB1); \
        Ph[kc][3] = packh2(pB2, pB3); \
    } \
    unsigned vA = vsb + (VB)*VBYTES; \
    _Pragma("unroll") \
    for (int nt = 0; nt < 8; nt++) { \
        unsigned c0, c1, c2, c3; \
        ldsm4(c0, c1, c2, c3, vA + nt*(8*VSTRH*2)); \
        mma_f16(Oa[nt], Ph[0], c0, c1); \
        mma_f16(Oa[nt], Ph[1], c2, c3); \
        ldsm4(c0, c1, c2, c3, vA + nt*(8*VSTRH*2) + 64); \
        mma_f16(Oa[nt], Ph[2], c0, c1); \
        mma_f16(Oa[nt], Ph[3], c2, c3); \
    } \
} while (0)

#define TILE(KT, CUR, NXT) do { \
    if ((KT) + 2 < 25) STAGE(kstg3, ((KT)+2) & 3, ((KT)+2)*64); \
    CP_COMMIT; \
    CP_WAIT1; \
    __syncthreads(); \
    if ((KT) + 1 < 25) COMPUTE_S(NXT, krd3); \
    SOFTPV(CUR, (KT) & 3); \
    kstg3 = (kstg3 == 2) ? 0 : kstg3 + 1; \
    krd3  = (krd3  == 2) ? 0 : krd3  + 1; \
} while (0)

    float Oa[8][4];
    #pragma unroll
    for (int nt = 0; nt < 8; nt++)
        #pragma unroll
        for (int j = 0; j < 4; j++) Oa[nt][j] = 0.f;
    float l0 = 0.f, l1 = 0.f;

    // prologue: stage tiles 0,1; compute S(0)
    STAGE(0, 0, 0);   CP_COMMIT;
    STAGE(1, 1, 64);  CP_COMMIT;
    CP_WAIT1;
    __syncthreads();

    float SvA[8][4], SvB[8][4];
    COMPUTE_S(SvA, 0);

    int kstg3 = 2, krd3 = 1;
    for (int kt = 0; kt < 24; kt += 2) {
        TILE(kt,     SvA, SvB);
        TILE(kt + 1, SvB, SvA);
    }
    TILE(24, SvA, SvB);

    // ---- final row-sum reduce + epilogue ----
    l0 += __shfl_xor_sync(0xffffffffu, l0, 1);
    l0 += __shfl_xor_sync(0xffffffffu, l0, 2);
    l1 += __shfl_xor_sync(0xffffffffu, l1, 1);
    l1 += __shfl_xor_sync(0xffffffffu, l1, 2);
    float inv0 = 1.f / l0, inv1 = 1.f / l1;
    int n0 = q0 + w*16 + g, n1 = n0 + 8;
    #pragma unroll
    for (int nt = 0; nt < 8; nt++) {
        int d = nt*8 + 2*qd;
        float o00 = Oa[nt][0] * inv0, o01 = Oa[nt][1] * inv0;
        float o10 = Oa[nt][2] * inv1, o11 = Oa[nt][3] * inv1;
        *(__half2*)&g_cath[((size_t)b*NNN + n0)*DIMC + head*DDD + d] = __floats2half2_rn(o00, o01);
        *(__half2*)&g_cath[((size_t)b*NNN + n1)*DIMC + head*DDD + d] = __floats2half2_rn(o10, o11);
        g_prev[((size_t)b*HDD + d    )*NNN + n0] = o00;
        g_prev[((size_t)b*HDD + d + 1)*NNN + n0] = o01;
        g_prev[((size_t)b*HDD + d    )*NNN + n1] = o10;
        g_prev[((size_t)b*HDD + d + 1)*NNN + n1] = o11;
    }
#undef STAGE
#undef COMPUTE_S
#undef SOFTPV
#undef TILE
}

// ---------------- final proj: fp16 MMA ----------------
#define PSTRH 24

__global__ __launch_bounds__(256) void proj_mma(float* __restrict__ out)
{
    __shared__ __align__(16) __half xsm[2][160*PSTRH];
    __shared__ __align__(16) __half wsm[2][64*PSTRH];

    int bi = blockIdx.x;
    int b  = bi / 40;
    int r  = bi % 40;
    int p0 = (r / 4) * 160;
    int o0 = (r % 4) * 64;

    int t    = threadIdx.x;
    int wid  = t >> 5;
    int lane = t & 31;
    int g    = lane >> 2;
    int qd   = lane & 3;
    int wo   = wid & 3;
    int wp   = wid >> 2;

    const __half* xb = g_cath + (size_t)b*NNN*DIMC;

    float Oa[10][4];
    #pragma unroll
    for (int nt = 0; nt < 10; nt++)
        #pragma unroll
        for (int j = 0; j < 4; j++) Oa[nt][j] = 0.f;

    {
        for (int i = t; i < 128; i += 256) {
            int row = i >> 1, c8 = (i & 1) * 8;
            cp16(&wsm[0][row*PSTRH + c8], &g_p_wh[(o0 + row)*DIMC + c8]);
        }
        for (int i = t; i < 320; i += 256) {
            int row = i >> 1, c8 = (i & 1) * 8;
            cp16(&xsm[0][row*PSTRH + c8], &xb[(size_t)(p0 + row)*DIMC + c8]);
        }
        CP_COMMIT;
    }

    for (int s = 0; s < 16; s++) {
        int buf = s & 1;
        if (s + 1 < 16) {
            int c0 = (s + 1) * 16, nb = buf ^ 1;
            for (int i = t; i < 128; i += 256) {
                int row = i >> 1, c8 = (i & 1) * 8;
                cp16(&wsm[nb][row*PSTRH + c8], &g_p_wh[(o0 + row)*DIMC + c0 + c8]);
            }
            for (int i = t; i < 320; i += 256) {
                int row = i >> 1, c8 = (i & 1) * 8;
                cp16(&xsm[nb][row*PSTRH + c8], &xb[(size_t)(p0 + row)*DIMC + c0 + c8]);
            }
        }
        CP_COMMIT;
        CP_WAIT1;
        __syncthreads();

        unsigned a[4];
        a[0] = *(const unsigned*)&wsm[buf][(wo*16 + g    )*PSTRH + 2*qd];
        a[1] = *(const unsigned*)&wsm[buf][(wo*16 + g + 8)*PSTRH + 2*qd];
        a[2] = *(const unsigned*)&wsm[buf][(wo*16 + g    )*PSTRH + 2*qd + 8];
        a[3] = *(const unsigned*)&wsm[buf][(wo*16 + g + 8)*PSTRH + 2*qd + 8];
        #pragma unroll
        for (int nt = 0; nt < 10; nt++) {
            unsigned b0 = *(const unsigned*)&xsm[buf][(wp*80 + nt*8 + g)*PSTRH + 2*qd];
            unsigned b1 = *(const unsigned*)&xsm[buf][(wp*80 + nt*8 + g)*PSTRH + 2*qd + 8];
            mma_f16(Oa[nt], a, b0, b1);
        }
        __syncthreads();
    }

    int orow0 = o0 + wo*16 + g, orow1 = orow0 + 8;
    float bb0 = g_p_bf[orow0], bb1 = g_p_bf[orow1];
    #pragma unroll
    for (int nt = 0; nt < 10; nt++) {
        int n = p0 + wp*80 + nt*8 + 2*qd;
        float v00 = fmaxf(Oa[nt][0] + bb0, 0.f);
        float v01 = fmaxf(Oa[nt][1] + bb0, 0.f);
        float v10 = fmaxf(Oa[nt][2] + bb1, 0.f);
        float v11 = fmaxf(Oa[nt][3] + bb1, 0.f);
        *(float2*)&out[((size_t)b*DIMC + orow0)*NNN + n] = make_float2(v00, v01);
        *(float2*)&out[((size_t)b*DIMC + orow1)*NNN + n] = make_float2(v10, v11);
    }
}

// ---------------- launch ----------------
extern "C" void kernel_launch(void* const* d_in, const int* in_sizes, int n_in,
                              void* d_out, int out_size)
{
    const float* x    = (const float*)d_in[0];
    const float* dw_w = (const float*)d_in[1];
    const float* dw_g = (const float*)d_in[2];
    const float* dw_b = (const float*)d_in[3];
    const float* dw_m = (const float*)d_in[4];
    const float* dw_v = (const float*)d_in[5];
    const float* q_w  = (const float*)d_in[6];
    const float* q_g  = (const float*)d_in[7];
    const float* q_b  = (const float*)d_in[8];
    const float* q_m  = (const float*)d_in[9];
    const float* q_v  = (const float*)d_in[10];
    const float* k_w  = (const float*)d_in[11];
    const float* k_g  = (const float*)d_in[12];
    const float* k_b  = (const float*)d_in[13];
    const float* k_m  = (const float*)d_in[14];
    const float* k_v  = (const float*)d_in[15];
    const float* v_w  = (const float*)d_in[16];
    const float* v_g  = (const float*)d_in[17];
    const float* v_b  = (const float*)d_in[18];
    const float* v_m  = (const float*)d_in[19];
    const float* v_v  = (const float*)d_in[20];
    const float* p_w  = (const float*)d_in[21];
    const float* p_g  = (const float*)d_in[22];
    const float* p_b  = (const float*)d_in[23];
    const float* p_m  = (const float*)d_in[24];
    const float* p_v  = (const float*)d_in[25];
    const float* attn_bias = (const float*)d_in[26];

    prep_fold<<<128, 256>>>(dw_w, dw_g, dw_b, dw_m, dw_v,
                            q_w, q_g, q_b, q_m, q_v,
                            k_w, k_g, k_b, k_m, k_v,
                            v_w, v_g, v_b, v_m, v_v,
                            p_w, p_g, p_b, p_m, p_v, attn_bias);

    dwconv_all<<<(BBB*DIMC*400)/256, 256>>>(x);

    for (int i = 0; i < NHH; i++) {
        qkv_mma<<<BBB*25, 256>>>(i, i > 0 ? 1 : 0);
        attn_mma<<<BBB*25, 128>>>(attn_bias, i);
    }

    proj_mma<<<640, 256>>>((float*)d_out);
}